// round 1
// baseline (speedup 1.0000x reference)
#include <cuda_runtime.h>
#include <cuda_bf16.h>
#include <math.h>

#define HIDDEN   4096
#define NKV      8
#define NH       32
#define HD       128
#define BATCH    2
#define SEQ      2048
#define TOKENS   (BATCH*SEQ)   // 4096
#define KVDIM    (NKV*HD)      // 1024

// ---------------- scratch (device globals; no runtime allocation) ----------
__device__ float g_Q [TOKENS*HIDDEN];   // 64 MB
__device__ float g_K [TOKENS*KVDIM];    // 16 MB
__device__ float g_V [TOKENS*KVDIM];    // 16 MB
__device__ float g_AO[TOKENS*HIDDEN];   // 64 MB

// ---------------------------------------------------------------------------
// SGEMM (TN):  C[m][n] = sum_k A[m][k] * B[n][k]
// A: [M,K] row-major, B: [N,K] row-major (i.e. C = A @ B^T).
// Tile: BM=128, BN=128, BK=16. 256 threads, each computes 8x8.
// M, N, K all multiples of 128/16 here -> no bounds checks.
// ---------------------------------------------------------------------------
__global__ __launch_bounds__(256) void sgemm_tn(
    const float* __restrict__ A, const float* __restrict__ B,
    float* __restrict__ C, int N, int K)
{
    const int BM = 128, BN = 128, BK = 16;
    __shared__ float As[BK][BM];   // As[k][m]
    __shared__ float Bs[BK][BN];   // Bs[k][n]

    const int tid = threadIdx.x;
    const int tx  = tid & 15;      // 0..15 -> n
    const int ty  = tid >> 4;      // 0..15 -> m
    const int m0  = blockIdx.y * BM;
    const int n0  = blockIdx.x * BN;

    const int lr = tid >> 2;         // 0..63 (row within tile, +64 second pass)
    const int lc = (tid & 3) << 2;   // 0,4,8,12 (k offset)

    const float* Aptr = A + (size_t)(m0 + lr) * K + lc;
    const float* Bptr = B + (size_t)(n0 + lr) * K + lc;

    float acc[8][8];
#pragma unroll
    for (int i = 0; i < 8; i++)
#pragma unroll
        for (int j = 0; j < 8; j++) acc[i][j] = 0.f;

    for (int k0 = 0; k0 < K; k0 += BK) {
        // fetch
        float4 a0 = *(const float4*)(Aptr + k0);
        float4 a1 = *(const float4*)(Aptr + (size_t)64 * K + k0);
        float4 b0 = *(const float4*)(Bptr + k0);
        float4 b1 = *(const float4*)(Bptr + (size_t)64 * K + k0);

        // store transposed into smem
        As[lc + 0][lr] = a0.x;  As[lc + 1][lr] = a0.y;
        As[lc + 2][lr] = a0.z;  As[lc + 3][lr] = a0.w;
        As[lc + 0][lr + 64] = a1.x;  As[lc + 1][lr + 64] = a1.y;
        As[lc + 2][lr + 64] = a1.z;  As[lc + 3][lr + 64] = a1.w;

        Bs[lc + 0][lr] = b0.x;  Bs[lc + 1][lr] = b0.y;
        Bs[lc + 2][lr] = b0.z;  Bs[lc + 3][lr] = b0.w;
        Bs[lc + 0][lr + 64] = b1.x;  Bs[lc + 1][lr + 64] = b1.y;
        Bs[lc + 2][lr + 64] = b1.z;  Bs[lc + 3][lr + 64] = b1.w;

        __syncthreads();

#pragma unroll
        for (int k = 0; k < BK; k++) {
            float4 av0 = *(const float4*)&As[k][ty * 8];
            float4 av1 = *(const float4*)&As[k][ty * 8 + 4];
            float4 bv0 = *(const float4*)&Bs[k][tx * 8];
            float4 bv1 = *(const float4*)&Bs[k][tx * 8 + 4];
            float ar[8] = {av0.x, av0.y, av0.z, av0.w, av1.x, av1.y, av1.z, av1.w};
            float br[8] = {bv0.x, bv0.y, bv0.z, bv0.w, bv1.x, bv1.y, bv1.z, bv1.w};
#pragma unroll
            for (int i = 0; i < 8; i++)
#pragma unroll
                for (int j = 0; j < 8; j++)
                    acc[i][j] = fmaf(ar[i], br[j], acc[i][j]);
        }
        __syncthreads();
    }

#pragma unroll
    for (int i = 0; i < 8; i++) {
        float* Crow = C + (size_t)(m0 + ty * 8 + i) * N + n0 + tx * 8;
        float4 c0 = make_float4(acc[i][0], acc[i][1], acc[i][2], acc[i][3]);
        float4 c1 = make_float4(acc[i][4], acc[i][5], acc[i][6], acc[i][7]);
        *(float4*)(Crow)     = c0;
        *(float4*)(Crow + 4) = c1;
    }
}

// ---------------------------------------------------------------------------
// Flash attention (causal, GQA). One CTA per (q_block=64 rows, q_head, batch).
// 256 threads in a 16x16 grid. S tile 64x64 (4x4/thread), O tile 64x128
// (4 rows x 8 cols/thread). Online softmax; width-16 shuffle row reductions.
// ---------------------------------------------------------------------------
#define QT_LD 68
#define KT_LD 68
// smem floats: Qt 128*68 + Kt 128*68 + Vs 64*128 + Ps 64*64
#define FLASH_SMEM_FLOATS (128*QT_LD + 128*KT_LD + 64*128 + 64*64)
#define FLASH_SMEM_BYTES  (FLASH_SMEM_FLOATS * 4)

__device__ __forceinline__ float rmax16(float v) {
#pragma unroll
    for (int o = 8; o > 0; o >>= 1) v = fmaxf(v, __shfl_xor_sync(0xffffffffu, v, o));
    return v;
}
__device__ __forceinline__ float rsum16(float v) {
#pragma unroll
    for (int o = 8; o > 0; o >>= 1) v += __shfl_xor_sync(0xffffffffu, v, o);
    return v;
}

__global__ __launch_bounds__(256) void flash_gqa()
{
    extern __shared__ float sm[];
    float* Qt = sm;                        // [128][QT_LD] (k-major, rows=d)
    float* Kt = Qt + 128 * QT_LD;          // [128][KT_LD]
    float* Vs = Kt + 128 * KT_LD;          // [64][128]
    float* Ps = Vs + 64 * 128;             // [64][64]

    const int tid = threadIdx.x;
    const int tx  = tid & 15;
    const int ty  = tid >> 4;
    const int qb  = blockIdx.x;            // 0..31
    const int hq  = blockIdx.y;            // 0..31
    const int b   = blockIdx.z;            // 0..1
    const int kv  = hq >> 2;
    const int r0  = qb * 64;
    const float scale = 0.08838834764831845f;  // 1/sqrt(128)

    // ---- load Q tile (transposed to Qt[d][r]), fold in scale ----
    const float* Qg = g_Q + (size_t)(b * SEQ + r0) * HIDDEN + hq * HD;
    for (int idx = tid; idx < 64 * 128; idx += 256) {
        int r = idx >> 7, d = idx & 127;
        Qt[d * QT_LD + r] = Qg[(size_t)r * HIDDEN + d] * scale;
    }

    float m_i[4], l_i[4], o[4][8];
#pragma unroll
    for (int i = 0; i < 4; i++) {
        m_i[i] = -1e30f; l_i[i] = 0.f;
#pragma unroll
        for (int c = 0; c < 8; c++) o[i][c] = 0.f;
    }

    const float* Kg = g_K + (size_t)(b * SEQ) * KVDIM + kv * HD;
    const float* Vg = g_V + (size_t)(b * SEQ) * KVDIM + kv * HD;

    for (int j = 0; j <= qb; j++) {
        const int c0 = j * 64;
        __syncthreads();  // protect Kt/Vs/Ps before overwrite
        for (int idx = tid; idx < 64 * 128; idx += 256) {
            int r = idx >> 7, d = idx & 127;
            float kvrow = Kg[(size_t)(c0 + r) * KVDIM + d];
            float vvrow = Vg[(size_t)(c0 + r) * KVDIM + d];
            Kt[d * KT_LD + r] = kvrow;
            Vs[r * 128 + d]   = vvrow;
        }
        __syncthreads();

        // ---- S = (Q*scale) @ K^T : s[i][jj], rows ty*4+i, cols tx*4+jj ----
        float s[4][4];
#pragma unroll
        for (int i = 0; i < 4; i++)
#pragma unroll
            for (int jj = 0; jj < 4; jj++) s[i][jj] = 0.f;

#pragma unroll 4
        for (int k = 0; k < 128; k++) {
            float4 av = *(const float4*)&Qt[k * QT_LD + ty * 4];
            float4 bv = *(const float4*)&Kt[k * KT_LD + tx * 4];
            float ar[4] = {av.x, av.y, av.z, av.w};
            float br[4] = {bv.x, bv.y, bv.z, bv.w};
#pragma unroll
            for (int i = 0; i < 4; i++)
#pragma unroll
                for (int jj = 0; jj < 4; jj++)
                    s[i][jj] = fmaf(ar[i], br[jj], s[i][jj]);
        }

        // ---- causal mask on diagonal block ----
        if (j == qb) {
#pragma unroll
            for (int i = 0; i < 4; i++)
#pragma unroll
                for (int jj = 0; jj < 4; jj++)
                    if (tx * 4 + jj > ty * 4 + i) s[i][jj] = -1e30f;
        }

        // ---- online softmax ----
        float alpha[4];
#pragma unroll
        for (int i = 0; i < 4; i++) {
            float mv = fmaxf(fmaxf(s[i][0], s[i][1]), fmaxf(s[i][2], s[i][3]));
            mv = rmax16(mv);
            float mnew = fmaxf(m_i[i], mv);
            alpha[i] = __expf(m_i[i] - mnew);
            float sum = 0.f;
#pragma unroll
            for (int jj = 0; jj < 4; jj++) {
                float p = __expf(s[i][jj] - mnew);
                s[i][jj] = p;
                sum += p;
            }
            sum = rsum16(sum);
            l_i[i] = l_i[i] * alpha[i] + sum;
            m_i[i] = mnew;
        }

        // rescale accumulator
#pragma unroll
        for (int i = 0; i < 4; i++)
#pragma unroll
            for (int c = 0; c < 8; c++) o[i][c] *= alpha[i];

        // store P tile
#pragma unroll
        for (int i = 0; i < 4; i++)
            *(float4*)&Ps[(ty * 4 + i) * 64 + tx * 4] =
                make_float4(s[i][0], s[i][1], s[i][2], s[i][3]);
        __syncthreads();

        // ---- O += P @ V ----
#pragma unroll 2
        for (int n = 0; n < 64; n++) {
            float p0 = Ps[(ty * 4 + 0) * 64 + n];
            float p1 = Ps[(ty * 4 + 1) * 64 + n];
            float p2 = Ps[(ty * 4 + 2) * 64 + n];
            float p3 = Ps[(ty * 4 + 3) * 64 + n];
            float4 v0 = *(const float4*)&Vs[n * 128 + tx * 8];
            float4 v1 = *(const float4*)&Vs[n * 128 + tx * 8 + 4];
            float vr[8] = {v0.x, v0.y, v0.z, v0.w, v1.x, v1.y, v1.z, v1.w};
#pragma unroll
            for (int c = 0; c < 8; c++) {
                o[0][c] = fmaf(p0, vr[c], o[0][c]);
                o[1][c] = fmaf(p1, vr[c], o[1][c]);
                o[2][c] = fmaf(p2, vr[c], o[2][c]);
                o[3][c] = fmaf(p3, vr[c], o[3][c]);
            }
        }
    }

    // ---- finalize & write ----
    float* Og = g_AO + (size_t)(b * SEQ + r0) * HIDDEN + hq * HD;
#pragma unroll
    for (int i = 0; i < 4; i++) {
        float inv = 1.f / l_i[i];
        int r = ty * 4 + i;
        float4 c0 = make_float4(o[i][0] * inv, o[i][1] * inv, o[i][2] * inv, o[i][3] * inv);
        float4 c1 = make_float4(o[i][4] * inv, o[i][5] * inv, o[i][6] * inv, o[i][7] * inv);
        *(float4*)&Og[(size_t)r * HIDDEN + tx * 8]     = c0;
        *(float4*)&Og[(size_t)r * HIDDEN + tx * 8 + 4] = c1;
    }
}

// ---------------------------------------------------------------------------
extern "C" void kernel_launch(void* const* d_in, const int* in_sizes, int n_in,
                              void* d_out, int out_size)
{
    const float* x  = (const float*)d_in[0];
    const float* Wq = (const float*)d_in[1];
    const float* Wk = (const float*)d_in[2];
    const float* Wv = (const float*)d_in[3];
    const float* Wo = (const float*)d_in[4];
    float* out = (float*)d_out;

    float *Qp, *Kp, *Vp, *AOp;
    cudaGetSymbolAddress((void**)&Qp,  g_Q);
    cudaGetSymbolAddress((void**)&Kp,  g_K);
    cudaGetSymbolAddress((void**)&Vp,  g_V);
    cudaGetSymbolAddress((void**)&AOp, g_AO);

    cudaFuncSetAttribute(flash_gqa, cudaFuncAttributeMaxDynamicSharedMemorySize,
                         FLASH_SMEM_BYTES);

    dim3 blk(256);
    // Q = x @ Wq^T   [4096,4096]
    sgemm_tn<<<dim3(HIDDEN / 128, TOKENS / 128), blk>>>(x, Wq, Qp, HIDDEN, HIDDEN);
    // K = x @ Wk^T   [4096,1024]
    sgemm_tn<<<dim3(KVDIM / 128, TOKENS / 128), blk>>>(x, Wk, Kp, KVDIM, HIDDEN);
    // V = x @ Wv^T   [4096,1024]
    sgemm_tn<<<dim3(KVDIM / 128, TOKENS / 128), blk>>>(x, Wv, Vp, KVDIM, HIDDEN);
    // attention
    flash_gqa<<<dim3(SEQ / 64, NH, BATCH), blk, FLASH_SMEM_BYTES>>>();
    // out = AO @ Wo^T  [4096,4096]
    sgemm_tn<<<dim3(HIDDEN / 128, TOKENS / 128), blk>>>(AOp, Wo, out, HIDDEN, HIDDEN);
}

// round 3
// speedup vs baseline: 1.7549x; 1.7549x over previous
#include <cuda_runtime.h>
#include <cuda_fp16.h>
#include <cstdint>
#include <math.h>

#define HIDDEN   4096
#define NKV      8
#define NH       32
#define HD       128
#define BATCH    2
#define SEQ      2048
#define TOKENS   (BATCH*SEQ)   // 4096
#define KVDIM    (NKV*HD)      // 1024

// ---------------- scratch (device globals; no runtime allocation) ----------
__device__ float g_Q [TOKENS*HIDDEN];
__device__ float g_K [TOKENS*KVDIM];
__device__ float g_V [TOKENS*KVDIM];
__device__ float g_AO[TOKENS*HIDDEN];

__device__ __half g_xh [TOKENS*HIDDEN], g_xl [TOKENS*HIDDEN];
__device__ __half g_wqh[HIDDEN*HIDDEN], g_wql[HIDDEN*HIDDEN];
__device__ __half g_wkh[KVDIM*HIDDEN],  g_wkl[KVDIM*HIDDEN];
__device__ __half g_wvh[KVDIM*HIDDEN],  g_wvl[KVDIM*HIDDEN];
__device__ __half g_woh[HIDDEN*HIDDEN], g_wol[HIDDEN*HIDDEN];
__device__ __half g_aoh[TOKENS*HIDDEN], g_aol[TOKENS*HIDDEN];

// ======================= helpers ============================================
__device__ __forceinline__ uint32_t smem_u32(const void* p) {
    uint32_t a;
    asm("{ .reg .u64 t; cvta.to.shared.u64 t, %1; cvt.u32.u64 %0, t; }"
        : "=r"(a) : "l"(p));
    return a;
}
__device__ __forceinline__ void cp16(uint32_t dst, const void* src) {
    asm volatile("cp.async.cg.shared.global [%0], [%1], 16;" :: "r"(dst), "l"(src));
}
__device__ __forceinline__ void cp_commit() { asm volatile("cp.async.commit_group;" ::: "memory"); }
template<int N> __device__ __forceinline__ void cp_wait() {
    asm volatile("cp.async.wait_group %0;" :: "n"(N) : "memory");
}
__device__ __forceinline__ void ldm_x4(uint32_t* r, uint32_t addr) {
    asm volatile("ldmatrix.sync.aligned.m8n8.x4.shared.b16 {%0,%1,%2,%3}, [%4];"
        : "=r"(r[0]), "=r"(r[1]), "=r"(r[2]), "=r"(r[3]) : "r"(addr));
}
__device__ __forceinline__ void mma16816(float* d, const uint32_t* a,
                                         uint32_t b0, uint32_t b1) {
    asm volatile(
        "mma.sync.aligned.m16n8k16.row.col.f32.f16.f16.f32 "
        "{%0,%1,%2,%3}, {%4,%5,%6,%7}, {%8,%9}, {%0,%1,%2,%3};"
        : "+f"(d[0]), "+f"(d[1]), "+f"(d[2]), "+f"(d[3])
        : "r"(a[0]), "r"(a[1]), "r"(a[2]), "r"(a[3]), "r"(b0), "r"(b1));
}

// ======================= split fp32 -> fp16 hi/lo ==========================
__global__ __launch_bounds__(256) void split_f32(
    const float4* __restrict__ x, __half2* __restrict__ hi,
    __half2* __restrict__ lo, int n4)
{
    int i = blockIdx.x * blockDim.x + threadIdx.x;
    if (i >= n4) return;
    float4 v = x[i];
    __half h0 = __float2half_rn(v.x), h1 = __float2half_rn(v.y);
    __half h2 = __float2half_rn(v.z), h3 = __float2half_rn(v.w);
    __half l0 = __float2half_rn(v.x - __half2float(h0));
    __half l1 = __float2half_rn(v.y - __half2float(h1));
    __half l2 = __float2half_rn(v.z - __half2float(h2));
    __half l3 = __float2half_rn(v.w - __half2float(h3));
    hi[2 * i]     = __halves2half2(h0, h1);
    hi[2 * i + 1] = __halves2half2(h2, h3);
    lo[2 * i]     = __halves2half2(l0, l1);
    lo[2 * i + 1] = __halves2half2(l2, l3);
}

// ======================= HMMA GEMM: C = A @ B^T =============================
// A: [M,K] fp16 hi/lo row-major, B: [N,K] fp16 hi/lo row-major, C fp32 [M,N].
// CTA tile 128x128, BK=32, 8 warps (2 m x 4 n), warp tile 64x32.
// 3-term split: Ah*Bh + Ah*Bl + Al*Bh (fp32 accum).
#define BM 128
#define BN 128
#define BK 32
#define ROWB 80                         // padded row bytes (40 halves)
#define TILE_B (128*ROWB)               // 10240 bytes per matrix per stage
#define STAGE_B (4*TILE_B)              // Ah, Al, Bh, Bl
#define GEMM_SMEM (2*STAGE_B)           // 81920

__global__ __launch_bounds__(256, 1) void gemm_hmma(
    const __half* __restrict__ Ah, const __half* __restrict__ Al,
    const __half* __restrict__ Bh, const __half* __restrict__ Bl,
    float* __restrict__ C, int N, int K)
{
    extern __shared__ char smraw[];
    const uint32_t sbase = smem_u32(smraw);
    const int tid  = threadIdx.x;
    const int wid  = tid >> 5;
    const int lane = tid & 31;
    const int wm   = wid & 1;           // 0..1 -> 64-row half
    const int wn   = wid >> 1;          // 0..3 -> 32-col quarter
    const int m0   = blockIdx.y * BM;
    const int n0   = blockIdx.x * BN;

    const __half* A0h = Ah + (size_t)m0 * K;
    const __half* A0l = Al + (size_t)m0 * K;
    const __half* B0h = Bh + (size_t)n0 * K;
    const __half* B0l = Bl + (size_t)n0 * K;

    // stage s buffers
    auto bAh = [&](int s) { return sbase + s * STAGE_B; };
    auto bAl = [&](int s) { return sbase + s * STAGE_B + TILE_B; };
    auto bBh = [&](int s) { return sbase + s * STAGE_B + 2 * TILE_B; };
    auto bBl = [&](int s) { return sbase + s * STAGE_B + 3 * TILE_B; };

    // each thread loads 2 chunks per matrix (512 16B-chunks / 256 threads)
    const int idx0 = tid, idx1 = tid + 256;
    const int r0c = idx0 >> 2, c0c = idx0 & 3;
    const int r1c = idx1 >> 2, c1c = idx1 & 3;

    auto load_stage = [&](int s, int k0) {
        uint32_t dA0 = r0c * ROWB + c0c * 16, dA1 = r1c * ROWB + c1c * 16;
        size_t sA0 = (size_t)r0c * K + k0 + c0c * 8;
        size_t sA1 = (size_t)r1c * K + k0 + c1c * 8;
        cp16(bAh(s) + dA0, A0h + sA0);  cp16(bAh(s) + dA1, A0h + sA1);
        cp16(bAl(s) + dA0, A0l + sA0);  cp16(bAl(s) + dA1, A0l + sA1);
        cp16(bBh(s) + dA0, B0h + sA0);  cp16(bBh(s) + dA1, B0h + sA1);
        cp16(bBl(s) + dA0, B0l + sA0);  cp16(bBl(s) + dA1, B0l + sA1);
    };

    float acc[4][4][4];
#pragma unroll
    for (int i = 0; i < 4; i++)
#pragma unroll
        for (int j = 0; j < 4; j++)
#pragma unroll
            for (int t = 0; t < 4; t++) acc[i][j][t] = 0.f;

    // ldmatrix lane address offsets
    const int aRow = lane & 15;                 // A: rows m0w + mi*16 + aRow
    const int aKof = (lane >> 4) * 16;          // +16B for k+8 half
    const int bRow = (lane & 7) + ((lane & 16) ? 8 : 0);
    const int bKof = (lane & 8) ? 16 : 0;

    const int warpM = wm * 64;
    const int warpN = wn * 32;

    const int nst = K / BK;                     // 128
    load_stage(0, 0);
    cp_commit();

    for (int s = 0; s < nst; s++) {
        const int buf = s & 1;
        if (s + 1 < nst) {
            load_stage(1 - buf, (s + 1) * BK);
            cp_commit();
            cp_wait<1>();
        } else {
            cp_wait<0>();
        }
        __syncthreads();

        const uint32_t sAh = bAh(buf), sAl = bAl(buf);
        const uint32_t sBh = bBh(buf), sBl = bBl(buf);

#pragma unroll
        for (int ks = 0; ks < 2; ks++) {
            const int kb = ks * 32;             // byte offset of k16 step
            uint32_t ah[4][4], al[4][4], bh[2][4], bl[2][4];
#pragma unroll
            for (int mi = 0; mi < 4; mi++) {
                uint32_t ad = (uint32_t)((warpM + mi * 16 + aRow) * ROWB + kb + aKof);
                ldm_x4(ah[mi], sAh + ad);
                ldm_x4(al[mi], sAl + ad);
            }
#pragma unroll
            for (int np = 0; np < 2; np++) {
                uint32_t bd = (uint32_t)((warpN + np * 16 + bRow) * ROWB + kb + bKof);
                ldm_x4(bh[np], sBh + bd);
                ldm_x4(bl[np], sBl + bd);
            }
            // term 1: Ah*Bh
#pragma unroll
            for (int mi = 0; mi < 4; mi++)
#pragma unroll
                for (int ni = 0; ni < 4; ni++)
                    mma16816(acc[mi][ni], ah[mi], bh[ni >> 1][(ni & 1) * 2],
                             bh[ni >> 1][(ni & 1) * 2 + 1]);
            // term 2: Ah*Bl
#pragma unroll
            for (int mi = 0; mi < 4; mi++)
#pragma unroll
                for (int ni = 0; ni < 4; ni++)
                    mma16816(acc[mi][ni], ah[mi], bl[ni >> 1][(ni & 1) * 2],
                             bl[ni >> 1][(ni & 1) * 2 + 1]);
            // term 3: Al*Bh
#pragma unroll
            for (int mi = 0; mi < 4; mi++)
#pragma unroll
                for (int ni = 0; ni < 4; ni++)
                    mma16816(acc[mi][ni], al[mi], bh[ni >> 1][(ni & 1) * 2],
                             bh[ni >> 1][(ni & 1) * 2 + 1]);
        }
        __syncthreads();
    }

    // epilogue
    const int er = lane >> 2;
    const int ec = (lane & 3) * 2;
#pragma unroll
    for (int mi = 0; mi < 4; mi++) {
#pragma unroll
        for (int ni = 0; ni < 4; ni++) {
            float* p = C + (size_t)(m0 + warpM + mi * 16 + er) * N
                         + (n0 + warpN + ni * 8 + ec);
            p[0] = acc[mi][ni][0];
            p[1] = acc[mi][ni][1];
            float* q = p + (size_t)8 * N;
            q[0] = acc[mi][ni][2];
            q[1] = acc[mi][ni][3];
        }
    }
}

// ======================= flash attention (fp32) =============================
#define QT_LD 68
#define KT_LD 68
#define FLASH_SMEM_FLOATS (128*QT_LD + 128*KT_LD + 64*128 + 64*64)
#define FLASH_SMEM_BYTES  (FLASH_SMEM_FLOATS * 4)

__device__ __forceinline__ float rmax16(float v) {
#pragma unroll
    for (int o = 8; o > 0; o >>= 1) v = fmaxf(v, __shfl_xor_sync(0xffffffffu, v, o));
    return v;
}
__device__ __forceinline__ float rsum16(float v) {
#pragma unroll
    for (int o = 8; o > 0; o >>= 1) v += __shfl_xor_sync(0xffffffffu, v, o);
    return v;
}

__global__ __launch_bounds__(256) void flash_gqa()
{
    extern __shared__ float smf[];
    float* Qt = smf;
    float* Kt = Qt + 128 * QT_LD;
    float* Vs = Kt + 128 * KT_LD;
    float* Ps = Vs + 64 * 128;

    const int tid = threadIdx.x;
    const int tx  = tid & 15;
    const int ty  = tid >> 4;
    const int qb  = blockIdx.x;
    const int hq  = blockIdx.y;
    const int b   = blockIdx.z;
    const int kv  = hq >> 2;
    const int r0  = qb * 64;
    const float scale = 0.08838834764831845f;

    const float* Qg = g_Q + (size_t)(b * SEQ + r0) * HIDDEN + hq * HD;
    for (int idx = tid; idx < 64 * 128; idx += 256) {
        int r = idx >> 7, d = idx & 127;
        Qt[d * QT_LD + r] = Qg[(size_t)r * HIDDEN + d] * scale;
    }

    float m_i[4], l_i[4], o[4][8];
#pragma unroll
    for (int i = 0; i < 4; i++) {
        m_i[i] = -1e30f; l_i[i] = 0.f;
#pragma unroll
        for (int c = 0; c < 8; c++) o[i][c] = 0.f;
    }

    const float* Kg = g_K + (size_t)(b * SEQ) * KVDIM + kv * HD;
    const float* Vg = g_V + (size_t)(b * SEQ) * KVDIM + kv * HD;

    for (int j = 0; j <= qb; j++) {
        const int c0 = j * 64;
        __syncthreads();
        for (int idx = tid; idx < 64 * 128; idx += 256) {
            int r = idx >> 7, d = idx & 127;
            Kt[d * KT_LD + r] = Kg[(size_t)(c0 + r) * KVDIM + d];
            Vs[r * 128 + d]   = Vg[(size_t)(c0 + r) * KVDIM + d];
        }
        __syncthreads();

        float s[4][4];
#pragma unroll
        for (int i = 0; i < 4; i++)
#pragma unroll
            for (int jj = 0; jj < 4; jj++) s[i][jj] = 0.f;

#pragma unroll 4
        for (int k = 0; k < 128; k++) {
            float4 av = *(const float4*)&Qt[k * QT_LD + ty * 4];
            float4 bv = *(const float4*)&Kt[k * KT_LD + tx * 4];
            float ar[4] = {av.x, av.y, av.z, av.w};
            float br[4] = {bv.x, bv.y, bv.z, bv.w};
#pragma unroll
            for (int i = 0; i < 4; i++)
#pragma unroll
                for (int jj = 0; jj < 4; jj++)
                    s[i][jj] = fmaf(ar[i], br[jj], s[i][jj]);
        }

        if (j == qb) {
#pragma unroll
            for (int i = 0; i < 4; i++)
#pragma unroll
                for (int jj = 0; jj < 4; jj++)
                    if (tx * 4 + jj > ty * 4 + i) s[i][jj] = -1e30f;
        }

        float alpha[4];
#pragma unroll
        for (int i = 0; i < 4; i++) {
            float mv = fmaxf(fmaxf(s[i][0], s[i][1]), fmaxf(s[i][2], s[i][3]));
            mv = rmax16(mv);
            float mnew = fmaxf(m_i[i], mv);
            alpha[i] = __expf(m_i[i] - mnew);
            float sum = 0.f;
#pragma unroll
            for (int jj = 0; jj < 4; jj++) {
                float p = __expf(s[i][jj] - mnew);
                s[i][jj] = p;
                sum += p;
            }
            sum = rsum16(sum);
            l_i[i] = l_i[i] * alpha[i] + sum;
            m_i[i] = mnew;
        }

#pragma unroll
        for (int i = 0; i < 4; i++)
#pragma unroll
            for (int c = 0; c < 8; c++) o[i][c] *= alpha[i];

#pragma unroll
        for (int i = 0; i < 4; i++)
            *(float4*)&Ps[(ty * 4 + i) * 64 + tx * 4] =
                make_float4(s[i][0], s[i][1], s[i][2], s[i][3]);
        __syncthreads();

#pragma unroll 2
        for (int n = 0; n < 64; n++) {
            float p0 = Ps[(ty * 4 + 0) * 64 + n];
            float p1 = Ps[(ty * 4 + 1) * 64 + n];
            float p2 = Ps[(ty * 4 + 2) * 64 + n];
            float p3 = Ps[(ty * 4 + 3) * 64 + n];
            float4 v0 = *(const float4*)&Vs[n * 128 + tx * 8];
            float4 v1 = *(const float4*)&Vs[n * 128 + tx * 8 + 4];
            float vr[8] = {v0.x, v0.y, v0.z, v0.w, v1.x, v1.y, v1.z, v1.w};
#pragma unroll
            for (int c = 0; c < 8; c++) {
                o[0][c] = fmaf(p0, vr[c], o[0][c]);
                o[1][c] = fmaf(p1, vr[c], o[1][c]);
                o[2][c] = fmaf(p2, vr[c], o[2][c]);
                o[3][c] = fmaf(p3, vr[c], o[3][c]);
            }
        }
    }

    float* Og = g_AO + (size_t)(b * SEQ + r0) * HIDDEN + hq * HD;
#pragma unroll
    for (int i = 0; i < 4; i++) {
        float inv = 1.f / l_i[i];
        int r = ty * 4 + i;
        *(float4*)&Og[(size_t)r * HIDDEN + tx * 8] =
            make_float4(o[i][0] * inv, o[i][1] * inv, o[i][2] * inv, o[i][3] * inv);
        *(float4*)&Og[(size_t)r * HIDDEN + tx * 8 + 4] =
            make_float4(o[i][4] * inv, o[i][5] * inv, o[i][6] * inv, o[i][7] * inv);
    }
}

// ============================================================================
extern "C" void kernel_launch(void* const* d_in, const int* in_sizes, int n_in,
                              void* d_out, int out_size)
{
    const float* x  = (const float*)d_in[0];
    const float* Wq = (const float*)d_in[1];
    const float* Wk = (const float*)d_in[2];
    const float* Wv = (const float*)d_in[3];
    const float* Wo = (const float*)d_in[4];
    float* out = (float*)d_out;

    float *Qp, *Kp, *Vp, *AOp;
    __half *xh, *xl, *wqh, *wql, *wkh, *wkl, *wvh, *wvl, *woh, *wol, *aoh, *aol;
    cudaGetSymbolAddress((void**)&Qp,  g_Q);
    cudaGetSymbolAddress((void**)&Kp,  g_K);
    cudaGetSymbolAddress((void**)&Vp,  g_V);
    cudaGetSymbolAddress((void**)&AOp, g_AO);
    cudaGetSymbolAddress((void**)&xh,  g_xh);  cudaGetSymbolAddress((void**)&xl,  g_xl);
    cudaGetSymbolAddress((void**)&wqh, g_wqh); cudaGetSymbolAddress((void**)&wql, g_wql);
    cudaGetSymbolAddress((void**)&wkh, g_wkh); cudaGetSymbolAddress((void**)&wkl, g_wkl);
    cudaGetSymbolAddress((void**)&wvh, g_wvh); cudaGetSymbolAddress((void**)&wvl, g_wvl);
    cudaGetSymbolAddress((void**)&woh, g_woh); cudaGetSymbolAddress((void**)&wol, g_wol);
    cudaGetSymbolAddress((void**)&aoh, g_aoh); cudaGetSymbolAddress((void**)&aol, g_aol);

    cudaFuncSetAttribute(gemm_hmma, cudaFuncAttributeMaxDynamicSharedMemorySize, GEMM_SMEM);
    cudaFuncSetAttribute(flash_gqa, cudaFuncAttributeMaxDynamicSharedMemorySize,
                         FLASH_SMEM_BYTES);

    const int XN4 = TOKENS * HIDDEN / 4;
    const int WN4 = HIDDEN * HIDDEN / 4;
    const int KN4 = KVDIM * HIDDEN / 4;

    split_f32<<<(XN4 + 255) / 256, 256>>>((const float4*)x,  (__half2*)xh,  (__half2*)xl,  XN4);
    split_f32<<<(WN4 + 255) / 256, 256>>>((const float4*)Wq, (__half2*)wqh, (__half2*)wql, WN4);
    split_f32<<<(KN4 + 255) / 256, 256>>>((const float4*)Wk, (__half2*)wkh, (__half2*)wkl, KN4);
    split_f32<<<(KN4 + 255) / 256, 256>>>((const float4*)Wv, (__half2*)wvh, (__half2*)wvl, KN4);
    split_f32<<<(WN4 + 255) / 256, 256>>>((const float4*)Wo, (__half2*)woh, (__half2*)wol, WN4);

    gemm_hmma<<<dim3(HIDDEN / BN, TOKENS / BM), 256, GEMM_SMEM>>>(xh, xl, wqh, wql, Qp, HIDDEN, HIDDEN);
    gemm_hmma<<<dim3(KVDIM  / BN, TOKENS / BM), 256, GEMM_SMEM>>>(xh, xl, wkh, wkl, Kp, KVDIM, HIDDEN);
    gemm_hmma<<<dim3(KVDIM  / BN, TOKENS / BM), 256, GEMM_SMEM>>>(xh, xl, wvh, wvl, Vp, KVDIM, HIDDEN);

    flash_gqa<<<dim3(SEQ / 64, NH, BATCH), 256, FLASH_SMEM_BYTES>>>();

    split_f32<<<(XN4 + 255) / 256, 256>>>((const float4*)AOp, (__half2*)aoh, (__half2*)aol, XN4);
    gemm_hmma<<<dim3(HIDDEN / BN, TOKENS / BM), 256, GEMM_SMEM>>>(aoh, aol, woh, wol, out, HIDDEN, HIDDEN);
}

// round 4
// speedup vs baseline: 2.7656x; 1.5760x over previous
#include <cuda_runtime.h>
#include <cuda_fp16.h>
#include <cstdint>
#include <math.h>

#define HIDDEN   4096
#define NKV      8
#define NH       32
#define HD       128
#define BATCH    2
#define SEQ      2048
#define TOKENS   (BATCH*SEQ)   // 4096
#define KVDIM    (NKV*HD)      // 1024

// ---------------- scratch (device globals; no runtime allocation) ----------
__device__ __half g_xh [TOKENS*HIDDEN], g_xl [TOKENS*HIDDEN];
__device__ __half g_wqh[HIDDEN*HIDDEN], g_wql[HIDDEN*HIDDEN];
__device__ __half g_wkh[KVDIM*HIDDEN],  g_wkl[KVDIM*HIDDEN];
__device__ __half g_wvh[KVDIM*HIDDEN],  g_wvl[KVDIM*HIDDEN];
__device__ __half g_woh[HIDDEN*HIDDEN], g_wol[HIDDEN*HIDDEN];
__device__ __half g_qh [TOKENS*HIDDEN], g_ql [TOKENS*HIDDEN];
__device__ __half g_kh [TOKENS*KVDIM],  g_kl [TOKENS*KVDIM];
__device__ __half g_vh [TOKENS*KVDIM],  g_vl [TOKENS*KVDIM];
__device__ __half g_vth[TOKENS*KVDIM],  g_vtl[TOKENS*KVDIM];  // [B][KVDIM][SEQ]
__device__ __half g_aoh[TOKENS*HIDDEN], g_aol[TOKENS*HIDDEN];

// ======================= helpers ============================================
__device__ __forceinline__ uint32_t smem_u32(const void* p) {
    uint32_t a;
    asm("{ .reg .u64 t; cvta.to.shared.u64 t, %1; cvt.u32.u64 %0, t; }"
        : "=r"(a) : "l"(p));
    return a;
}
__device__ __forceinline__ void cp16(uint32_t dst, const void* src) {
    asm volatile("cp.async.cg.shared.global [%0], [%1], 16;" :: "r"(dst), "l"(src));
}
__device__ __forceinline__ void cp_commit() { asm volatile("cp.async.commit_group;" ::: "memory"); }
template<int N> __device__ __forceinline__ void cp_wait() {
    asm volatile("cp.async.wait_group %0;" :: "n"(N) : "memory");
}
__device__ __forceinline__ void ldm_x4(uint32_t* r, uint32_t addr) {
    asm volatile("ldmatrix.sync.aligned.m8n8.x4.shared.b16 {%0,%1,%2,%3}, [%4];"
        : "=r"(r[0]), "=r"(r[1]), "=r"(r[2]), "=r"(r[3]) : "r"(addr));
}
__device__ __forceinline__ void mma16816(float* d, const uint32_t* a,
                                         uint32_t b0, uint32_t b1) {
    asm volatile(
        "mma.sync.aligned.m16n8k16.row.col.f32.f16.f16.f32 "
        "{%0,%1,%2,%3}, {%4,%5,%6,%7}, {%8,%9}, {%0,%1,%2,%3};"
        : "+f"(d[0]), "+f"(d[1]), "+f"(d[2]), "+f"(d[3])
        : "r"(a[0]), "r"(a[1]), "r"(a[2]), "r"(a[3]), "r"(b0), "r"(b1));
}
__device__ __forceinline__ uint32_t pack_h2(__half a, __half b) {
    __half2 h = __halves2half2(a, b);
    return *(uint32_t*)&h;
}

// ======================= split fp32 -> fp16 hi/lo ==========================
__global__ __launch_bounds__(256) void split_f32(
    const float4* __restrict__ x, __half2* __restrict__ hi,
    __half2* __restrict__ lo, int n4)
{
    int i = blockIdx.x * blockDim.x + threadIdx.x;
    if (i >= n4) return;
    float4 v = x[i];
    __half h0 = __float2half_rn(v.x), h1 = __float2half_rn(v.y);
    __half h2 = __float2half_rn(v.z), h3 = __float2half_rn(v.w);
    __half l0 = __float2half_rn(v.x - __half2float(h0));
    __half l1 = __float2half_rn(v.y - __half2float(h1));
    __half l2 = __float2half_rn(v.z - __half2float(h2));
    __half l3 = __float2half_rn(v.w - __half2float(h3));
    hi[2 * i]     = __halves2half2(h0, h1);
    hi[2 * i + 1] = __halves2half2(h2, h3);
    lo[2 * i]     = __halves2half2(l0, l1);
    lo[2 * i + 1] = __halves2half2(l2, l3);
}

// ======================= HMMA GEMM: C = A @ B^T =============================
#define BM 128
#define BN 128
#define BK 32
#define ROWB 80
#define TILE_B (128*ROWB)
#define STAGE_B (4*TILE_B)
#define GEMM_SMEM (2*STAGE_B)

__global__ __launch_bounds__(256, 1) void gemm_hmma(
    const __half* __restrict__ Ah, const __half* __restrict__ Al,
    const __half* __restrict__ Bh, const __half* __restrict__ Bl,
    float* __restrict__ C, __half* __restrict__ Ch, __half* __restrict__ Cl,
    int N, int K, int split_out)
{
    extern __shared__ char smraw[];
    const uint32_t sbase = smem_u32(smraw);
    const int tid  = threadIdx.x;
    const int wid  = tid >> 5;
    const int lane = tid & 31;
    const int wm   = wid & 1;
    const int wn   = wid >> 1;
    const int m0   = blockIdx.y * BM;
    const int n0   = blockIdx.x * BN;

    const __half* A0h = Ah + (size_t)m0 * K;
    const __half* A0l = Al + (size_t)m0 * K;
    const __half* B0h = Bh + (size_t)n0 * K;
    const __half* B0l = Bl + (size_t)n0 * K;

    auto bAh = [&](int s) { return sbase + s * STAGE_B; };
    auto bAl = [&](int s) { return sbase + s * STAGE_B + TILE_B; };
    auto bBh = [&](int s) { return sbase + s * STAGE_B + 2 * TILE_B; };
    auto bBl = [&](int s) { return sbase + s * STAGE_B + 3 * TILE_B; };

    const int idx0 = tid, idx1 = tid + 256;
    const int r0c = idx0 >> 2, c0c = idx0 & 3;
    const int r1c = idx1 >> 2, c1c = idx1 & 3;

    auto load_stage = [&](int s, int k0) {
        uint32_t dA0 = r0c * ROWB + c0c * 16, dA1 = r1c * ROWB + c1c * 16;
        size_t sA0 = (size_t)r0c * K + k0 + c0c * 8;
        size_t sA1 = (size_t)r1c * K + k0 + c1c * 8;
        cp16(bAh(s) + dA0, A0h + sA0);  cp16(bAh(s) + dA1, A0h + sA1);
        cp16(bAl(s) + dA0, A0l + sA0);  cp16(bAl(s) + dA1, A0l + sA1);
        cp16(bBh(s) + dA0, B0h + sA0);  cp16(bBh(s) + dA1, B0h + sA1);
        cp16(bBl(s) + dA0, B0l + sA0);  cp16(bBl(s) + dA1, B0l + sA1);
    };

    float acc[4][4][4];
#pragma unroll
    for (int i = 0; i < 4; i++)
#pragma unroll
        for (int j = 0; j < 4; j++)
#pragma unroll
            for (int t = 0; t < 4; t++) acc[i][j][t] = 0.f;

    const int aRow = lane & 15;
    const int aKof = (lane >> 4) * 16;
    const int bRow = (lane & 7) + ((lane & 16) ? 8 : 0);
    const int bKof = (lane & 8) ? 16 : 0;

    const int warpM = wm * 64;
    const int warpN = wn * 32;

    const int nst = K / BK;
    load_stage(0, 0);
    cp_commit();

    for (int s = 0; s < nst; s++) {
        const int buf = s & 1;
        if (s + 1 < nst) {
            load_stage(1 - buf, (s + 1) * BK);
            cp_commit();
            cp_wait<1>();
        } else {
            cp_wait<0>();
        }
        __syncthreads();

        const uint32_t sAh = bAh(buf), sAl = bAl(buf);
        const uint32_t sBh = bBh(buf), sBl = bBl(buf);

#pragma unroll
        for (int ks = 0; ks < 2; ks++) {
            const int kb = ks * 32;
            uint32_t ah[4][4], al[4][4], bh[2][4], bl[2][4];
#pragma unroll
            for (int mi = 0; mi < 4; mi++) {
                uint32_t ad = (uint32_t)((warpM + mi * 16 + aRow) * ROWB + kb + aKof);
                ldm_x4(ah[mi], sAh + ad);
                ldm_x4(al[mi], sAl + ad);
            }
#pragma unroll
            for (int np = 0; np < 2; np++) {
                uint32_t bd = (uint32_t)((warpN + np * 16 + bRow) * ROWB + kb + bKof);
                ldm_x4(bh[np], sBh + bd);
                ldm_x4(bl[np], sBl + bd);
            }
#pragma unroll
            for (int mi = 0; mi < 4; mi++)
#pragma unroll
                for (int ni = 0; ni < 4; ni++)
                    mma16816(acc[mi][ni], ah[mi], bh[ni >> 1][(ni & 1) * 2],
                             bh[ni >> 1][(ni & 1) * 2 + 1]);
#pragma unroll
            for (int mi = 0; mi < 4; mi++)
#pragma unroll
                for (int ni = 0; ni < 4; ni++)
                    mma16816(acc[mi][ni], ah[mi], bl[ni >> 1][(ni & 1) * 2],
                             bl[ni >> 1][(ni & 1) * 2 + 1]);
#pragma unroll
            for (int mi = 0; mi < 4; mi++)
#pragma unroll
                for (int ni = 0; ni < 4; ni++)
                    mma16816(acc[mi][ni], al[mi], bh[ni >> 1][(ni & 1) * 2],
                             bh[ni >> 1][(ni & 1) * 2 + 1]);
        }
        __syncthreads();
    }

    const int er = lane >> 2;
    const int ec = (lane & 3) * 2;
    if (!split_out) {
#pragma unroll
        for (int mi = 0; mi < 4; mi++)
#pragma unroll
            for (int ni = 0; ni < 4; ni++) {
                float* p = C + (size_t)(m0 + warpM + mi * 16 + er) * N
                             + (n0 + warpN + ni * 8 + ec);
                p[0] = acc[mi][ni][0];
                p[1] = acc[mi][ni][1];
                float* q = p + (size_t)8 * N;
                q[0] = acc[mi][ni][2];
                q[1] = acc[mi][ni][3];
            }
    } else {
#pragma unroll
        for (int mi = 0; mi < 4; mi++)
#pragma unroll
            for (int ni = 0; ni < 4; ni++) {
                size_t off0 = (size_t)(m0 + warpM + mi * 16 + er) * N
                            + (n0 + warpN + ni * 8 + ec);
                size_t off1 = off0 + (size_t)8 * N;
                float v0 = acc[mi][ni][0], v1 = acc[mi][ni][1];
                float v2 = acc[mi][ni][2], v3 = acc[mi][ni][3];
                __half h0 = __float2half_rn(v0), h1 = __float2half_rn(v1);
                __half h2 = __float2half_rn(v2), h3 = __float2half_rn(v3);
                *(uint32_t*)(Ch + off0) = pack_h2(h0, h1);
                *(uint32_t*)(Ch + off1) = pack_h2(h2, h3);
                *(uint32_t*)(Cl + off0) = pack_h2(
                    __float2half_rn(v0 - __half2float(h0)),
                    __float2half_rn(v1 - __half2float(h1)));
                *(uint32_t*)(Cl + off1) = pack_h2(
                    __float2half_rn(v2 - __half2float(h2)),
                    __float2half_rn(v3 - __half2float(h3)));
            }
    }
}

// ======================= V transpose (halves) ===============================
// in: [B*SEQ][KVDIM]; out: [B][KVDIM][SEQ]
__global__ __launch_bounds__(256) void transpose_v(
    const __half* __restrict__ vh, const __half* __restrict__ vl,
    __half* __restrict__ vth, __half* __restrict__ vtl)
{
    __shared__ __half th[32][33], tl[32][33];
    const int b  = blockIdx.z;
    const int k0 = blockIdx.y * 32;
    const int s0 = blockIdx.x * 32;
    const int tx = threadIdx.x & 31;
    const int ty = threadIdx.x >> 5;   // 0..7
#pragma unroll
    for (int i = 0; i < 4; i++) {
        int row = ty + i * 8;
        size_t src = (size_t)(b * SEQ + s0 + row) * KVDIM + k0 + tx;
        th[row][tx] = vh[src];
        tl[row][tx] = vl[src];
    }
    __syncthreads();
#pragma unroll
    for (int i = 0; i < 4; i++) {
        int row = ty + i * 8;
        size_t dst = ((size_t)b * KVDIM + k0 + row) * SEQ + s0 + tx;
        vth[dst] = th[tx][row];
        vtl[dst] = tl[tx][row];
    }
}

// ======================= HMMA flash attention ===============================
// CTA: 128 q rows x one (head, batch). 8 warps, warp w owns rows [16w,16w+16).
// kv blocks of 64, double-buffered. 3-term fp16 split both GEMMs.
#define QROWB 272
#define KROWB 272
#define VROWB 144
#define SQ_L      34816
#define SKV_BASE  69632
#define SKV_STRIDE 71680
#define OFF_KH 0
#define OFF_KL 17408
#define OFF_VTH 34816
#define OFF_VTL 53248
#define FLASH_SMEM 212992

__global__ __launch_bounds__(256, 1) void flash_hmma(
    const __half* __restrict__ qh, const __half* __restrict__ ql,
    const __half* __restrict__ kh, const __half* __restrict__ kl,
    const __half* __restrict__ vth, const __half* __restrict__ vtl,
    __half* __restrict__ aoh, __half* __restrict__ aol)
{
    extern __shared__ char smraw[];
    const uint32_t sb = smem_u32(smraw);
    const int tid = threadIdx.x, wid = tid >> 5, lane = tid & 31;
    const int qb = (int)(gridDim.x - 1 - blockIdx.x);   // big work first
    const int hq = blockIdx.y, b = blockIdx.z;
    const int kvh = hq >> 2;
    const int qrow0 = qb * 128;
    const int g = lane >> 2, tig = lane & 3;
    const float scale = 0.08838834764831845f;

    // ---- Q tile load (fp16 hi/lo) ----
    const __half* qhg = qh + (size_t)(b * SEQ + qrow0) * HIDDEN + hq * HD;
    const __half* qlg = ql + (size_t)(b * SEQ + qrow0) * HIDDEN + hq * HD;
#pragma unroll
    for (int t = 0; t < 8; t++) {
        int idx = tid + t * 256;
        int r = idx >> 4, c = idx & 15;
        uint32_t d = (uint32_t)(r * QROWB + c * 16);
        size_t s = (size_t)r * HIDDEN + c * 8;
        cp16(sb + d, qhg + s);
        cp16(sb + SQ_L + d, qlg + s);
    }
    cp_commit();

    const __half* khg = kh + (size_t)(b * SEQ) * KVDIM + kvh * HD;
    const __half* klg = kl + (size_t)(b * SEQ) * KVDIM + kvh * HD;
    const __half* vthg = vth + ((size_t)b * KVDIM + kvh * HD) * SEQ;
    const __half* vtlg = vtl + ((size_t)b * KVDIM + kvh * HD) * SEQ;

    auto load_kv = [&](int stage, int j) {
        uint32_t base = sb + SKV_BASE + stage * SKV_STRIDE;
        int c0 = j * 64;
#pragma unroll
        for (int t = 0; t < 4; t++) {                 // K: 64 rows x 16 chunks
            int idx = tid + t * 256;
            int r = idx >> 4, c = idx & 15;
            uint32_t d = (uint32_t)(r * KROWB + c * 16);
            size_t s = (size_t)(c0 + r) * KVDIM + c * 8;
            cp16(base + OFF_KH + d, khg + s);
            cp16(base + OFF_KL + d, klg + s);
        }
#pragma unroll
        for (int t = 0; t < 4; t++) {                 // Vt: 128 rows x 8 chunks
            int idx = tid + t * 256;
            int r = idx >> 3, c = idx & 7;
            uint32_t d = (uint32_t)(r * VROWB + c * 16);
            size_t s = (size_t)r * SEQ + c0 + c * 8;
            cp16(base + OFF_VTH + d, vthg + s);
            cp16(base + OFF_VTL + d, vtlg + s);
        }
    };

    const int nb = 2 * qb + 2;
    load_kv(0, 0);
    cp_commit();

    float oacc[16][4];
#pragma unroll
    for (int i = 0; i < 16; i++)
#pragma unroll
        for (int t = 0; t < 4; t++) oacc[i][t] = 0.f;
    float m0 = -1e30f, m1 = -1e30f, l0 = 0.f, l1 = 0.f;

    const int aRow = lane & 15;
    const int aKof = (lane >> 4) * 16;
    const int bRow = (lane & 7) + ((lane & 16) ? 8 : 0);
    const int bKof = (lane & 8) ? 16 : 0;

    const int rg0 = qrow0 + 16 * wid + g;
    const int rg1 = rg0 + 8;

    for (int j = 0; j < nb; j++) {
        const int buf = j & 1;
        if (j + 1 < nb) {
            load_kv(1 - buf, j + 1);
            cp_commit();
            cp_wait<1>();
        } else {
            cp_wait<0>();
        }
        __syncthreads();

        const uint32_t kbase = sb + SKV_BASE + buf * SKV_STRIDE;

        // ---- S = Q @ K^T (3-term split) ----
        float sacc[8][4];
#pragma unroll
        for (int i = 0; i < 8; i++)
#pragma unroll
            for (int t = 0; t < 4; t++) sacc[i][t] = 0.f;

#pragma unroll
        for (int kd = 0; kd < 8; kd++) {
            uint32_t aa = (uint32_t)((16 * wid + aRow) * QROWB + kd * 32 + aKof);
            uint32_t ah[4], al[4];
            ldm_x4(ah, sb + aa);
            ldm_x4(al, sb + SQ_L + aa);
            uint32_t bh[4][4], bl[4][4];
#pragma unroll
            for (int np = 0; np < 4; np++) {
                uint32_t ba = (uint32_t)((np * 16 + bRow) * KROWB + kd * 32 + bKof);
                ldm_x4(bh[np], kbase + OFF_KH + ba);
                ldm_x4(bl[np], kbase + OFF_KL + ba);
            }
#pragma unroll
            for (int ni = 0; ni < 8; ni++) {
                uint32_t b0h = bh[ni >> 1][(ni & 1) * 2], b1h = bh[ni >> 1][(ni & 1) * 2 + 1];
                uint32_t b0l = bl[ni >> 1][(ni & 1) * 2], b1l = bl[ni >> 1][(ni & 1) * 2 + 1];
                mma16816(sacc[ni], ah, b0h, b1h);
                mma16816(sacc[ni], ah, b0l, b1l);
                mma16816(sacc[ni], al, b0h, b1h);
            }
        }

        // ---- scale + causal mask ----
        const int c0 = j * 64;
#pragma unroll
        for (int ni = 0; ni < 8; ni++)
#pragma unroll
            for (int t = 0; t < 4; t++) sacc[ni][t] *= scale;
        if (j >= 2 * qb) {
#pragma unroll
            for (int ni = 0; ni < 8; ni++) {
                int cg = c0 + ni * 8 + 2 * tig;
                if (cg     > rg0) sacc[ni][0] = -1e30f;
                if (cg + 1 > rg0) sacc[ni][1] = -1e30f;
                if (cg     > rg1) sacc[ni][2] = -1e30f;
                if (cg + 1 > rg1) sacc[ni][3] = -1e30f;
            }
        }

        // ---- online softmax ----
        float vm0 = -1e30f, vm1 = -1e30f;
#pragma unroll
        for (int ni = 0; ni < 8; ni++) {
            vm0 = fmaxf(vm0, fmaxf(sacc[ni][0], sacc[ni][1]));
            vm1 = fmaxf(vm1, fmaxf(sacc[ni][2], sacc[ni][3]));
        }
        vm0 = fmaxf(vm0, __shfl_xor_sync(0xffffffffu, vm0, 1));
        vm0 = fmaxf(vm0, __shfl_xor_sync(0xffffffffu, vm0, 2));
        vm1 = fmaxf(vm1, __shfl_xor_sync(0xffffffffu, vm1, 1));
        vm1 = fmaxf(vm1, __shfl_xor_sync(0xffffffffu, vm1, 2));
        float mn0 = fmaxf(m0, vm0), mn1 = fmaxf(m1, vm1);
        float al0 = __expf(m0 - mn0), al1 = __expf(m1 - mn1);
        float sum0 = 0.f, sum1 = 0.f;
#pragma unroll
        for (int ni = 0; ni < 8; ni++) {
            sacc[ni][0] = __expf(sacc[ni][0] - mn0);
            sacc[ni][1] = __expf(sacc[ni][1] - mn0);
            sacc[ni][2] = __expf(sacc[ni][2] - mn1);
            sacc[ni][3] = __expf(sacc[ni][3] - mn1);
            sum0 += sacc[ni][0] + sacc[ni][1];
            sum1 += sacc[ni][2] + sacc[ni][3];
        }
        sum0 += __shfl_xor_sync(0xffffffffu, sum0, 1);
        sum0 += __shfl_xor_sync(0xffffffffu, sum0, 2);
        sum1 += __shfl_xor_sync(0xffffffffu, sum1, 1);
        sum1 += __shfl_xor_sync(0xffffffffu, sum1, 2);
        l0 = l0 * al0 + sum0;  l1 = l1 * al1 + sum1;
        m0 = mn0;  m1 = mn1;

#pragma unroll
        for (int nd = 0; nd < 16; nd++) {
            oacc[nd][0] *= al0;  oacc[nd][1] *= al0;
            oacc[nd][2] *= al1;  oacc[nd][3] *= al1;
        }

        // ---- P fragments (fp16 hi/lo split, registers) ----
        uint32_t pah[4][4], pal[4][4];
#pragma unroll
        for (int t = 0; t < 4; t++) {
            float p00 = sacc[2 * t][0],     p01 = sacc[2 * t][1];
            float p10 = sacc[2 * t][2],     p11 = sacc[2 * t][3];
            float p20 = sacc[2 * t + 1][0], p21 = sacc[2 * t + 1][1];
            float p30 = sacc[2 * t + 1][2], p31 = sacc[2 * t + 1][3];
            __half h00 = __float2half_rn(p00), h01 = __float2half_rn(p01);
            __half h10 = __float2half_rn(p10), h11 = __float2half_rn(p11);
            __half h20 = __float2half_rn(p20), h21 = __float2half_rn(p21);
            __half h30 = __float2half_rn(p30), h31 = __float2half_rn(p31);
            pah[t][0] = pack_h2(h00, h01);
            pah[t][1] = pack_h2(h10, h11);
            pah[t][2] = pack_h2(h20, h21);
            pah[t][3] = pack_h2(h30, h31);
            pal[t][0] = pack_h2(__float2half_rn(p00 - __half2float(h00)),
                                __float2half_rn(p01 - __half2float(h01)));
            pal[t][1] = pack_h2(__float2half_rn(p10 - __half2float(h10)),
                                __float2half_rn(p11 - __half2float(h11)));
            pal[t][2] = pack_h2(__float2half_rn(p20 - __half2float(h20)),
                                __float2half_rn(p21 - __half2float(h21)));
            pal[t][3] = pack_h2(__float2half_rn(p30 - __half2float(h30)),
                                __float2half_rn(p31 - __half2float(h31)));
        }

        // ---- O += P @ V (V^T in smem, 3-term split) ----
#pragma unroll
        for (int t = 0; t < 4; t++) {
#pragma unroll
            for (int np = 0; np < 8; np++) {
                uint32_t ba = (uint32_t)((np * 16 + bRow) * VROWB + t * 32 + bKof);
                uint32_t vbh[4], vbl[4];
                ldm_x4(vbh, kbase + OFF_VTH + ba);
                ldm_x4(vbl, kbase + OFF_VTL + ba);
#pragma unroll
                for (int q = 0; q < 2; q++) {
                    int nd = np * 2 + q;
                    uint32_t b0h = vbh[q * 2], b1h = vbh[q * 2 + 1];
                    uint32_t b0l = vbl[q * 2], b1l = vbl[q * 2 + 1];
                    mma16816(oacc[nd], pah[t], b0h, b1h);
                    mma16816(oacc[nd], pah[t], b0l, b1l);
                    mma16816(oacc[nd], pal[t], b0h, b1h);
                }
            }
        }
        __syncthreads();
    }

    // ---- finalize: O/l -> fp16 hi/lo gmem ----
    float inv0 = 1.f / l0, inv1 = 1.f / l1;
    size_t row0 = (size_t)(b * SEQ + qrow0 + 16 * wid + g) * HIDDEN + hq * HD;
    size_t row1 = row0 + (size_t)8 * HIDDEN;
#pragma unroll
    for (int nd = 0; nd < 16; nd++) {
        int col = nd * 8 + 2 * tig;
        float v0 = oacc[nd][0] * inv0, v1 = oacc[nd][1] * inv0;
        float v2 = oacc[nd][2] * inv1, v3 = oacc[nd][3] * inv1;
        __half h0 = __float2half_rn(v0), h1 = __float2half_rn(v1);
        __half h2 = __float2half_rn(v2), h3 = __float2half_rn(v3);
        *(uint32_t*)(aoh + row0 + col) = pack_h2(h0, h1);
        *(uint32_t*)(aoh + row1 + col) = pack_h2(h2, h3);
        *(uint32_t*)(aol + row0 + col) = pack_h2(
            __float2half_rn(v0 - __half2float(h0)),
            __float2half_rn(v1 - __half2float(h1)));
        *(uint32_t*)(aol + row1 + col) = pack_h2(
            __float2half_rn(v2 - __half2float(h2)),
            __float2half_rn(v3 - __half2float(h3)));
    }
}

// ============================================================================
extern "C" void kernel_launch(void* const* d_in, const int* in_sizes, int n_in,
                              void* d_out, int out_size)
{
    const float* x  = (const float*)d_in[0];
    const float* Wq = (const float*)d_in[1];
    const float* Wk = (const float*)d_in[2];
    const float* Wv = (const float*)d_in[3];
    const float* Wo = (const float*)d_in[4];
    float* out = (float*)d_out;

    __half *xh, *xl, *wqh, *wql, *wkh, *wkl, *wvh, *wvl, *woh, *wol;
    __half *qh, *ql, *kh, *kl, *vh, *vl, *vth, *vtl, *aoh, *aol;
    cudaGetSymbolAddress((void**)&xh,  g_xh);  cudaGetSymbolAddress((void**)&xl,  g_xl);
    cudaGetSymbolAddress((void**)&wqh, g_wqh); cudaGetSymbolAddress((void**)&wql, g_wql);
    cudaGetSymbolAddress((void**)&wkh, g_wkh); cudaGetSymbolAddress((void**)&wkl, g_wkl);
    cudaGetSymbolAddress((void**)&wvh, g_wvh); cudaGetSymbolAddress((void**)&wvl, g_wvl);
    cudaGetSymbolAddress((void**)&woh, g_woh); cudaGetSymbolAddress((void**)&wol, g_wol);
    cudaGetSymbolAddress((void**)&qh,  g_qh);  cudaGetSymbolAddress((void**)&ql,  g_ql);
    cudaGetSymbolAddress((void**)&kh,  g_kh);  cudaGetSymbolAddress((void**)&kl,  g_kl);
    cudaGetSymbolAddress((void**)&vh,  g_vh);  cudaGetSymbolAddress((void**)&vl,  g_vl);
    cudaGetSymbolAddress((void**)&vth, g_vth); cudaGetSymbolAddress((void**)&vtl, g_vtl);
    cudaGetSymbolAddress((void**)&aoh, g_aoh); cudaGetSymbolAddress((void**)&aol, g_aol);

    cudaFuncSetAttribute(gemm_hmma, cudaFuncAttributeMaxDynamicSharedMemorySize, GEMM_SMEM);
    cudaFuncSetAttribute(flash_hmma, cudaFuncAttributeMaxDynamicSharedMemorySize, FLASH_SMEM);

    const int XN4 = TOKENS * HIDDEN / 4;
    const int WN4 = HIDDEN * HIDDEN / 4;
    const int KN4 = KVDIM * HIDDEN / 4;

    split_f32<<<(XN4 + 255) / 256, 256>>>((const float4*)x,  (__half2*)xh,  (__half2*)xl,  XN4);
    split_f32<<<(WN4 + 255) / 256, 256>>>((const float4*)Wq, (__half2*)wqh, (__half2*)wql, WN4);
    split_f32<<<(KN4 + 255) / 256, 256>>>((const float4*)Wk, (__half2*)wkh, (__half2*)wkl, KN4);
    split_f32<<<(KN4 + 255) / 256, 256>>>((const float4*)Wv, (__half2*)wvh, (__half2*)wvl, KN4);
    split_f32<<<(WN4 + 255) / 256, 256>>>((const float4*)Wo, (__half2*)woh, (__half2*)wol, WN4);

    // projections -> fp16 hi/lo outputs
    gemm_hmma<<<dim3(HIDDEN / BN, TOKENS / BM), 256, GEMM_SMEM>>>(
        xh, xl, wqh, wql, nullptr, qh, ql, HIDDEN, HIDDEN, 1);
    gemm_hmma<<<dim3(KVDIM / BN, TOKENS / BM), 256, GEMM_SMEM>>>(
        xh, xl, wkh, wkl, nullptr, kh, kl, KVDIM, HIDDEN, 1);
    gemm_hmma<<<dim3(KVDIM / BN, TOKENS / BM), 256, GEMM_SMEM>>>(
        xh, xl, wvh, wvl, nullptr, vh, vl, KVDIM, HIDDEN, 1);

    transpose_v<<<dim3(SEQ / 32, KVDIM / 32, BATCH), 256>>>(vh, vl, vth, vtl);

    flash_hmma<<<dim3(SEQ / 128, NH, BATCH), 256, FLASH_SMEM>>>(
        qh, ql, kh, kl, vth, vtl, aoh, aol);

    gemm_hmma<<<dim3(HIDDEN / BN, TOKENS / BM), 256, GEMM_SMEM>>>(
        aoh, aol, woh, wol, out, nullptr, nullptr, HIDDEN, HIDDEN, 0);
}

// round 5
// speedup vs baseline: 3.1055x; 1.1229x over previous
#include <cuda_runtime.h>
#include <cuda_fp16.h>
#include <cstdint>
#include <math.h>

#define HIDDEN   4096
#define NKV      8
#define NH       32
#define HD       128
#define BATCH    2
#define SEQ      2048
#define TOKENS   (BATCH*SEQ)   // 4096
#define KVDIM    (NKV*HD)      // 1024

// ---------------- scratch (device globals; no runtime allocation) ----------
__device__ __half g_xh [TOKENS*HIDDEN], g_xl [TOKENS*HIDDEN];
__device__ __half g_wqh[HIDDEN*HIDDEN], g_wql[HIDDEN*HIDDEN];
__device__ __half g_wkh[KVDIM*HIDDEN],  g_wkl[KVDIM*HIDDEN];
__device__ __half g_wvh[KVDIM*HIDDEN],  g_wvl[KVDIM*HIDDEN];
__device__ __half g_woh[HIDDEN*HIDDEN], g_wol[HIDDEN*HIDDEN];
__device__ __half g_qh [TOKENS*HIDDEN], g_ql [TOKENS*HIDDEN];
__device__ __half g_kh [TOKENS*KVDIM],  g_kl [TOKENS*KVDIM];
__device__ __half g_vh [TOKENS*KVDIM],  g_vl [TOKENS*KVDIM];
__device__ __half g_vth[TOKENS*KVDIM],  g_vtl[TOKENS*KVDIM];  // [B][KVDIM][SEQ]
__device__ __half g_aoh[TOKENS*HIDDEN], g_aol[TOKENS*HIDDEN];

// ======================= helpers ============================================
__device__ __forceinline__ uint32_t smem_u32(const void* p) {
    uint32_t a;
    asm("{ .reg .u64 t; cvta.to.shared.u64 t, %1; cvt.u32.u64 %0, t; }"
        : "=r"(a) : "l"(p));
    return a;
}
__device__ __forceinline__ void cp16(uint32_t dst, const void* src) {
    asm volatile("cp.async.cg.shared.global [%0], [%1], 16;" :: "r"(dst), "l"(src));
}
__device__ __forceinline__ void cp_commit() { asm volatile("cp.async.commit_group;" ::: "memory"); }
template<int N> __device__ __forceinline__ void cp_wait() {
    asm volatile("cp.async.wait_group %0;" :: "n"(N) : "memory");
}
__device__ __forceinline__ void ldm_x4(uint32_t* r, uint32_t addr) {
    asm volatile("ldmatrix.sync.aligned.m8n8.x4.shared.b16 {%0,%1,%2,%3}, [%4];"
        : "=r"(r[0]), "=r"(r[1]), "=r"(r[2]), "=r"(r[3]) : "r"(addr));
}
__device__ __forceinline__ void mma16816(float* d, const uint32_t* a,
                                         uint32_t b0, uint32_t b1) {
    asm volatile(
        "mma.sync.aligned.m16n8k16.row.col.f32.f16.f16.f32 "
        "{%0,%1,%2,%3}, {%4,%5,%6,%7}, {%8,%9}, {%0,%1,%2,%3};"
        : "+f"(d[0]), "+f"(d[1]), "+f"(d[2]), "+f"(d[3])
        : "r"(a[0]), "r"(a[1]), "r"(a[2]), "r"(a[3]), "r"(b0), "r"(b1));
}
__device__ __forceinline__ uint32_t pack_h2(__half a, __half b) {
    __half2 h = __halves2half2(a, b);
    return *(uint32_t*)&h;
}

// ======================= split fp32 -> fp16 hi/lo ==========================
__global__ __launch_bounds__(256) void split_f32(
    const float4* __restrict__ x, __half2* __restrict__ hi,
    __half2* __restrict__ lo, int n4)
{
    int i = blockIdx.x * blockDim.x + threadIdx.x;
    if (i >= n4) return;
    float4 v = x[i];
    __half h0 = __float2half_rn(v.x), h1 = __float2half_rn(v.y);
    __half h2 = __float2half_rn(v.z), h3 = __float2half_rn(v.w);
    __half l0 = __float2half_rn(v.x - __half2float(h0));
    __half l1 = __float2half_rn(v.y - __half2float(h1));
    __half l2 = __float2half_rn(v.z - __half2float(h2));
    __half l3 = __float2half_rn(v.w - __half2float(h3));
    hi[2 * i]     = __halves2half2(h0, h1);
    hi[2 * i + 1] = __halves2half2(h2, h3);
    lo[2 * i]     = __halves2half2(l0, l1);
    lo[2 * i + 1] = __halves2half2(l2, l3);
}

// ======================= HMMA GEMM: C = A @ B^T =============================
// Tile 128x256xBK32, 8 warps (2m x 4n), warp tile 64x64, 3-stage cp.async.
#define BM 128
#define BN 256
#define BK 32
#define ROWB 80
#define A_ST (BM*ROWB)                // 10240 bytes per matrix
#define B_ST (BN*ROWB)                // 20480
#define STAGE_B (2*A_ST + 2*B_ST)     // 61440
#define NSTAGE 3
#define GEMM_SMEM (NSTAGE*STAGE_B)    // 184320

__global__ __launch_bounds__(256, 1) void gemm_hmma(
    const __half* __restrict__ Ah, const __half* __restrict__ Al,
    const __half* __restrict__ Bh, const __half* __restrict__ Bl,
    float* __restrict__ C, __half* __restrict__ Ch, __half* __restrict__ Cl,
    int N, int K, int split_out)
{
    extern __shared__ char smraw[];
    const uint32_t sbase = smem_u32(smraw);
    const int tid  = threadIdx.x;
    const int wid  = tid >> 5;
    const int lane = tid & 31;
    const int wm   = wid & 1;           // 0..1
    const int wn   = wid >> 1;          // 0..3

    // ---- CTA swizzle: supertiles of 8 m-blocks for L2 reuse ----
    const int gx = gridDim.x, gy = gridDim.y;
    int lin = blockIdx.y * gx + blockIdx.x;
    const int SW = 8;
    int per  = SW * gx;
    int band = lin / per;
    int rem  = lin - band * per;
    int h    = gy - band * SW; if (h > SW) h = SW;
    int mb   = band * SW + rem % h;
    int nb   = rem / h;
    const int m0 = mb * BM;
    const int n0 = nb * BN;

    const __half* A0h = Ah + (size_t)m0 * K;
    const __half* A0l = Al + (size_t)m0 * K;
    const __half* B0h = Bh + (size_t)n0 * K;
    const __half* B0l = Bl + (size_t)n0 * K;

    auto bAh = [&](int s) { return sbase + s * STAGE_B; };
    auto bAl = [&](int s) { return sbase + s * STAGE_B + A_ST; };
    auto bBh = [&](int s) { return sbase + s * STAGE_B + 2 * A_ST; };
    auto bBl = [&](int s) { return sbase + s * STAGE_B + 2 * A_ST + B_ST; };

    auto load_stage = [&](int s, int k0) {
        // A: 512 chunks (hi+lo), 2 per thread per matrix
#pragma unroll
        for (int t = 0; t < 2; t++) {
            int idx = tid + t * 256;
            int r = idx >> 2, c = idx & 3;
            uint32_t d = (uint32_t)(r * ROWB + c * 16);
            size_t so = (size_t)r * K + k0 + c * 8;
            cp16(bAh(s) + d, A0h + so);
            cp16(bAl(s) + d, A0l + so);
        }
        // B: 1024 chunks (hi+lo), 4 per thread per matrix
#pragma unroll
        for (int t = 0; t < 4; t++) {
            int idx = tid + t * 256;
            int r = idx >> 2, c = idx & 3;
            uint32_t d = (uint32_t)(r * ROWB + c * 16);
            size_t so = (size_t)r * K + k0 + c * 8;
            cp16(bBh(s) + d, B0h + so);
            cp16(bBl(s) + d, B0l + so);
        }
    };

    float acc[4][8][4];
#pragma unroll
    for (int i = 0; i < 4; i++)
#pragma unroll
        for (int j = 0; j < 8; j++)
#pragma unroll
            for (int t = 0; t < 4; t++) acc[i][j][t] = 0.f;

    const int aRow = lane & 15;
    const int aKof = (lane >> 4) * 16;
    const int bRow = (lane & 7) + ((lane & 16) ? 8 : 0);
    const int bKof = (lane & 8) ? 16 : 0;

    const int warpM = wm * 64;
    const int warpN = wn * 64;

    const int nst = K / BK;
    load_stage(0, 0);
    cp_commit();
    load_stage(1, BK);
    cp_commit();

    for (int s = 0; s < nst; s++) {
        const int buf = s % NSTAGE;
        if (s + 1 < nst) cp_wait<1>(); else cp_wait<0>();
        __syncthreads();

        const uint32_t sAh = bAh(buf), sAl = bAl(buf);
        const uint32_t sBh = bBh(buf), sBl = bBl(buf);

#pragma unroll
        for (int ks = 0; ks < 2; ks++) {
            const int kb = ks * 32;
            uint32_t ah[4][4], al[4][4];
#pragma unroll
            for (int mi = 0; mi < 4; mi++) {
                uint32_t ad = (uint32_t)((warpM + mi * 16 + aRow) * ROWB + kb + aKof);
                ldm_x4(ah[mi], sAh + ad);
                ldm_x4(al[mi], sAl + ad);
            }
#pragma unroll
            for (int np = 0; np < 4; np++) {
                uint32_t bd = (uint32_t)((warpN + np * 16 + bRow) * ROWB + kb + bKof);
                uint32_t bh[4], bl[4];
                ldm_x4(bh, sBh + bd);
                ldm_x4(bl, sBl + bd);
#pragma unroll
                for (int q = 0; q < 2; q++) {
                    const int ni = np * 2 + q;
                    const uint32_t b0h = bh[q * 2], b1h = bh[q * 2 + 1];
                    const uint32_t b0l = bl[q * 2], b1l = bl[q * 2 + 1];
#pragma unroll
                    for (int mi = 0; mi < 4; mi++) {
                        mma16816(acc[mi][ni], ah[mi], b0h, b1h);
                        mma16816(acc[mi][ni], ah[mi], b0l, b1l);
                        mma16816(acc[mi][ni], al[mi], b0h, b1h);
                    }
                }
            }
        }

        if (s + 2 < nst) {
            load_stage((s + 2) % NSTAGE, (s + 2) * BK);
            cp_commit();
        }
        __syncthreads();
    }

    const int er = lane >> 2;
    const int ec = (lane & 3) * 2;
    if (!split_out) {
#pragma unroll
        for (int mi = 0; mi < 4; mi++)
#pragma unroll
            for (int ni = 0; ni < 8; ni++) {
                float* p = C + (size_t)(m0 + warpM + mi * 16 + er) * N
                             + (n0 + warpN + ni * 8 + ec);
                p[0] = acc[mi][ni][0];
                p[1] = acc[mi][ni][1];
                float* q = p + (size_t)8 * N;
                q[0] = acc[mi][ni][2];
                q[1] = acc[mi][ni][3];
            }
    } else {
#pragma unroll
        for (int mi = 0; mi < 4; mi++)
#pragma unroll
            for (int ni = 0; ni < 8; ni++) {
                size_t off0 = (size_t)(m0 + warpM + mi * 16 + er) * N
                            + (n0 + warpN + ni * 8 + ec);
                size_t off1 = off0 + (size_t)8 * N;
                float v0 = acc[mi][ni][0], v1 = acc[mi][ni][1];
                float v2 = acc[mi][ni][2], v3 = acc[mi][ni][3];
                __half h0 = __float2half_rn(v0), h1 = __float2half_rn(v1);
                __half h2 = __float2half_rn(v2), h3 = __float2half_rn(v3);
                *(uint32_t*)(Ch + off0) = pack_h2(h0, h1);
                *(uint32_t*)(Ch + off1) = pack_h2(h2, h3);
                *(uint32_t*)(Cl + off0) = pack_h2(
                    __float2half_rn(v0 - __half2float(h0)),
                    __float2half_rn(v1 - __half2float(h1)));
                *(uint32_t*)(Cl + off1) = pack_h2(
                    __float2half_rn(v2 - __half2float(h2)),
                    __float2half_rn(v3 - __half2float(h3)));
            }
    }
}

// ======================= V transpose (halves) ===============================
__global__ __launch_bounds__(256) void transpose_v(
    const __half* __restrict__ vh, const __half* __restrict__ vl,
    __half* __restrict__ vth, __half* __restrict__ vtl)
{
    __shared__ __half th[32][33], tl[32][33];
    const int b  = blockIdx.z;
    const int k0 = blockIdx.y * 32;
    const int s0 = blockIdx.x * 32;
    const int tx = threadIdx.x & 31;
    const int ty = threadIdx.x >> 5;
#pragma unroll
    for (int i = 0; i < 4; i++) {
        int row = ty + i * 8;
        size_t src = (size_t)(b * SEQ + s0 + row) * KVDIM + k0 + tx;
        th[row][tx] = vh[src];
        tl[row][tx] = vl[src];
    }
    __syncthreads();
#pragma unroll
    for (int i = 0; i < 4; i++) {
        int row = ty + i * 8;
        size_t dst = ((size_t)b * KVDIM + k0 + row) * SEQ + s0 + tx;
        vth[dst] = th[tx][row];
        vtl[dst] = tl[tx][row];
    }
}

// ======================= HMMA flash attention ===============================
#define QROWB 272
#define KROWB 272
#define VROWB 144
#define SQ_L      34816
#define SKV_BASE  69632
#define SKV_STRIDE 71680
#define OFF_KH 0
#define OFF_KL 17408
#define OFF_VTH 34816
#define OFF_VTL 53248
#define FLASH_SMEM 212992

__global__ __launch_bounds__(256, 1) void flash_hmma(
    const __half* __restrict__ qh, const __half* __restrict__ ql,
    const __half* __restrict__ kh, const __half* __restrict__ kl,
    const __half* __restrict__ vth, const __half* __restrict__ vtl,
    __half* __restrict__ aoh, __half* __restrict__ aol)
{
    extern __shared__ char smraw[];
    const uint32_t sb = smem_u32(smraw);
    const int tid = threadIdx.x, wid = tid >> 5, lane = tid & 31;
    const int qb = (int)(gridDim.x - 1 - blockIdx.x);
    const int hq = blockIdx.y, b = blockIdx.z;
    const int kvh = hq >> 2;
    const int qrow0 = qb * 128;
    const int g = lane >> 2, tig = lane & 3;
    const float scale = 0.08838834764831845f;

    const __half* qhg = qh + (size_t)(b * SEQ + qrow0) * HIDDEN + hq * HD;
    const __half* qlg = ql + (size_t)(b * SEQ + qrow0) * HIDDEN + hq * HD;
#pragma unroll
    for (int t = 0; t < 8; t++) {
        int idx = tid + t * 256;
        int r = idx >> 4, c = idx & 15;
        uint32_t d = (uint32_t)(r * QROWB + c * 16);
        size_t s = (size_t)r * HIDDEN + c * 8;
        cp16(sb + d, qhg + s);
        cp16(sb + SQ_L + d, qlg + s);
    }
    cp_commit();

    const __half* khg = kh + (size_t)(b * SEQ) * KVDIM + kvh * HD;
    const __half* klg = kl + (size_t)(b * SEQ) * KVDIM + kvh * HD;
    const __half* vthg = vth + ((size_t)b * KVDIM + kvh * HD) * SEQ;
    const __half* vtlg = vtl + ((size_t)b * KVDIM + kvh * HD) * SEQ;

    auto load_kv = [&](int stage, int j) {
        uint32_t base = sb + SKV_BASE + stage * SKV_STRIDE;
        int c0 = j * 64;
#pragma unroll
        for (int t = 0; t < 4; t++) {
            int idx = tid + t * 256;
            int r = idx >> 4, c = idx & 15;
            uint32_t d = (uint32_t)(r * KROWB + c * 16);
            size_t s = (size_t)(c0 + r) * KVDIM + c * 8;
            cp16(base + OFF_KH + d, khg + s);
            cp16(base + OFF_KL + d, klg + s);
        }
#pragma unroll
        for (int t = 0; t < 4; t++) {
            int idx = tid + t * 256;
            int r = idx >> 3, c = idx & 7;
            uint32_t d = (uint32_t)(r * VROWB + c * 16);
            size_t s = (size_t)r * SEQ + c0 + c * 8;
            cp16(base + OFF_VTH + d, vthg + s);
            cp16(base + OFF_VTL + d, vtlg + s);
        }
    };

    const int nb = 2 * qb + 2;
    load_kv(0, 0);
    cp_commit();

    float oacc[16][4];
#pragma unroll
    for (int i = 0; i < 16; i++)
#pragma unroll
        for (int t = 0; t < 4; t++) oacc[i][t] = 0.f;
    float m0 = -1e30f, m1 = -1e30f, l0 = 0.f, l1 = 0.f;

    const int aRow = lane & 15;
    const int aKof = (lane >> 4) * 16;
    const int bRow = (lane & 7) + ((lane & 16) ? 8 : 0);
    const int bKof = (lane & 8) ? 16 : 0;

    const int rg0 = qrow0 + 16 * wid + g;
    const int rg1 = rg0 + 8;

    for (int j = 0; j < nb; j++) {
        const int buf = j & 1;
        if (j + 1 < nb) {
            load_kv(1 - buf, j + 1);
            cp_commit();
            cp_wait<1>();
        } else {
            cp_wait<0>();
        }
        __syncthreads();

        const uint32_t kbase = sb + SKV_BASE + buf * SKV_STRIDE;

        float sacc[8][4];
#pragma unroll
        for (int i = 0; i < 8; i++)
#pragma unroll
            for (int t = 0; t < 4; t++) sacc[i][t] = 0.f;

#pragma unroll
        for (int kd = 0; kd < 8; kd++) {
            uint32_t aa = (uint32_t)((16 * wid + aRow) * QROWB + kd * 32 + aKof);
            uint32_t ah[4], al[4];
            ldm_x4(ah, sb + aa);
            ldm_x4(al, sb + SQ_L + aa);
            uint32_t bh[4][4], bl[4][4];
#pragma unroll
            for (int np = 0; np < 4; np++) {
                uint32_t ba = (uint32_t)((np * 16 + bRow) * KROWB + kd * 32 + bKof);
                ldm_x4(bh[np], kbase + OFF_KH + ba);
                ldm_x4(bl[np], kbase + OFF_KL + ba);
            }
#pragma unroll
            for (int ni = 0; ni < 8; ni++) {
                uint32_t b0h = bh[ni >> 1][(ni & 1) * 2], b1h = bh[ni >> 1][(ni & 1) * 2 + 1];
                uint32_t b0l = bl[ni >> 1][(ni & 1) * 2], b1l = bl[ni >> 1][(ni & 1) * 2 + 1];
                mma16816(sacc[ni], ah, b0h, b1h);
                mma16816(sacc[ni], ah, b0l, b1l);
                mma16816(sacc[ni], al, b0h, b1h);
            }
        }

        const int c0 = j * 64;
#pragma unroll
        for (int ni = 0; ni < 8; ni++)
#pragma unroll
            for (int t = 0; t < 4; t++) sacc[ni][t] *= scale;
        if (j >= 2 * qb) {
#pragma unroll
            for (int ni = 0; ni < 8; ni++) {
                int cg = c0 + ni * 8 + 2 * tig;
                if (cg     > rg0) sacc[ni][0] = -1e30f;
                if (cg + 1 > rg0) sacc[ni][1] = -1e30f;
                if (cg     > rg1) sacc[ni][2] = -1e30f;
                if (cg + 1 > rg1) sacc[ni][3] = -1e30f;
            }
        }

        float vm0 = -1e30f, vm1 = -1e30f;
#pragma unroll
        for (int ni = 0; ni < 8; ni++) {
            vm0 = fmaxf(vm0, fmaxf(sacc[ni][0], sacc[ni][1]));
            vm1 = fmaxf(vm1, fmaxf(sacc[ni][2], sacc[ni][3]));
        }
        vm0 = fmaxf(vm0, __shfl_xor_sync(0xffffffffu, vm0, 1));
        vm0 = fmaxf(vm0, __shfl_xor_sync(0xffffffffu, vm0, 2));
        vm1 = fmaxf(vm1, __shfl_xor_sync(0xffffffffu, vm1, 1));
        vm1 = fmaxf(vm1, __shfl_xor_sync(0xffffffffu, vm1, 2));
        float mn0 = fmaxf(m0, vm0), mn1 = fmaxf(m1, vm1);
        float al0 = __expf(m0 - mn0), al1 = __expf(m1 - mn1);
        float sum0 = 0.f, sum1 = 0.f;
#pragma unroll
        for (int ni = 0; ni < 8; ni++) {
            sacc[ni][0] = __expf(sacc[ni][0] - mn0);
            sacc[ni][1] = __expf(sacc[ni][1] - mn0);
            sacc[ni][2] = __expf(sacc[ni][2] - mn1);
            sacc[ni][3] = __expf(sacc[ni][3] - mn1);
            sum0 += sacc[ni][0] + sacc[ni][1];
            sum1 += sacc[ni][2] + sacc[ni][3];
        }
        sum0 += __shfl_xor_sync(0xffffffffu, sum0, 1);
        sum0 += __shfl_xor_sync(0xffffffffu, sum0, 2);
        sum1 += __shfl_xor_sync(0xffffffffu, sum1, 1);
        sum1 += __shfl_xor_sync(0xffffffffu, sum1, 2);
        l0 = l0 * al0 + sum0;  l1 = l1 * al1 + sum1;
        m0 = mn0;  m1 = mn1;

#pragma unroll
        for (int nd = 0; nd < 16; nd++) {
            oacc[nd][0] *= al0;  oacc[nd][1] *= al0;
            oacc[nd][2] *= al1;  oacc[nd][3] *= al1;
        }

        uint32_t pah[4][4], pal[4][4];
#pragma unroll
        for (int t = 0; t < 4; t++) {
            float p00 = sacc[2 * t][0],     p01 = sacc[2 * t][1];
            float p10 = sacc[2 * t][2],     p11 = sacc[2 * t][3];
            float p20 = sacc[2 * t + 1][0], p21 = sacc[2 * t + 1][1];
            float p30 = sacc[2 * t + 1][2], p31 = sacc[2 * t + 1][3];
            __half h00 = __float2half_rn(p00), h01 = __float2half_rn(p01);
            __half h10 = __float2half_rn(p10), h11 = __float2half_rn(p11);
            __half h20 = __float2half_rn(p20), h21 = __float2half_rn(p21);
            __half h30 = __float2half_rn(p30), h31 = __float2half_rn(p31);
            pah[t][0] = pack_h2(h00, h01);
            pah[t][1] = pack_h2(h10, h11);
            pah[t][2] = pack_h2(h20, h21);
            pah[t][3] = pack_h2(h30, h31);
            pal[t][0] = pack_h2(__float2half_rn(p00 - __half2float(h00)),
                                __float2half_rn(p01 - __half2float(h01)));
            pal[t][1] = pack_h2(__float2half_rn(p10 - __half2float(h10)),
                                __float2half_rn(p11 - __half2float(h11)));
            pal[t][2] = pack_h2(__float2half_rn(p20 - __half2float(h20)),
                                __float2half_rn(p21 - __half2float(h21)));
            pal[t][3] = pack_h2(__float2half_rn(p30 - __half2float(h30)),
                                __float2half_rn(p31 - __half2float(h31)));
        }

#pragma unroll
        for (int t = 0; t < 4; t++) {
#pragma unroll
            for (int np = 0; np < 8; np++) {
                uint32_t ba = (uint32_t)((np * 16 + bRow) * VROWB + t * 32 + bKof);
                uint32_t vbh[4], vbl[4];
                ldm_x4(vbh, kbase + OFF_VTH + ba);
                ldm_x4(vbl, kbase + OFF_VTL + ba);
#pragma unroll
                for (int q = 0; q < 2; q++) {
                    int nd = np * 2 + q;
                    uint32_t b0h = vbh[q * 2], b1h = vbh[q * 2 + 1];
                    uint32_t b0l = vbl[q * 2], b1l = vbl[q * 2 + 1];
                    mma16816(oacc[nd], pah[t], b0h, b1h);
                    mma16816(oacc[nd], pah[t], b0l, b1l);
                    mma16816(oacc[nd], pal[t], b0h, b1h);
                }
            }
        }
        __syncthreads();
    }

    float inv0 = 1.f / l0, inv1 = 1.f / l1;
    size_t row0 = (size_t)(b * SEQ + qrow0 + 16 * wid + g) * HIDDEN + hq * HD;
    size_t row1 = row0 + (size_t)8 * HIDDEN;
#pragma unroll
    for (int nd = 0; nd < 16; nd++) {
        int col = nd * 8 + 2 * tig;
        float v0 = oacc[nd][0] * inv0, v1 = oacc[nd][1] * inv0;
        float v2 = oacc[nd][2] * inv1, v3 = oacc[nd][3] * inv1;
        __half h0 = __float2half_rn(v0), h1 = __float2half_rn(v1);
        __half h2 = __float2half_rn(v2), h3 = __float2half_rn(v3);
        *(uint32_t*)(aoh + row0 + col) = pack_h2(h0, h1);
        *(uint32_t*)(aoh + row1 + col) = pack_h2(h2, h3);
        *(uint32_t*)(aol + row0 + col) = pack_h2(
            __float2half_rn(v0 - __half2float(h0)),
            __float2half_rn(v1 - __half2float(h1)));
        *(uint32_t*)(aol + row1 + col) = pack_h2(
            __float2half_rn(v2 - __half2float(h2)),
            __float2half_rn(v3 - __half2float(h3)));
    }
}

// ============================================================================
extern "C" void kernel_launch(void* const* d_in, const int* in_sizes, int n_in,
                              void* d_out, int out_size)
{
    const float* x  = (const float*)d_in[0];
    const float* Wq = (const float*)d_in[1];
    const float* Wk = (const float*)d_in[2];
    const float* Wv = (const float*)d_in[3];
    const float* Wo = (const float*)d_in[4];
    float* out = (float*)d_out;

    __half *xh, *xl, *wqh, *wql, *wkh, *wkl, *wvh, *wvl, *woh, *wol;
    __half *qh, *ql, *kh, *kl, *vh, *vl, *vth, *vtl, *aoh, *aol;
    cudaGetSymbolAddress((void**)&xh,  g_xh);  cudaGetSymbolAddress((void**)&xl,  g_xl);
    cudaGetSymbolAddress((void**)&wqh, g_wqh); cudaGetSymbolAddress((void**)&wql, g_wql);
    cudaGetSymbolAddress((void**)&wkh, g_wkh); cudaGetSymbolAddress((void**)&wkl, g_wkl);
    cudaGetSymbolAddress((void**)&wvh, g_wvh); cudaGetSymbolAddress((void**)&wvl, g_wvl);
    cudaGetSymbolAddress((void**)&woh, g_woh); cudaGetSymbolAddress((void**)&wol, g_wol);
    cudaGetSymbolAddress((void**)&qh,  g_qh);  cudaGetSymbolAddress((void**)&ql,  g_ql);
    cudaGetSymbolAddress((void**)&kh,  g_kh);  cudaGetSymbolAddress((void**)&kl,  g_kl);
    cudaGetSymbolAddress((void**)&vh,  g_vh);  cudaGetSymbolAddress((void**)&vl,  g_vl);
    cudaGetSymbolAddress((void**)&vth, g_vth); cudaGetSymbolAddress((void**)&vtl, g_vtl);
    cudaGetSymbolAddress((void**)&aoh, g_aoh); cudaGetSymbolAddress((void**)&aol, g_aol);

    cudaFuncSetAttribute(gemm_hmma, cudaFuncAttributeMaxDynamicSharedMemorySize, GEMM_SMEM);
    cudaFuncSetAttribute(flash_hmma, cudaFuncAttributeMaxDynamicSharedMemorySize, FLASH_SMEM);

    const int XN4 = TOKENS * HIDDEN / 4;
    const int WN4 = HIDDEN * HIDDEN / 4;
    const int KN4 = KVDIM * HIDDEN / 4;

    split_f32<<<(XN4 + 255) / 256, 256>>>((const float4*)x,  (__half2*)xh,  (__half2*)xl,  XN4);
    split_f32<<<(WN4 + 255) / 256, 256>>>((const float4*)Wq, (__half2*)wqh, (__half2*)wql, WN4);
    split_f32<<<(KN4 + 255) / 256, 256>>>((const float4*)Wk, (__half2*)wkh, (__half2*)wkl, KN4);
    split_f32<<<(KN4 + 255) / 256, 256>>>((const float4*)Wv, (__half2*)wvh, (__half2*)wvl, KN4);
    split_f32<<<(WN4 + 255) / 256, 256>>>((const float4*)Wo, (__half2*)woh, (__half2*)wol, WN4);

    gemm_hmma<<<dim3(HIDDEN / BN, TOKENS / BM), 256, GEMM_SMEM>>>(
        xh, xl, wqh, wql, nullptr, qh, ql, HIDDEN, HIDDEN, 1);
    gemm_hmma<<<dim3(KVDIM / BN, TOKENS / BM), 256, GEMM_SMEM>>>(
        xh, xl, wkh, wkl, nullptr, kh, kl, KVDIM, HIDDEN, 1);
    gemm_hmma<<<dim3(KVDIM / BN, TOKENS / BM), 256, GEMM_SMEM>>>(
        xh, xl, wvh, wvl, nullptr, vh, vl, KVDIM, HIDDEN, 1);

    transpose_v<<<dim3(SEQ / 32, KVDIM / 32, BATCH), 256>>>(vh, vl, vth, vtl);

    flash_hmma<<<dim3(SEQ / 128, NH, BATCH), 256, FLASH_SMEM>>>(
        qh, ql, kh, kl, vth, vtl, aoh, aol);

    gemm_hmma<<<dim3(HIDDEN / BN, TOKENS / BM), 256, GEMM_SMEM>>>(
        aoh, aol, woh, wol, out, nullptr, nullptr, HIDDEN, HIDDEN, 0);
}

// round 6
// speedup vs baseline: 3.9918x; 1.2854x over previous
#include <cuda_runtime.h>
#include <cuda_fp16.h>
#include <cstdint>
#include <math.h>

#define HIDDEN   4096
#define NKV      8
#define NH       32
#define HD       128
#define BATCH    2
#define SEQ      2048
#define TOKENS   (BATCH*SEQ)   // 4096
#define KVDIM    (NKV*HD)      // 1024

// ---------------- scratch (device globals; no runtime allocation) ----------
__device__ __half g_xh [TOKENS*HIDDEN];
__device__ __half g_wqh[HIDDEN*HIDDEN], g_wql[HIDDEN*HIDDEN];
__device__ __half g_wkh[KVDIM*HIDDEN],  g_wkl[KVDIM*HIDDEN];
__device__ __half g_wvh[KVDIM*HIDDEN],  g_wvl[KVDIM*HIDDEN];
__device__ __half g_woh[HIDDEN*HIDDEN], g_wol[HIDDEN*HIDDEN];
__device__ __half g_qh [TOKENS*HIDDEN], g_ql [TOKENS*HIDDEN];
__device__ __half g_kh [TOKENS*KVDIM],  g_kl [TOKENS*KVDIM];
__device__ __half g_vh [TOKENS*KVDIM],  g_vl [TOKENS*KVDIM];
__device__ __half g_vth[TOKENS*KVDIM],  g_vtl[TOKENS*KVDIM];  // [B][KVDIM][SEQ]
__device__ __half g_aoh[TOKENS*HIDDEN];

// ======================= helpers ============================================
__device__ __forceinline__ uint32_t smem_u32(const void* p) {
    uint32_t a;
    asm("{ .reg .u64 t; cvta.to.shared.u64 t, %1; cvt.u32.u64 %0, t; }"
        : "=r"(a) : "l"(p));
    return a;
}
__device__ __forceinline__ void cp16(uint32_t dst, const void* src) {
    asm volatile("cp.async.cg.shared.global [%0], [%1], 16;" :: "r"(dst), "l"(src));
}
__device__ __forceinline__ void cp_commit() { asm volatile("cp.async.commit_group;" ::: "memory"); }
template<int N> __device__ __forceinline__ void cp_wait() {
    asm volatile("cp.async.wait_group %0;" :: "n"(N) : "memory");
}
__device__ __forceinline__ void ldm_x4(uint32_t* r, uint32_t addr) {
    asm volatile("ldmatrix.sync.aligned.m8n8.x4.shared.b16 {%0,%1,%2,%3}, [%4];"
        : "=r"(r[0]), "=r"(r[1]), "=r"(r[2]), "=r"(r[3]) : "r"(addr));
}
__device__ __forceinline__ void mma16816(float* d, const uint32_t* a,
                                         uint32_t b0, uint32_t b1) {
    asm volatile(
        "mma.sync.aligned.m16n8k16.row.col.f32.f16.f16.f32 "
        "{%0,%1,%2,%3}, {%4,%5,%6,%7}, {%8,%9}, {%0,%1,%2,%3};"
        : "+f"(d[0]), "+f"(d[1]), "+f"(d[2]), "+f"(d[3])
        : "r"(a[0]), "r"(a[1]), "r"(a[2]), "r"(a[3]), "r"(b0), "r"(b1));
}
__device__ __forceinline__ uint32_t pack_h2(__half a, __half b) {
    __half2 h = __halves2half2(a, b);
    return *(uint32_t*)&h;
}

// ======================= split fp32 -> fp16 hi/lo ==========================
__global__ __launch_bounds__(256) void split_f32(
    const float4* __restrict__ x, __half2* __restrict__ hi,
    __half2* __restrict__ lo, int n4)
{
    int i = blockIdx.x * blockDim.x + threadIdx.x;
    if (i >= n4) return;
    float4 v = x[i];
    __half h0 = __float2half_rn(v.x), h1 = __float2half_rn(v.y);
    __half h2 = __float2half_rn(v.z), h3 = __float2half_rn(v.w);
    hi[2 * i]     = __halves2half2(h0, h1);
    hi[2 * i + 1] = __halves2half2(h2, h3);
    if (lo) {
        lo[2 * i] = __halves2half2(__float2half_rn(v.x - __half2float(h0)),
                                   __float2half_rn(v.y - __half2float(h1)));
        lo[2 * i + 1] = __halves2half2(__float2half_rn(v.z - __half2float(h2)),
                                       __float2half_rn(v.w - __half2float(h3)));
    }
}

// ======================= HMMA GEMM core (2-term split) ======================
// C = A @ B^T with A hi-only, B hi/lo. Tile 128x256xBK32, 8 warps, 3 stages.
#define BM 128
#define BN 256
#define BK 32
#define ROWB 80
#define A_ST (BM*ROWB)                 // 10240
#define B_ST (BN*ROWB)                 // 20480
#define STAGE_B (A_ST + 2*B_ST)        // 51200
#define NSTAGE 3
#define GEMM_SMEM (NSTAGE*STAGE_B)     // 153600

struct GemmOut {
    float* C;        // fp32 out (if !split)
    __half* Ch;      // fp16 hi out (if split)
    __half* Cl;      // fp16 lo out (if split)
    int Nout;
    int split;
};

__device__ __forceinline__ void gemm2_core(
    uint32_t sbase, const __half* A0h, const __half* B0h, const __half* B0l,
    int m0, int ncol0, int K, const GemmOut& o)
{
    const int tid  = threadIdx.x;
    const int wid  = tid >> 5;
    const int lane = tid & 31;
    const int wm   = wid & 1;
    const int wn   = wid >> 1;

    auto bA  = [&](int s) { return sbase + s * STAGE_B; };
    auto bBh = [&](int s) { return sbase + s * STAGE_B + A_ST; };
    auto bBl = [&](int s) { return sbase + s * STAGE_B + A_ST + B_ST; };

    auto load_stage = [&](int s, int k0) {
#pragma unroll
        for (int t = 0; t < 2; t++) {                // A hi: 512 chunks
            int idx = tid + t * 256;
            int r = idx >> 2, c = idx & 3;
            uint32_t d = (uint32_t)(r * ROWB + c * 16);
            cp16(bA(s) + d, A0h + (size_t)r * K + k0 + c * 8);
        }
#pragma unroll
        for (int t = 0; t < 4; t++) {                // B hi+lo: 1024 chunks ea
            int idx = tid + t * 256;
            int r = idx >> 2, c = idx & 3;
            uint32_t d = (uint32_t)(r * ROWB + c * 16);
            size_t so = (size_t)r * K + k0 + c * 8;
            cp16(bBh(s) + d, B0h + so);
            cp16(bBl(s) + d, B0l + so);
        }
    };

    float acc[4][8][4];
#pragma unroll
    for (int i = 0; i < 4; i++)
#pragma unroll
        for (int j = 0; j < 8; j++)
#pragma unroll
            for (int t = 0; t < 4; t++) acc[i][j][t] = 0.f;

    const int aRow = lane & 15;
    const int aKof = (lane >> 4) * 16;
    const int bRow = (lane & 7) + ((lane & 16) ? 8 : 0);
    const int bKof = (lane & 8) ? 16 : 0;
    const int warpM = wm * 64;
    const int warpN = wn * 64;

    const int nst = K / BK;
    load_stage(0, 0);
    cp_commit();
    load_stage(1, BK);
    cp_commit();

    for (int s = 0; s < nst; s++) {
        const int buf = s % NSTAGE;
        if (s + 1 < nst) cp_wait<1>(); else cp_wait<0>();
        __syncthreads();

        const uint32_t sA = bA(buf), sBh = bBh(buf), sBl = bBl(buf);

#pragma unroll
        for (int ks = 0; ks < 2; ks++) {
            const int kb = ks * 32;
            uint32_t ah[4][4];
#pragma unroll
            for (int mi = 0; mi < 4; mi++) {
                uint32_t ad = (uint32_t)((warpM + mi * 16 + aRow) * ROWB + kb + aKof);
                ldm_x4(ah[mi], sA + ad);
            }
#pragma unroll
            for (int np = 0; np < 4; np++) {
                uint32_t bd = (uint32_t)((warpN + np * 16 + bRow) * ROWB + kb + bKof);
                uint32_t bh[4], bl[4];
                ldm_x4(bh, sBh + bd);
                ldm_x4(bl, sBl + bd);
#pragma unroll
                for (int q = 0; q < 2; q++) {
                    const int ni = np * 2 + q;
                    const uint32_t b0h = bh[q * 2], b1h = bh[q * 2 + 1];
                    const uint32_t b0l = bl[q * 2], b1l = bl[q * 2 + 1];
#pragma unroll
                    for (int mi = 0; mi < 4; mi++) {
                        mma16816(acc[mi][ni], ah[mi], b0h, b1h);
                        mma16816(acc[mi][ni], ah[mi], b0l, b1l);
                    }
                }
            }
        }

        if (s + 2 < nst) {
            load_stage((s + 2) % NSTAGE, (s + 2) * BK);
            cp_commit();
        }
    }

    const int er = lane >> 2;
    const int ec = (lane & 3) * 2;
    if (!o.split) {
#pragma unroll
        for (int mi = 0; mi < 4; mi++)
#pragma unroll
            for (int ni = 0; ni < 8; ni++) {
                float* p = o.C + (size_t)(m0 + warpM + mi * 16 + er) * o.Nout
                               + (ncol0 + warpN + ni * 8 + ec);
                p[0] = acc[mi][ni][0];
                p[1] = acc[mi][ni][1];
                float* q = p + (size_t)8 * o.Nout;
                q[0] = acc[mi][ni][2];
                q[1] = acc[mi][ni][3];
            }
    } else {
#pragma unroll
        for (int mi = 0; mi < 4; mi++)
#pragma unroll
            for (int ni = 0; ni < 8; ni++) {
                size_t off0 = (size_t)(m0 + warpM + mi * 16 + er) * o.Nout
                            + (ncol0 + warpN + ni * 8 + ec);
                size_t off1 = off0 + (size_t)8 * o.Nout;
                float v0 = acc[mi][ni][0], v1 = acc[mi][ni][1];
                float v2 = acc[mi][ni][2], v3 = acc[mi][ni][3];
                __half h0 = __float2half_rn(v0), h1 = __float2half_rn(v1);
                __half h2 = __float2half_rn(v2), h3 = __float2half_rn(v3);
                *(uint32_t*)(o.Ch + off0) = pack_h2(h0, h1);
                *(uint32_t*)(o.Ch + off1) = pack_h2(h2, h3);
                *(uint32_t*)(o.Cl + off0) = pack_h2(
                    __float2half_rn(v0 - __half2float(h0)),
                    __float2half_rn(v1 - __half2float(h1)));
                *(uint32_t*)(o.Cl + off1) = pack_h2(
                    __float2half_rn(v2 - __half2float(h2)),
                    __float2half_rn(v3 - __half2float(h3)));
            }
    }
}

// swizzled block mapping (supertiles of 8 m-blocks)
__device__ __forceinline__ void cta_map(int gx, int gy, int& mb, int& nb) {
    int lin = blockIdx.y * gx + blockIdx.x;
    const int SW = 8;
    int per  = SW * gx;
    int band = lin / per;
    int rem  = lin - band * per;
    int h    = gy - band * SW; if (h > SW) h = SW;
    mb = band * SW + rem % h;
    nb = rem / h;
}

// fused QKV projection: virtual N = 6144 (Q 4096 | K 1024 | V 1024)
__global__ __launch_bounds__(256, 1) void qkv_hmma(
    const __half* __restrict__ xh,
    const __half* __restrict__ wqh, const __half* __restrict__ wql,
    const __half* __restrict__ wkh, const __half* __restrict__ wkl,
    const __half* __restrict__ wvh, const __half* __restrict__ wvl,
    __half* __restrict__ qh, __half* __restrict__ ql,
    __half* __restrict__ kh, __half* __restrict__ kl,
    __half* __restrict__ vh, __half* __restrict__ vl)
{
    extern __shared__ char smraw[];
    const uint32_t sbase = smem_u32(smraw);
    int mb, nb;
    cta_map(gridDim.x, gridDim.y, mb, nb);
    const int m0 = mb * BM;

    const __half *Bh_, *Bl_;
    GemmOut o; o.C = nullptr; o.split = 1;
    int ncol;
    if (nb < 16)      { Bh_ = wqh; Bl_ = wql; o.Ch = qh; o.Cl = ql; o.Nout = HIDDEN; ncol = nb * BN; }
    else if (nb < 20) { Bh_ = wkh; Bl_ = wkl; o.Ch = kh; o.Cl = kl; o.Nout = KVDIM;  ncol = (nb - 16) * BN; }
    else              { Bh_ = wvh; Bl_ = wvl; o.Ch = vh; o.Cl = vl; o.Nout = KVDIM;  ncol = (nb - 20) * BN; }

    gemm2_core(sbase, xh + (size_t)m0 * HIDDEN,
               Bh_ + (size_t)ncol * HIDDEN, Bl_ + (size_t)ncol * HIDDEN,
               m0, ncol, HIDDEN, o);
}

// generic output GEMM (fp32 out)
__global__ __launch_bounds__(256, 1) void gemm_hmma2(
    const __half* __restrict__ Ah,
    const __half* __restrict__ Bh, const __half* __restrict__ Bl,
    float* __restrict__ C, int N, int K)
{
    extern __shared__ char smraw[];
    const uint32_t sbase = smem_u32(smraw);
    int mb, nb;
    cta_map(gridDim.x, gridDim.y, mb, nb);
    const int m0 = mb * BM, n0 = nb * BN;
    GemmOut o; o.C = C; o.Ch = nullptr; o.Cl = nullptr; o.Nout = N; o.split = 0;
    gemm2_core(sbase, Ah + (size_t)m0 * K,
               Bh + (size_t)n0 * K, Bl + (size_t)n0 * K, m0, n0, K, o);
}

// ======================= V transpose (halves) ===============================
__global__ __launch_bounds__(256) void transpose_v(
    const __half* __restrict__ vh, const __half* __restrict__ vl,
    __half* __restrict__ vth, __half* __restrict__ vtl)
{
    __shared__ __half th[32][33], tl[32][33];
    const int b  = blockIdx.z;
    const int k0 = blockIdx.y * 32;
    const int s0 = blockIdx.x * 32;
    const int tx = threadIdx.x & 31;
    const int ty = threadIdx.x >> 5;
#pragma unroll
    for (int i = 0; i < 4; i++) {
        int row = ty + i * 8;
        size_t src = (size_t)(b * SEQ + s0 + row) * KVDIM + k0 + tx;
        th[row][tx] = vh[src];
        tl[row][tx] = vl[src];
    }
    __syncthreads();
#pragma unroll
    for (int i = 0; i < 4; i++) {
        int row = ty + i * 8;
        size_t dst = ((size_t)b * KVDIM + k0 + row) * SEQ + s0 + tx;
        vth[dst] = th[tx][row];
        vtl[dst] = tl[tx][row];
    }
}

// ======================= HMMA flash attention (3-term) ======================
#define QROWB 272
#define KROWB 272
#define VROWB 144
#define SQ_L      34816
#define SKV_BASE  69632
#define SKV_STRIDE 71680
#define OFF_KH 0
#define OFF_KL 17408
#define OFF_VTH 34816
#define OFF_VTL 53248
#define FLASH_SMEM 212992

__global__ __launch_bounds__(256, 1) void flash_hmma(
    const __half* __restrict__ qh, const __half* __restrict__ ql,
    const __half* __restrict__ kh, const __half* __restrict__ kl,
    const __half* __restrict__ vth, const __half* __restrict__ vtl,
    __half* __restrict__ aoh)
{
    extern __shared__ char smraw[];
    const uint32_t sb = smem_u32(smraw);
    const int tid = threadIdx.x, wid = tid >> 5, lane = tid & 31;
    const int qb = (int)(gridDim.x - 1 - blockIdx.x);
    const int hq = blockIdx.y, b = blockIdx.z;
    const int kvh = hq >> 2;
    const int qrow0 = qb * 128;
    const int g = lane >> 2, tig = lane & 3;
    const float scale = 0.08838834764831845f;

    const __half* qhg = qh + (size_t)(b * SEQ + qrow0) * HIDDEN + hq * HD;
    const __half* qlg = ql + (size_t)(b * SEQ + qrow0) * HIDDEN + hq * HD;
#pragma unroll
    for (int t = 0; t < 8; t++) {
        int idx = tid + t * 256;
        int r = idx >> 4, c = idx & 15;
        uint32_t d = (uint32_t)(r * QROWB + c * 16);
        size_t s = (size_t)r * HIDDEN + c * 8;
        cp16(sb + d, qhg + s);
        cp16(sb + SQ_L + d, qlg + s);
    }
    cp_commit();

    const __half* khg = kh + (size_t)(b * SEQ) * KVDIM + kvh * HD;
    const __half* klg = kl + (size_t)(b * SEQ) * KVDIM + kvh * HD;
    const __half* vthg = vth + ((size_t)b * KVDIM + kvh * HD) * SEQ;
    const __half* vtlg = vtl + ((size_t)b * KVDIM + kvh * HD) * SEQ;

    auto load_kv = [&](int stage, int j) {
        uint32_t base = sb + SKV_BASE + stage * SKV_STRIDE;
        int c0 = j * 64;
#pragma unroll
        for (int t = 0; t < 4; t++) {
            int idx = tid + t * 256;
            int r = idx >> 4, c = idx & 15;
            uint32_t d = (uint32_t)(r * KROWB + c * 16);
            size_t s = (size_t)(c0 + r) * KVDIM + c * 8;
            cp16(base + OFF_KH + d, khg + s);
            cp16(base + OFF_KL + d, klg + s);
        }
#pragma unroll
        for (int t = 0; t < 4; t++) {
            int idx = tid + t * 256;
            int r = idx >> 3, c = idx & 7;
            uint32_t d = (uint32_t)(r * VROWB + c * 16);
            size_t s = (size_t)r * SEQ + c0 + c * 8;
            cp16(base + OFF_VTH + d, vthg + s);
            cp16(base + OFF_VTL + d, vtlg + s);
        }
    };

    const int nb = 2 * qb + 2;
    load_kv(0, 0);
    cp_commit();

    float oacc[16][4];
#pragma unroll
    for (int i = 0; i < 16; i++)
#pragma unroll
        for (int t = 0; t < 4; t++) oacc[i][t] = 0.f;
    float m0 = -1e30f, m1 = -1e30f, l0 = 0.f, l1 = 0.f;

    const int aRow = lane & 15;
    const int aKof = (lane >> 4) * 16;
    const int bRow = (lane & 7) + ((lane & 16) ? 8 : 0);
    const int bKof = (lane & 8) ? 16 : 0;

    const int rg0 = qrow0 + 16 * wid + g;
    const int rg1 = rg0 + 8;

    for (int j = 0; j < nb; j++) {
        const int buf = j & 1;
        if (j + 1 < nb) {
            load_kv(1 - buf, j + 1);
            cp_commit();
            cp_wait<1>();
        } else {
            cp_wait<0>();
        }
        __syncthreads();

        const uint32_t kbase = sb + SKV_BASE + buf * SKV_STRIDE;

        float sacc[8][4];
#pragma unroll
        for (int i = 0; i < 8; i++)
#pragma unroll
            for (int t = 0; t < 4; t++) sacc[i][t] = 0.f;

#pragma unroll
        for (int kd = 0; kd < 8; kd++) {
            uint32_t aa = (uint32_t)((16 * wid + aRow) * QROWB + kd * 32 + aKof);
            uint32_t ah[4], al[4];
            ldm_x4(ah, sb + aa);
            ldm_x4(al, sb + SQ_L + aa);
            uint32_t bh[4][4], bl[4][4];
#pragma unroll
            for (int np = 0; np < 4; np++) {
                uint32_t ba = (uint32_t)((np * 16 + bRow) * KROWB + kd * 32 + bKof);
                ldm_x4(bh[np], kbase + OFF_KH + ba);
                ldm_x4(bl[np], kbase + OFF_KL + ba);
            }
#pragma unroll
            for (int ni = 0; ni < 8; ni++) {
                uint32_t b0h = bh[ni >> 1][(ni & 1) * 2], b1h = bh[ni >> 1][(ni & 1) * 2 + 1];
                uint32_t b0l = bl[ni >> 1][(ni & 1) * 2], b1l = bl[ni >> 1][(ni & 1) * 2 + 1];
                mma16816(sacc[ni], ah, b0h, b1h);
                mma16816(sacc[ni], ah, b0l, b1l);
                mma16816(sacc[ni], al, b0h, b1h);
            }
        }

        const int c0 = j * 64;
#pragma unroll
        for (int ni = 0; ni < 8; ni++)
#pragma unroll
            for (int t = 0; t < 4; t++) sacc[ni][t] *= scale;
        if (j >= 2 * qb) {
#pragma unroll
            for (int ni = 0; ni < 8; ni++) {
                int cg = c0 + ni * 8 + 2 * tig;
                if (cg     > rg0) sacc[ni][0] = -1e30f;
                if (cg + 1 > rg0) sacc[ni][1] = -1e30f;
                if (cg     > rg1) sacc[ni][2] = -1e30f;
                if (cg + 1 > rg1) sacc[ni][3] = -1e30f;
            }
        }

        float vm0 = -1e30f, vm1 = -1e30f;
#pragma unroll
        for (int ni = 0; ni < 8; ni++) {
            vm0 = fmaxf(vm0, fmaxf(sacc[ni][0], sacc[ni][1]));
            vm1 = fmaxf(vm1, fmaxf(sacc[ni][2], sacc[ni][3]));
        }
        vm0 = fmaxf(vm0, __shfl_xor_sync(0xffffffffu, vm0, 1));
        vm0 = fmaxf(vm0, __shfl_xor_sync(0xffffffffu, vm0, 2));
        vm1 = fmaxf(vm1, __shfl_xor_sync(0xffffffffu, vm1, 1));
        vm1 = fmaxf(vm1, __shfl_xor_sync(0xffffffffu, vm1, 2));
        float mn0 = fmaxf(m0, vm0), mn1 = fmaxf(m1, vm1);
        float al0 = __expf(m0 - mn0), al1 = __expf(m1 - mn1);
        float sum0 = 0.f, sum1 = 0.f;
#pragma unroll
        for (int ni = 0; ni < 8; ni++) {
            sacc[ni][0] = __expf(sacc[ni][0] - mn0);
            sacc[ni][1] = __expf(sacc[ni][1] - mn0);
            sacc[ni][2] = __expf(sacc[ni][2] - mn1);
            sacc[ni][3] = __expf(sacc[ni][3] - mn1);
            sum0 += sacc[ni][0] + sacc[ni][1];
            sum1 += sacc[ni][2] + sacc[ni][3];
        }
        sum0 += __shfl_xor_sync(0xffffffffu, sum0, 1);
        sum0 += __shfl_xor_sync(0xffffffffu, sum0, 2);
        sum1 += __shfl_xor_sync(0xffffffffu, sum1, 1);
        sum1 += __shfl_xor_sync(0xffffffffu, sum1, 2);
        l0 = l0 * al0 + sum0;  l1 = l1 * al1 + sum1;
        m0 = mn0;  m1 = mn1;

#pragma unroll
        for (int nd = 0; nd < 16; nd++) {
            oacc[nd][0] *= al0;  oacc[nd][1] *= al0;
            oacc[nd][2] *= al1;  oacc[nd][3] *= al1;
        }

        uint32_t pah[4][4], pal[4][4];
#pragma unroll
        for (int t = 0; t < 4; t++) {
            float p00 = sacc[2 * t][0],     p01 = sacc[2 * t][1];
            float p10 = sacc[2 * t][2],     p11 = sacc[2 * t][3];
            float p20 = sacc[2 * t + 1][0], p21 = sacc[2 * t + 1][1];
            float p30 = sacc[2 * t + 1][2], p31 = sacc[2 * t + 1][3];
            __half h00 = __float2half_rn(p00), h01 = __float2half_rn(p01);
            __half h10 = __float2half_rn(p10), h11 = __float2half_rn(p11);
            __half h20 = __float2half_rn(p20), h21 = __float2half_rn(p21);
            __half h30 = __float2half_rn(p30), h31 = __float2half_rn(p31);
            pah[t][0] = pack_h2(h00, h01);
            pah[t][1] = pack_h2(h10, h11);
            pah[t][2] = pack_h2(h20, h21);
            pah[t][3] = pack_h2(h30, h31);
            pal[t][0] = pack_h2(__float2half_rn(p00 - __half2float(h00)),
                                __float2half_rn(p01 - __half2float(h01)));
            pal[t][1] = pack_h2(__float2half_rn(p10 - __half2float(h10)),
                                __float2half_rn(p11 - __half2float(h11)));
            pal[t][2] = pack_h2(__float2half_rn(p20 - __half2float(h20)),
                                __float2half_rn(p21 - __half2float(h21)));
            pal[t][3] = pack_h2(__float2half_rn(p30 - __half2float(h30)),
                                __float2half_rn(p31 - __half2float(h31)));
        }

#pragma unroll
        for (int t = 0; t < 4; t++) {
#pragma unroll
            for (int np = 0; np < 8; np++) {
                uint32_t ba = (uint32_t)((np * 16 + bRow) * VROWB + t * 32 + bKof);
                uint32_t vbh[4], vbl[4];
                ldm_x4(vbh, kbase + OFF_VTH + ba);
                ldm_x4(vbl, kbase + OFF_VTL + ba);
#pragma unroll
                for (int q = 0; q < 2; q++) {
                    int nd = np * 2 + q;
                    uint32_t b0h = vbh[q * 2], b1h = vbh[q * 2 + 1];
                    uint32_t b0l = vbl[q * 2], b1l = vbl[q * 2 + 1];
                    mma16816(oacc[nd], pah[t], b0h, b1h);
                    mma16816(oacc[nd], pah[t], b0l, b1l);
                    mma16816(oacc[nd], pal[t], b0h, b1h);
                }
            }
        }
        __syncthreads();
    }

    float inv0 = 1.f / l0, inv1 = 1.f / l1;
    size_t row0 = (size_t)(b * SEQ + qrow0 + 16 * wid + g) * HIDDEN + hq * HD;
    size_t row1 = row0 + (size_t)8 * HIDDEN;
#pragma unroll
    for (int nd = 0; nd < 16; nd++) {
        int col = nd * 8 + 2 * tig;
        *(uint32_t*)(aoh + row0 + col) = pack_h2(
            __float2half_rn(oacc[nd][0] * inv0), __float2half_rn(oacc[nd][1] * inv0));
        *(uint32_t*)(aoh + row1 + col) = pack_h2(
            __float2half_rn(oacc[nd][2] * inv1), __float2half_rn(oacc[nd][3] * inv1));
    }
}

// ============================================================================
extern "C" void kernel_launch(void* const* d_in, const int* in_sizes, int n_in,
                              void* d_out, int out_size)
{
    const float* x  = (const float*)d_in[0];
    const float* Wq = (const float*)d_in[1];
    const float* Wk = (const float*)d_in[2];
    const float* Wv = (const float*)d_in[3];
    const float* Wo = (const float*)d_in[4];
    float* out = (float*)d_out;

    __half *xh, *wqh, *wql, *wkh, *wkl, *wvh, *wvl, *woh, *wol;
    __half *qh, *ql, *kh, *kl, *vh, *vl, *vth, *vtl, *aoh;
    cudaGetSymbolAddress((void**)&xh,  g_xh);
    cudaGetSymbolAddress((void**)&wqh, g_wqh); cudaGetSymbolAddress((void**)&wql, g_wql);
    cudaGetSymbolAddress((void**)&wkh, g_wkh); cudaGetSymbolAddress((void**)&wkl, g_wkl);
    cudaGetSymbolAddress((void**)&wvh, g_wvh); cudaGetSymbolAddress((void**)&wvl, g_wvl);
    cudaGetSymbolAddress((void**)&woh, g_woh); cudaGetSymbolAddress((void**)&wol, g_wol);
    cudaGetSymbolAddress((void**)&qh,  g_qh);  cudaGetSymbolAddress((void**)&ql,  g_ql);
    cudaGetSymbolAddress((void**)&kh,  g_kh);  cudaGetSymbolAddress((void**)&kl,  g_kl);
    cudaGetSymbolAddress((void**)&vh,  g_vh);  cudaGetSymbolAddress((void**)&vl,  g_vl);
    cudaGetSymbolAddress((void**)&vth, g_vth); cudaGetSymbolAddress((void**)&vtl, g_vtl);
    cudaGetSymbolAddress((void**)&aoh, g_aoh);

    cudaFuncSetAttribute(qkv_hmma,  cudaFuncAttributeMaxDynamicSharedMemorySize, GEMM_SMEM);
    cudaFuncSetAttribute(gemm_hmma2, cudaFuncAttributeMaxDynamicSharedMemorySize, GEMM_SMEM);
    cudaFuncSetAttribute(flash_hmma, cudaFuncAttributeMaxDynamicSharedMemorySize, FLASH_SMEM);

    const int XN4 = TOKENS * HIDDEN / 4;
    const int WN4 = HIDDEN * HIDDEN / 4;
    const int KN4 = KVDIM * HIDDEN / 4;

    split_f32<<<(XN4 + 255) / 256, 256>>>((const float4*)x,  (__half2*)xh,  nullptr, XN4);
    split_f32<<<(WN4 + 255) / 256, 256>>>((const float4*)Wq, (__half2*)wqh, (__half2*)wql, WN4);
    split_f32<<<(KN4 + 255) / 256, 256>>>((const float4*)Wk, (__half2*)wkh, (__half2*)wkl, KN4);
    split_f32<<<(KN4 + 255) / 256, 256>>>((const float4*)Wv, (__half2*)wvh, (__half2*)wvl, KN4);
    split_f32<<<(WN4 + 255) / 256, 256>>>((const float4*)Wo, (__half2*)woh, (__half2*)wol, WN4);

    // fused QKV projection (virtual N = 6144)
    qkv_hmma<<<dim3(6144 / BN, TOKENS / BM), 256, GEMM_SMEM>>>(
        xh, wqh, wql, wkh, wkl, wvh, wvl, qh, ql, kh, kl, vh, vl);

    transpose_v<<<dim3(SEQ / 32, KVDIM / 32, BATCH), 256>>>(vh, vl, vth, vtl);

    flash_hmma<<<dim3(SEQ / 128, NH, BATCH), 256, FLASH_SMEM>>>(
        qh, ql, kh, kl, vth, vtl, aoh);

    gemm_hmma2<<<dim3(HIDDEN / BN, TOKENS / BM), 256, GEMM_SMEM>>>(
        aoh, woh, wol, out, HIDDEN, HIDDEN);
}

// round 7
// speedup vs baseline: 4.1854x; 1.0485x over previous
#include <cuda_runtime.h>
#include <cuda_fp16.h>
#include <cstdint>
#include <math.h>

#define HIDDEN   4096
#define NKV      8
#define NH       32
#define HD       128
#define BATCH    2
#define SEQ      2048
#define TOKENS   (BATCH*SEQ)   // 4096
#define KVDIM    (NKV*HD)      // 1024

// ---------------- scratch (device globals; no runtime allocation) ----------
__device__ __half g_xh [TOKENS*HIDDEN], g_xl [TOKENS*HIDDEN];
__device__ __half g_wqh[HIDDEN*HIDDEN];
__device__ __half g_wkh[KVDIM*HIDDEN];
__device__ __half g_wvh[KVDIM*HIDDEN];
__device__ __half g_woh[HIDDEN*HIDDEN];
__device__ __half g_qh [TOKENS*HIDDEN], g_ql [TOKENS*HIDDEN];
__device__ __half g_kh [TOKENS*KVDIM],  g_kl [TOKENS*KVDIM];
__device__ __half g_vh [TOKENS*KVDIM],  g_vl [TOKENS*KVDIM];
__device__ __half g_vth[TOKENS*KVDIM],  g_vtl[TOKENS*KVDIM];  // [B][KVDIM][SEQ]
__device__ __half g_aoh[TOKENS*HIDDEN], g_aol[TOKENS*HIDDEN];

// ======================= helpers ============================================
__device__ __forceinline__ uint32_t smem_u32(const void* p) {
    uint32_t a;
    asm("{ .reg .u64 t; cvta.to.shared.u64 t, %1; cvt.u32.u64 %0, t; }"
        : "=r"(a) : "l"(p));
    return a;
}
__device__ __forceinline__ void cp16(uint32_t dst, const void* src) {
    asm volatile("cp.async.cg.shared.global [%0], [%1], 16;" :: "r"(dst), "l"(src));
}
__device__ __forceinline__ void cp_commit() { asm volatile("cp.async.commit_group;" ::: "memory"); }
template<int N> __device__ __forceinline__ void cp_wait() {
    asm volatile("cp.async.wait_group %0;" :: "n"(N) : "memory");
}
__device__ __forceinline__ void ldm_x4(uint32_t* r, uint32_t addr) {
    asm volatile("ldmatrix.sync.aligned.m8n8.x4.shared.b16 {%0,%1,%2,%3}, [%4];"
        : "=r"(r[0]), "=r"(r[1]), "=r"(r[2]), "=r"(r[3]) : "r"(addr));
}
__device__ __forceinline__ void mma16816(float* d, const uint32_t* a,
                                         uint32_t b0, uint32_t b1) {
    asm volatile(
        "mma.sync.aligned.m16n8k16.row.col.f32.f16.f16.f32 "
        "{%0,%1,%2,%3}, {%4,%5,%6,%7}, {%8,%9}, {%0,%1,%2,%3};"
        : "+f"(d[0]), "+f"(d[1]), "+f"(d[2]), "+f"(d[3])
        : "r"(a[0]), "r"(a[1]), "r"(a[2]), "r"(a[3]), "r"(b0), "r"(b1));
}
__device__ __forceinline__ uint32_t pack_h2(__half a, __half b) {
    __half2 h = __halves2half2(a, b);
    return *(uint32_t*)&h;
}

// ======================= split fp32 -> fp16 hi/lo ==========================
__global__ __launch_bounds__(256) void split_f32(
    const float4* __restrict__ x, __half2* __restrict__ hi,
    __half2* __restrict__ lo, int n4)
{
    int i = blockIdx.x * blockDim.x + threadIdx.x;
    if (i >= n4) return;
    float4 v = x[i];
    __half h0 = __float2half_rn(v.x), h1 = __float2half_rn(v.y);
    __half h2 = __float2half_rn(v.z), h3 = __float2half_rn(v.w);
    hi[2 * i]     = __halves2half2(h0, h1);
    hi[2 * i + 1] = __halves2half2(h2, h3);
    if (lo) {
        lo[2 * i] = __halves2half2(__float2half_rn(v.x - __half2float(h0)),
                                   __float2half_rn(v.y - __half2float(h1)));
        lo[2 * i + 1] = __halves2half2(__float2half_rn(v.z - __half2float(h2)),
                                       __float2half_rn(v.w - __half2float(h3)));
    }
}

// ======================= HMMA GEMM core (A-split, 2-term) ===================
// C = A @ B^T with A hi/lo (activations), B hi only (weights).
// Tile 128x256xBK32, 8 warps, warp tile 64x64, 3-stage cp.async.
#define BM 128
#define BN 256
#define BK 32
#define ROWB 80
#define A_ST (BM*ROWB)                 // 10240
#define B_ST (BN*ROWB)                 // 20480
#define STAGE_B (2*A_ST + B_ST)        // 40960
#define NSTAGE 3
#define GEMM_SMEM (NSTAGE*STAGE_B)     // 122880

struct GemmOut {
    float* C;
    __half* Ch;
    __half* Cl;
    int Nout;
    int split;
};

__device__ __forceinline__ void gemm2_core(
    uint32_t sbase, const __half* A0h, const __half* A0l, const __half* B0h,
    int m0, int ncol0, int K, const GemmOut& o)
{
    const int tid  = threadIdx.x;
    const int wid  = tid >> 5;
    const int lane = tid & 31;
    const int wm   = wid & 1;
    const int wn   = wid >> 1;

    auto bAh = [&](int s) { return sbase + s * STAGE_B; };
    auto bAl = [&](int s) { return sbase + s * STAGE_B + A_ST; };
    auto bB  = [&](int s) { return sbase + s * STAGE_B + 2 * A_ST; };

    auto load_stage = [&](int s, int k0) {
#pragma unroll
        for (int t = 0; t < 2; t++) {                // A hi+lo: 512 chunks each
            int idx = tid + t * 256;
            int r = idx >> 2, c = idx & 3;
            uint32_t d = (uint32_t)(r * ROWB + c * 16);
            size_t so = (size_t)r * K + k0 + c * 8;
            cp16(bAh(s) + d, A0h + so);
            cp16(bAl(s) + d, A0l + so);
        }
#pragma unroll
        for (int t = 0; t < 4; t++) {                // B hi: 1024 chunks
            int idx = tid + t * 256;
            int r = idx >> 2, c = idx & 3;
            uint32_t d = (uint32_t)(r * ROWB + c * 16);
            cp16(bB(s) + d, B0h + (size_t)r * K + k0 + c * 8);
        }
    };

    float acc[4][8][4];
#pragma unroll
    for (int i = 0; i < 4; i++)
#pragma unroll
        for (int j = 0; j < 8; j++)
#pragma unroll
            for (int t = 0; t < 4; t++) acc[i][j][t] = 0.f;

    const int aRow = lane & 15;
    const int aKof = (lane >> 4) * 16;
    const int bRow = (lane & 7) + ((lane & 16) ? 8 : 0);
    const int bKof = (lane & 8) ? 16 : 0;
    const int warpM = wm * 64;
    const int warpN = wn * 64;

    const int nst = K / BK;
    load_stage(0, 0);
    cp_commit();
    load_stage(1, BK);
    cp_commit();

    for (int s = 0; s < nst; s++) {
        const int buf = s % NSTAGE;
        if (s + 1 < nst) cp_wait<1>(); else cp_wait<0>();
        __syncthreads();

        const uint32_t sAh = bAh(buf), sAl = bAl(buf), sB = bB(buf);

#pragma unroll
        for (int ks = 0; ks < 2; ks++) {
            const int kb = ks * 32;
            uint32_t ah[4][4], al[4][4], bh[4][4];
#pragma unroll
            for (int mi = 0; mi < 4; mi++) {
                uint32_t ad = (uint32_t)((warpM + mi * 16 + aRow) * ROWB + kb + aKof);
                ldm_x4(ah[mi], sAh + ad);
                ldm_x4(al[mi], sAl + ad);
            }
#pragma unroll
            for (int np = 0; np < 4; np++) {
                uint32_t bd = (uint32_t)((warpN + np * 16 + bRow) * ROWB + kb + bKof);
                ldm_x4(bh[np], sB + bd);
            }
            // term 1: Ah * Bh  (same-acc RAW distance = 32 MMAs)
#pragma unroll
            for (int np = 0; np < 4; np++)
#pragma unroll
                for (int q = 0; q < 2; q++) {
                    const int ni = np * 2 + q;
                    const uint32_t b0 = bh[np][q * 2], b1 = bh[np][q * 2 + 1];
#pragma unroll
                    for (int mi = 0; mi < 4; mi++)
                        mma16816(acc[mi][ni], ah[mi], b0, b1);
                }
            // term 2: Al * Bh
#pragma unroll
            for (int np = 0; np < 4; np++)
#pragma unroll
                for (int q = 0; q < 2; q++) {
                    const int ni = np * 2 + q;
                    const uint32_t b0 = bh[np][q * 2], b1 = bh[np][q * 2 + 1];
#pragma unroll
                    for (int mi = 0; mi < 4; mi++)
                        mma16816(acc[mi][ni], al[mi], b0, b1);
                }
        }

        if (s + 2 < nst) {
            load_stage((s + 2) % NSTAGE, (s + 2) * BK);
            cp_commit();
        }
    }

    const int er = lane >> 2;
    const int ec = (lane & 3) * 2;
    if (!o.split) {
#pragma unroll
        for (int mi = 0; mi < 4; mi++)
#pragma unroll
            for (int ni = 0; ni < 8; ni++) {
                float* p = o.C + (size_t)(m0 + warpM + mi * 16 + er) * o.Nout
                               + (ncol0 + warpN + ni * 8 + ec);
                p[0] = acc[mi][ni][0];
                p[1] = acc[mi][ni][1];
                float* q = p + (size_t)8 * o.Nout;
                q[0] = acc[mi][ni][2];
                q[1] = acc[mi][ni][3];
            }
    } else {
#pragma unroll
        for (int mi = 0; mi < 4; mi++)
#pragma unroll
            for (int ni = 0; ni < 8; ni++) {
                size_t off0 = (size_t)(m0 + warpM + mi * 16 + er) * o.Nout
                            + (ncol0 + warpN + ni * 8 + ec);
                size_t off1 = off0 + (size_t)8 * o.Nout;
                float v0 = acc[mi][ni][0], v1 = acc[mi][ni][1];
                float v2 = acc[mi][ni][2], v3 = acc[mi][ni][3];
                __half h0 = __float2half_rn(v0), h1 = __float2half_rn(v1);
                __half h2 = __float2half_rn(v2), h3 = __float2half_rn(v3);
                *(uint32_t*)(o.Ch + off0) = pack_h2(h0, h1);
                *(uint32_t*)(o.Ch + off1) = pack_h2(h2, h3);
                *(uint32_t*)(o.Cl + off0) = pack_h2(
                    __float2half_rn(v0 - __half2float(h0)),
                    __float2half_rn(v1 - __half2float(h1)));
                *(uint32_t*)(o.Cl + off1) = pack_h2(
                    __float2half_rn(v2 - __half2float(h2)),
                    __float2half_rn(v3 - __half2float(h3)));
            }
    }
}

// swizzled block mapping (supertiles of 8 m-blocks)
__device__ __forceinline__ void cta_map(int gx, int gy, int& mb, int& nb) {
    int lin = blockIdx.y * gx + blockIdx.x;
    const int SW = 8;
    int per  = SW * gx;
    int band = lin / per;
    int rem  = lin - band * per;
    int h    = gy - band * SW; if (h > SW) h = SW;
    mb = band * SW + rem % h;
    nb = rem / h;
}

// fused QKV projection: virtual N = 6144 (Q 4096 | K 1024 | V 1024)
__global__ __launch_bounds__(256, 1) void qkv_hmma(
    const __half* __restrict__ xh, const __half* __restrict__ xl,
    const __half* __restrict__ wqh,
    const __half* __restrict__ wkh,
    const __half* __restrict__ wvh,
    __half* __restrict__ qh, __half* __restrict__ ql,
    __half* __restrict__ kh, __half* __restrict__ kl,
    __half* __restrict__ vh, __half* __restrict__ vl)
{
    extern __shared__ char smraw[];
    const uint32_t sbase = smem_u32(smraw);
    int mb, nb;
    cta_map(gridDim.x, gridDim.y, mb, nb);
    const int m0 = mb * BM;

    const __half* Bh_;
    GemmOut o; o.C = nullptr; o.split = 1;
    int ncol;
    if (nb < 16)      { Bh_ = wqh; o.Ch = qh; o.Cl = ql; o.Nout = HIDDEN; ncol = nb * BN; }
    else if (nb < 20) { Bh_ = wkh; o.Ch = kh; o.Cl = kl; o.Nout = KVDIM;  ncol = (nb - 16) * BN; }
    else              { Bh_ = wvh; o.Ch = vh; o.Cl = vl; o.Nout = KVDIM;  ncol = (nb - 20) * BN; }

    gemm2_core(sbase, xh + (size_t)m0 * HIDDEN, xl + (size_t)m0 * HIDDEN,
               Bh_ + (size_t)ncol * HIDDEN, m0, ncol, HIDDEN, o);
}

// output GEMM (fp32 out): A = AO hi/lo, B = Wo hi
__global__ __launch_bounds__(256, 1) void gemm_hmma2(
    const __half* __restrict__ Ah, const __half* __restrict__ Al,
    const __half* __restrict__ Bh,
    float* __restrict__ C, int N, int K)
{
    extern __shared__ char smraw[];
    const uint32_t sbase = smem_u32(smraw);
    int mb, nb;
    cta_map(gridDim.x, gridDim.y, mb, nb);
    const int m0 = mb * BM, n0 = nb * BN;
    GemmOut o; o.C = C; o.Ch = nullptr; o.Cl = nullptr; o.Nout = N; o.split = 0;
    gemm2_core(sbase, Ah + (size_t)m0 * K, Al + (size_t)m0 * K,
               Bh + (size_t)n0 * K, m0, n0, K, o);
}

// ======================= V transpose (halves) ===============================
__global__ __launch_bounds__(256) void transpose_v(
    const __half* __restrict__ vh, const __half* __restrict__ vl,
    __half* __restrict__ vth, __half* __restrict__ vtl)
{
    __shared__ __half th[32][33], tl[32][33];
    const int b  = blockIdx.z;
    const int k0 = blockIdx.y * 32;
    const int s0 = blockIdx.x * 32;
    const int tx = threadIdx.x & 31;
    const int ty = threadIdx.x >> 5;
#pragma unroll
    for (int i = 0; i < 4; i++) {
        int row = ty + i * 8;
        size_t src = (size_t)(b * SEQ + s0 + row) * KVDIM + k0 + tx;
        th[row][tx] = vh[src];
        tl[row][tx] = vl[src];
    }
    __syncthreads();
#pragma unroll
    for (int i = 0; i < 4; i++) {
        int row = ty + i * 8;
        size_t dst = ((size_t)b * KVDIM + k0 + row) * SEQ + s0 + tx;
        vth[dst] = th[tx][row];
        vtl[dst] = tl[tx][row];
    }
}

// ======================= HMMA flash attention (3-term) ======================
#define QROWB 272
#define KROWB 272
#define VROWB 144
#define SQ_L      34816
#define SKV_BASE  69632
#define SKV_STRIDE 71680
#define OFF_KH 0
#define OFF_KL 17408
#define OFF_VTH 34816
#define OFF_VTL 53248
#define FLASH_SMEM 212992

__global__ __launch_bounds__(256, 1) void flash_hmma(
    const __half* __restrict__ qh, const __half* __restrict__ ql,
    const __half* __restrict__ kh, const __half* __restrict__ kl,
    const __half* __restrict__ vth, const __half* __restrict__ vtl,
    __half* __restrict__ aoh, __half* __restrict__ aol)
{
    extern __shared__ char smraw[];
    const uint32_t sb = smem_u32(smraw);
    const int tid = threadIdx.x, wid = tid >> 5, lane = tid & 31;
    const int qb = (int)(gridDim.x - 1 - blockIdx.x);
    const int hq = blockIdx.y, b = blockIdx.z;
    const int kvh = hq >> 2;
    const int qrow0 = qb * 128;
    const int g = lane >> 2, tig = lane & 3;
    const float scale = 0.08838834764831845f;

    const __half* qhg = qh + (size_t)(b * SEQ + qrow0) * HIDDEN + hq * HD;
    const __half* qlg = ql + (size_t)(b * SEQ + qrow0) * HIDDEN + hq * HD;
#pragma unroll
    for (int t = 0; t < 8; t++) {
        int idx = tid + t * 256;
        int r = idx >> 4, c = idx & 15;
        uint32_t d = (uint32_t)(r * QROWB + c * 16);
        size_t s = (size_t)r * HIDDEN + c * 8;
        cp16(sb + d, qhg + s);
        cp16(sb + SQ_L + d, qlg + s);
    }
    cp_commit();

    const __half* khg = kh + (size_t)(b * SEQ) * KVDIM + kvh * HD;
    const __half* klg = kl + (size_t)(b * SEQ) * KVDIM + kvh * HD;
    const __half* vthg = vth + ((size_t)b * KVDIM + kvh * HD) * SEQ;
    const __half* vtlg = vtl + ((size_t)b * KVDIM + kvh * HD) * SEQ;

    auto load_kv = [&](int stage, int j) {
        uint32_t base = sb + SKV_BASE + stage * SKV_STRIDE;
        int c0 = j * 64;
#pragma unroll
        for (int t = 0; t < 4; t++) {
            int idx = tid + t * 256;
            int r = idx >> 4, c = idx & 15;
            uint32_t d = (uint32_t)(r * KROWB + c * 16);
            size_t s = (size_t)(c0 + r) * KVDIM + c * 8;
            cp16(base + OFF_KH + d, khg + s);
            cp16(base + OFF_KL + d, klg + s);
        }
#pragma unroll
        for (int t = 0; t < 4; t++) {
            int idx = tid + t * 256;
            int r = idx >> 3, c = idx & 7;
            uint32_t d = (uint32_t)(r * VROWB + c * 16);
            size_t s = (size_t)r * SEQ + c0 + c * 8;
            cp16(base + OFF_VTH + d, vthg + s);
            cp16(base + OFF_VTL + d, vtlg + s);
        }
    };

    const int nb = 2 * qb + 2;
    load_kv(0, 0);
    cp_commit();

    float oacc[16][4];
#pragma unroll
    for (int i = 0; i < 16; i++)
#pragma unroll
        for (int t = 0; t < 4; t++) oacc[i][t] = 0.f;
    float m0 = -1e30f, m1 = -1e30f, l0 = 0.f, l1 = 0.f;

    const int aRow = lane & 15;
    const int aKof = (lane >> 4) * 16;
    const int bRow = (lane & 7) + ((lane & 16) ? 8 : 0);
    const int bKof = (lane & 8) ? 16 : 0;

    const int rg0 = qrow0 + 16 * wid + g;
    const int rg1 = rg0 + 8;

    for (int j = 0; j < nb; j++) {
        const int buf = j & 1;
        if (j + 1 < nb) {
            load_kv(1 - buf, j + 1);
            cp_commit();
            cp_wait<1>();
        } else {
            cp_wait<0>();
        }
        __syncthreads();

        const uint32_t kbase = sb + SKV_BASE + buf * SKV_STRIDE;

        float sacc[8][4];
#pragma unroll
        for (int i = 0; i < 8; i++)
#pragma unroll
            for (int t = 0; t < 4; t++) sacc[i][t] = 0.f;

#pragma unroll
        for (int kd = 0; kd < 8; kd++) {
            uint32_t aa = (uint32_t)((16 * wid + aRow) * QROWB + kd * 32 + aKof);
            uint32_t ah[4], al[4];
            ldm_x4(ah, sb + aa);
            ldm_x4(al, sb + SQ_L + aa);
            uint32_t bh[4][4], bl[4][4];
#pragma unroll
            for (int np = 0; np < 4; np++) {
                uint32_t ba = (uint32_t)((np * 16 + bRow) * KROWB + kd * 32 + bKof);
                ldm_x4(bh[np], kbase + OFF_KH + ba);
                ldm_x4(bl[np], kbase + OFF_KL + ba);
            }
#pragma unroll
            for (int ni = 0; ni < 8; ni++) {
                uint32_t b0h = bh[ni >> 1][(ni & 1) * 2], b1h = bh[ni >> 1][(ni & 1) * 2 + 1];
                mma16816(sacc[ni], ah, b0h, b1h);
            }
#pragma unroll
            for (int ni = 0; ni < 8; ni++) {
                uint32_t b0l = bl[ni >> 1][(ni & 1) * 2], b1l = bl[ni >> 1][(ni & 1) * 2 + 1];
                mma16816(sacc[ni], ah, b0l, b1l);
            }
#pragma unroll
            for (int ni = 0; ni < 8; ni++) {
                uint32_t b0h = bh[ni >> 1][(ni & 1) * 2], b1h = bh[ni >> 1][(ni & 1) * 2 + 1];
                mma16816(sacc[ni], al, b0h, b1h);
            }
        }

        const int c0 = j * 64;
#pragma unroll
        for (int ni = 0; ni < 8; ni++)
#pragma unroll
            for (int t = 0; t < 4; t++) sacc[ni][t] *= scale;
        if (j >= 2 * qb) {
#pragma unroll
            for (int ni = 0; ni < 8; ni++) {
                int cg = c0 + ni * 8 + 2 * tig;
                if (cg     > rg0) sacc[ni][0] = -1e30f;
                if (cg + 1 > rg0) sacc[ni][1] = -1e30f;
                if (cg     > rg1) sacc[ni][2] = -1e30f;
                if (cg + 1 > rg1) sacc[ni][3] = -1e30f;
            }
        }

        float vm0 = -1e30f, vm1 = -1e30f;
#pragma unroll
        for (int ni = 0; ni < 8; ni++) {
            vm0 = fmaxf(vm0, fmaxf(sacc[ni][0], sacc[ni][1]));
            vm1 = fmaxf(vm1, fmaxf(sacc[ni][2], sacc[ni][3]));
        }
        vm0 = fmaxf(vm0, __shfl_xor_sync(0xffffffffu, vm0, 1));
        vm0 = fmaxf(vm0, __shfl_xor_sync(0xffffffffu, vm0, 2));
        vm1 = fmaxf(vm1, __shfl_xor_sync(0xffffffffu, vm1, 1));
        vm1 = fmaxf(vm1, __shfl_xor_sync(0xffffffffu, vm1, 2));
        float mn0 = fmaxf(m0, vm0), mn1 = fmaxf(m1, vm1);
        float al0 = __expf(m0 - mn0), al1 = __expf(m1 - mn1);
        float sum0 = 0.f, sum1 = 0.f;
#pragma unroll
        for (int ni = 0; ni < 8; ni++) {
            sacc[ni][0] = __expf(sacc[ni][0] - mn0);
            sacc[ni][1] = __expf(sacc[ni][1] - mn0);
            sacc[ni][2] = __expf(sacc[ni][2] - mn1);
            sacc[ni][3] = __expf(sacc[ni][3] - mn1);
            sum0 += sacc[ni][0] + sacc[ni][1];
            sum1 += sacc[ni][2] + sacc[ni][3];
        }
        sum0 += __shfl_xor_sync(0xffffffffu, sum0, 1);
        sum0 += __shfl_xor_sync(0xffffffffu, sum0, 2);
        sum1 += __shfl_xor_sync(0xffffffffu, sum1, 1);
        sum1 += __shfl_xor_sync(0xffffffffu, sum1, 2);
        l0 = l0 * al0 + sum0;  l1 = l1 * al1 + sum1;
        m0 = mn0;  m1 = mn1;

#pragma unroll
        for (int nd = 0; nd < 16; nd++) {
            oacc[nd][0] *= al0;  oacc[nd][1] *= al0;
            oacc[nd][2] *= al1;  oacc[nd][3] *= al1;
        }

        uint32_t pah[4][4], pal[4][4];
#pragma unroll
        for (int t = 0; t < 4; t++) {
            float p00 = sacc[2 * t][0],     p01 = sacc[2 * t][1];
            float p10 = sacc[2 * t][2],     p11 = sacc[2 * t][3];
            float p20 = sacc[2 * t + 1][0], p21 = sacc[2 * t + 1][1];
            float p30 = sacc[2 * t + 1][2], p31 = sacc[2 * t + 1][3];
            __half h00 = __float2half_rn(p00), h01 = __float2half_rn(p01);
            __half h10 = __float2half_rn(p10), h11 = __float2half_rn(p11);
            __half h20 = __float2half_rn(p20), h21 = __float2half_rn(p21);
            __half h30 = __float2half_rn(p30), h31 = __float2half_rn(p31);
            pah[t][0] = pack_h2(h00, h01);
            pah[t][1] = pack_h2(h10, h11);
            pah[t][2] = pack_h2(h20, h21);
            pah[t][3] = pack_h2(h30, h31);
            pal[t][0] = pack_h2(__float2half_rn(p00 - __half2float(h00)),
                                __float2half_rn(p01 - __half2float(h01)));
            pal[t][1] = pack_h2(__float2half_rn(p10 - __half2float(h10)),
                                __float2half_rn(p11 - __half2float(h11)));
            pal[t][2] = pack_h2(__float2half_rn(p20 - __half2float(h20)),
                                __float2half_rn(p21 - __half2float(h21)));
            pal[t][3] = pack_h2(__float2half_rn(p30 - __half2float(h30)),
                                __float2half_rn(p31 - __half2float(h31)));
        }

#pragma unroll
        for (int t = 0; t < 4; t++) {
#pragma unroll
            for (int np = 0; np < 8; np++) {
                uint32_t ba = (uint32_t)((np * 16 + bRow) * VROWB + t * 32 + bKof);
                uint32_t vbh[4], vbl[4];
                ldm_x4(vbh, kbase + OFF_VTH + ba);
                ldm_x4(vbl, kbase + OFF_VTL + ba);
#pragma unroll
                for (int q = 0; q < 2; q++) {
                    int nd = np * 2 + q;
                    uint32_t b0h = vbh[q * 2], b1h = vbh[q * 2 + 1];
                    uint32_t b0l = vbl[q * 2], b1l = vbl[q * 2 + 1];
                    mma16816(oacc[nd], pah[t], b0h, b1h);
                    mma16816(oacc[nd], pah[t], b0l, b1l);
                    mma16816(oacc[nd], pal[t], b0h, b1h);
                }
            }
        }
        __syncthreads();
    }

    float inv0 = 1.f / l0, inv1 = 1.f / l1;
    size_t row0 = (size_t)(b * SEQ + qrow0 + 16 * wid + g) * HIDDEN + hq * HD;
    size_t row1 = row0 + (size_t)8 * HIDDEN;
#pragma unroll
    for (int nd = 0; nd < 16; nd++) {
        int col = nd * 8 + 2 * tig;
        float v0 = oacc[nd][0] * inv0, v1 = oacc[nd][1] * inv0;
        float v2 = oacc[nd][2] * inv1, v3 = oacc[nd][3] * inv1;
        __half h0 = __float2half_rn(v0), h1 = __float2half_rn(v1);
        __half h2 = __float2half_rn(v2), h3 = __float2half_rn(v3);
        *(uint32_t*)(aoh + row0 + col) = pack_h2(h0, h1);
        *(uint32_t*)(aoh + row1 + col) = pack_h2(h2, h3);
        *(uint32_t*)(aol + row0 + col) = pack_h2(
            __float2half_rn(v0 - __half2float(h0)),
            __float2half_rn(v1 - __half2float(h1)));
        *(uint32_t*)(aol + row1 + col) = pack_h2(
            __float2half_rn(v2 - __half2float(h2)),
            __float2half_rn(v3 - __half2float(h3)));
    }
}

// ============================================================================
extern "C" void kernel_launch(void* const* d_in, const int* in_sizes, int n_in,
                              void* d_out, int out_size)
{
    const float* x  = (const float*)d_in[0];
    const float* Wq = (const float*)d_in[1];
    const float* Wk = (const float*)d_in[2];
    const float* Wv = (const float*)d_in[3];
    const float* Wo = (const float*)d_in[4];
    float* out = (float*)d_out;

    __half *xh, *xl, *wqh, *wkh, *wvh, *woh;
    __half *qh, *ql, *kh, *kl, *vh, *vl, *vth, *vtl, *aoh, *aol;
    cudaGetSymbolAddress((void**)&xh,  g_xh);  cudaGetSymbolAddress((void**)&xl,  g_xl);
    cudaGetSymbolAddress((void**)&wqh, g_wqh);
    cudaGetSymbolAddress((void**)&wkh, g_wkh);
    cudaGetSymbolAddress((void**)&wvh, g_wvh);
    cudaGetSymbolAddress((void**)&woh, g_woh);
    cudaGetSymbolAddress((void**)&qh,  g_qh);  cudaGetSymbolAddress((void**)&ql,  g_ql);
    cudaGetSymbolAddress((void**)&kh,  g_kh);  cudaGetSymbolAddress((void**)&kl,  g_kl);
    cudaGetSymbolAddress((void**)&vh,  g_vh);  cudaGetSymbolAddress((void**)&vl,  g_vl);
    cudaGetSymbolAddress((void**)&vth, g_vth); cudaGetSymbolAddress((void**)&vtl, g_vtl);
    cudaGetSymbolAddress((void**)&aoh, g_aoh); cudaGetSymbolAddress((void**)&aol, g_aol);

    cudaFuncSetAttribute(qkv_hmma,   cudaFuncAttributeMaxDynamicSharedMemorySize, GEMM_SMEM);
    cudaFuncSetAttribute(gemm_hmma2, cudaFuncAttributeMaxDynamicSharedMemorySize, GEMM_SMEM);
    cudaFuncSetAttribute(flash_hmma, cudaFuncAttributeMaxDynamicSharedMemorySize, FLASH_SMEM);

    const int XN4 = TOKENS * HIDDEN / 4;
    const int WN4 = HIDDEN * HIDDEN / 4;
    const int KN4 = KVDIM * HIDDEN / 4;

    split_f32<<<(XN4 + 255) / 256, 256>>>((const float4*)x,  (__half2*)xh,  (__half2*)xl, XN4);
    split_f32<<<(WN4 + 255) / 256, 256>>>((const float4*)Wq, (__half2*)wqh, nullptr, WN4);
    split_f32<<<(KN4 + 255) / 256, 256>>>((const float4*)Wk, (__half2*)wkh, nullptr, KN4);
    split_f32<<<(KN4 + 255) / 256, 256>>>((const float4*)Wv, (__half2*)wvh, nullptr, KN4);
    split_f32<<<(WN4 + 255) / 256, 256>>>((const float4*)Wo, (__half2*)woh, nullptr, WN4);

    qkv_hmma<<<dim3(6144 / BN, TOKENS / BM), 256, GEMM_SMEM>>>(
        xh, xl, wqh, wkh, wvh, qh, ql, kh, kl, vh, vl);

    transpose_v<<<dim3(SEQ / 32, KVDIM / 32, BATCH), 256>>>(vh, vl, vth, vtl);

    flash_hmma<<<dim3(SEQ / 128, NH, BATCH), 256, FLASH_SMEM>>>(
        qh, ql, kh, kl, vth, vtl, aoh, aol);

    gemm_hmma2<<<dim3(HIDDEN / BN, TOKENS / BM), 256, GEMM_SMEM>>>(
        aoh, aol, woh, out, HIDDEN, HIDDEN);
}

// round 8
// speedup vs baseline: 4.4168x; 1.0553x over previous
#include <cuda_runtime.h>
#include <cuda_fp16.h>
#include <cstdint>
#include <math.h>

#define HIDDEN   4096
#define NKV      8
#define NH       32
#define HD       128
#define BATCH    2
#define SEQ      2048
#define TOKENS   (BATCH*SEQ)   // 4096
#define KVDIM    (NKV*HD)      // 1024

// ---------------- scratch (device globals; no runtime allocation) ----------
__device__ __half g_xh [TOKENS*HIDDEN], g_xl [TOKENS*HIDDEN];
__device__ __half g_wqh[HIDDEN*HIDDEN];
__device__ __half g_wkh[KVDIM*HIDDEN];
__device__ __half g_wvh[KVDIM*HIDDEN];
__device__ __half g_woh[HIDDEN*HIDDEN];
__device__ __half g_qh [TOKENS*HIDDEN], g_ql [TOKENS*HIDDEN];
__device__ __half g_kh [TOKENS*KVDIM],  g_kl [TOKENS*KVDIM];
__device__ __half g_vh [TOKENS*KVDIM],  g_vl [TOKENS*KVDIM];
__device__ __half g_vth[TOKENS*KVDIM],  g_vtl[TOKENS*KVDIM];  // [B][KVDIM][SEQ]
__device__ __half g_aoh[TOKENS*HIDDEN], g_aol[TOKENS*HIDDEN];

// ======================= helpers ============================================
__device__ __forceinline__ uint32_t smem_u32(const void* p) {
    uint32_t a;
    asm("{ .reg .u64 t; cvta.to.shared.u64 t, %1; cvt.u32.u64 %0, t; }"
        : "=r"(a) : "l"(p));
    return a;
}
__device__ __forceinline__ void cp16(uint32_t dst, const void* src) {
    asm volatile("cp.async.cg.shared.global [%0], [%1], 16;" :: "r"(dst), "l"(src));
}
__device__ __forceinline__ void cp_commit() { asm volatile("cp.async.commit_group;" ::: "memory"); }
template<int N> __device__ __forceinline__ void cp_wait() {
    asm volatile("cp.async.wait_group %0;" :: "n"(N) : "memory");
}
__device__ __forceinline__ void ldm_x4(uint32_t* r, uint32_t addr) {
    asm volatile("ldmatrix.sync.aligned.m8n8.x4.shared.b16 {%0,%1,%2,%3}, [%4];"
        : "=r"(r[0]), "=r"(r[1]), "=r"(r[2]), "=r"(r[3]) : "r"(addr));
}
__device__ __forceinline__ void mma16816(float* d, const uint32_t* a,
                                         uint32_t b0, uint32_t b1) {
    asm volatile(
        "mma.sync.aligned.m16n8k16.row.col.f32.f16.f16.f32 "
        "{%0,%1,%2,%3}, {%4,%5,%6,%7}, {%8,%9}, {%0,%1,%2,%3};"
        : "+f"(d[0]), "+f"(d[1]), "+f"(d[2]), "+f"(d[3])
        : "r"(a[0]), "r"(a[1]), "r"(a[2]), "r"(a[3]), "r"(b0), "r"(b1));
}
__device__ __forceinline__ uint32_t pack_h2(__half a, __half b) {
    __half2 h = __halves2half2(a, b);
    return *(uint32_t*)&h;
}

// ======================= split fp32 -> fp16 hi/lo ==========================
__global__ __launch_bounds__(256) void split_f32(
    const float4* __restrict__ x, __half2* __restrict__ hi,
    __half2* __restrict__ lo, int n4)
{
    int i = blockIdx.x * blockDim.x + threadIdx.x;
    if (i >= n4) return;
    float4 v = x[i];
    __half h0 = __float2half_rn(v.x), h1 = __float2half_rn(v.y);
    __half h2 = __float2half_rn(v.z), h3 = __float2half_rn(v.w);
    hi[2 * i]     = __halves2half2(h0, h1);
    hi[2 * i + 1] = __halves2half2(h2, h3);
    if (lo) {
        lo[2 * i] = __halves2half2(__float2half_rn(v.x - __half2float(h0)),
                                   __float2half_rn(v.y - __half2float(h1)));
        lo[2 * i + 1] = __halves2half2(__float2half_rn(v.z - __half2float(h2)),
                                       __float2half_rn(v.w - __half2float(h3)));
    }
}

// ======================= HMMA GEMM core (A-split, 2-term) ===================
// C = A @ B^T with A hi/lo (activations), B hi only (weights).
// Tile 128x256xBK64, 8 warps, warp tile 64x64, 3-stage cp.async.
#define BM 128
#define BN 256
#define BK 64
#define ROWB 144                       // 128B data + 16B pad, conflict-free
#define A_ST (BM*ROWB)                 // 18432
#define B_ST (BN*ROWB)                 // 36864
#define STAGE_B (2*A_ST + B_ST)        // 73728
#define NSTAGE 3
#define GEMM_SMEM (NSTAGE*STAGE_B)     // 221184

struct GemmOut {
    float* C;
    __half* Ch;
    __half* Cl;
    int Nout;
    int split;
};

__device__ __forceinline__ void gemm2_core(
    uint32_t sbase, const __half* A0h, const __half* A0l, const __half* B0h,
    int m0, int ncol0, int K, const GemmOut& o)
{
    const int tid  = threadIdx.x;
    const int wid  = tid >> 5;
    const int lane = tid & 31;
    const int wm   = wid & 1;
    const int wn   = wid >> 1;

    auto bAh = [&](int s) { return sbase + s * STAGE_B; };
    auto bAl = [&](int s) { return sbase + s * STAGE_B + A_ST; };
    auto bB  = [&](int s) { return sbase + s * STAGE_B + 2 * A_ST; };

    auto load_stage = [&](int s, int k0) {
#pragma unroll
        for (int t = 0; t < 4; t++) {                // A hi+lo: 1024 chunks each
            int idx = tid + t * 256;
            int r = idx >> 3, c = idx & 7;
            uint32_t d = (uint32_t)(r * ROWB + c * 16);
            size_t so = (size_t)r * K + k0 + c * 8;
            cp16(bAh(s) + d, A0h + so);
            cp16(bAl(s) + d, A0l + so);
        }
#pragma unroll
        for (int t = 0; t < 8; t++) {                // B hi: 2048 chunks
            int idx = tid + t * 256;
            int r = idx >> 3, c = idx & 7;
            uint32_t d = (uint32_t)(r * ROWB + c * 16);
            cp16(bB(s) + d, B0h + (size_t)r * K + k0 + c * 8);
        }
    };

    float acc[4][8][4];
#pragma unroll
    for (int i = 0; i < 4; i++)
#pragma unroll
        for (int j = 0; j < 8; j++)
#pragma unroll
            for (int t = 0; t < 4; t++) acc[i][j][t] = 0.f;

    const int aRow = lane & 15;
    const int aKof = (lane >> 4) * 16;
    const int bRow = (lane & 7) + ((lane & 16) ? 8 : 0);
    const int bKof = (lane & 8) ? 16 : 0;
    const int warpM = wm * 64;
    const int warpN = wn * 64;

    const int nst = K / BK;
    load_stage(0, 0);
    cp_commit();
    load_stage(1, BK);
    cp_commit();

    for (int s = 0; s < nst; s++) {
        const int buf = s % NSTAGE;
        if (s + 1 < nst) cp_wait<1>(); else cp_wait<0>();
        __syncthreads();

        const uint32_t sAh = bAh(buf), sAl = bAl(buf), sB = bB(buf);

#pragma unroll
        for (int ks = 0; ks < 4; ks++) {
            const int kb = ks * 32;
            uint32_t ah[4][4], al[4][4], bh[4][4];
#pragma unroll
            for (int mi = 0; mi < 4; mi++) {
                uint32_t ad = (uint32_t)((warpM + mi * 16 + aRow) * ROWB + kb + aKof);
                ldm_x4(ah[mi], sAh + ad);
                ldm_x4(al[mi], sAl + ad);
            }
#pragma unroll
            for (int np = 0; np < 4; np++) {
                uint32_t bd = (uint32_t)((warpN + np * 16 + bRow) * ROWB + kb + bKof);
                ldm_x4(bh[np], sB + bd);
            }
            // term 1: Ah * Bh  (same-acc RAW distance = 32 MMAs)
#pragma unroll
            for (int np = 0; np < 4; np++)
#pragma unroll
                for (int q = 0; q < 2; q++) {
                    const int ni = np * 2 + q;
                    const uint32_t b0 = bh[np][q * 2], b1 = bh[np][q * 2 + 1];
#pragma unroll
                    for (int mi = 0; mi < 4; mi++)
                        mma16816(acc[mi][ni], ah[mi], b0, b1);
                }
            // term 2: Al * Bh
#pragma unroll
            for (int np = 0; np < 4; np++)
#pragma unroll
                for (int q = 0; q < 2; q++) {
                    const int ni = np * 2 + q;
                    const uint32_t b0 = bh[np][q * 2], b1 = bh[np][q * 2 + 1];
#pragma unroll
                    for (int mi = 0; mi < 4; mi++)
                        mma16816(acc[mi][ni], al[mi], b0, b1);
                }
        }

        if (s + 2 < nst) {
            load_stage((s + 2) % NSTAGE, (s + 2) * BK);
            cp_commit();
        }
    }

    const int er = lane >> 2;
    const int ec = (lane & 3) * 2;
    if (!o.split) {
#pragma unroll
        for (int mi = 0; mi < 4; mi++)
#pragma unroll
            for (int ni = 0; ni < 8; ni++) {
                float* p = o.C + (size_t)(m0 + warpM + mi * 16 + er) * o.Nout
                               + (ncol0 + warpN + ni * 8 + ec);
                p[0] = acc[mi][ni][0];
                p[1] = acc[mi][ni][1];
                float* q = p + (size_t)8 * o.Nout;
                q[0] = acc[mi][ni][2];
                q[1] = acc[mi][ni][3];
            }
    } else {
#pragma unroll
        for (int mi = 0; mi < 4; mi++)
#pragma unroll
            for (int ni = 0; ni < 8; ni++) {
                size_t off0 = (size_t)(m0 + warpM + mi * 16 + er) * o.Nout
                            + (ncol0 + warpN + ni * 8 + ec);
                size_t off1 = off0 + (size_t)8 * o.Nout;
                float v0 = acc[mi][ni][0], v1 = acc[mi][ni][1];
                float v2 = acc[mi][ni][2], v3 = acc[mi][ni][3];
                __half h0 = __float2half_rn(v0), h1 = __float2half_rn(v1);
                __half h2 = __float2half_rn(v2), h3 = __float2half_rn(v3);
                *(uint32_t*)(o.Ch + off0) = pack_h2(h0, h1);
                *(uint32_t*)(o.Ch + off1) = pack_h2(h2, h3);
                *(uint32_t*)(o.Cl + off0) = pack_h2(
                    __float2half_rn(v0 - __half2float(h0)),
                    __float2half_rn(v1 - __half2float(h1)));
                *(uint32_t*)(o.Cl + off1) = pack_h2(
                    __float2half_rn(v2 - __half2float(h2)),
                    __float2half_rn(v3 - __half2float(h3)));
            }
    }
}

// swizzled block mapping (supertiles of 8 m-blocks)
__device__ __forceinline__ void cta_map(int gx, int gy, int& mb, int& nb) {
    int lin = blockIdx.y * gx + blockIdx.x;
    const int SW = 8;
    int per  = SW * gx;
    int band = lin / per;
    int rem  = lin - band * per;
    int h    = gy - band * SW; if (h > SW) h = SW;
    mb = band * SW + rem % h;
    nb = rem / h;
}

// fused QKV projection: virtual N = 6144 (Q 4096 | K 1024 | V 1024)
__global__ __launch_bounds__(256, 1) void qkv_hmma(
    const __half* __restrict__ xh, const __half* __restrict__ xl,
    const __half* __restrict__ wqh,
    const __half* __restrict__ wkh,
    const __half* __restrict__ wvh,
    __half* __restrict__ qh, __half* __restrict__ ql,
    __half* __restrict__ kh, __half* __restrict__ kl,
    __half* __restrict__ vh, __half* __restrict__ vl)
{
    extern __shared__ char smraw[];
    const uint32_t sbase = smem_u32(smraw);
    int mb, nb;
    cta_map(gridDim.x, gridDim.y, mb, nb);
    const int m0 = mb * BM;

    const __half* Bh_;
    GemmOut o; o.C = nullptr; o.split = 1;
    int ncol;
    if (nb < 16)      { Bh_ = wqh; o.Ch = qh; o.Cl = ql; o.Nout = HIDDEN; ncol = nb * BN; }
    else if (nb < 20) { Bh_ = wkh; o.Ch = kh; o.Cl = kl; o.Nout = KVDIM;  ncol = (nb - 16) * BN; }
    else              { Bh_ = wvh; o.Ch = vh; o.Cl = vl; o.Nout = KVDIM;  ncol = (nb - 20) * BN; }

    gemm2_core(sbase, xh + (size_t)m0 * HIDDEN, xl + (size_t)m0 * HIDDEN,
               Bh_ + (size_t)ncol * HIDDEN, m0, ncol, HIDDEN, o);
}

// output GEMM (fp32 out): A = AO hi/lo, B = Wo hi
__global__ __launch_bounds__(256, 1) void gemm_hmma2(
    const __half* __restrict__ Ah, const __half* __restrict__ Al,
    const __half* __restrict__ Bh,
    float* __restrict__ C, int N, int K)
{
    extern __shared__ char smraw[];
    const uint32_t sbase = smem_u32(smraw);
    int mb, nb;
    cta_map(gridDim.x, gridDim.y, mb, nb);
    const int m0 = mb * BM, n0 = nb * BN;
    GemmOut o; o.C = C; o.Ch = nullptr; o.Cl = nullptr; o.Nout = N; o.split = 0;
    gemm2_core(sbase, Ah + (size_t)m0 * K, Al + (size_t)m0 * K,
               Bh + (size_t)n0 * K, m0, n0, K, o);
}

// ======================= V transpose (halves) ===============================
__global__ __launch_bounds__(256) void transpose_v(
    const __half* __restrict__ vh, const __half* __restrict__ vl,
    __half* __restrict__ vth, __half* __restrict__ vtl)
{
    __shared__ __half th[32][33], tl[32][33];
    const int b  = blockIdx.z;
    const int k0 = blockIdx.y * 32;
    const int s0 = blockIdx.x * 32;
    const int tx = threadIdx.x & 31;
    const int ty = threadIdx.x >> 5;
#pragma unroll
    for (int i = 0; i < 4; i++) {
        int row = ty + i * 8;
        size_t src = (size_t)(b * SEQ + s0 + row) * KVDIM + k0 + tx;
        th[row][tx] = vh[src];
        tl[row][tx] = vl[src];
    }
    __syncthreads();
#pragma unroll
    for (int i = 0; i < 4; i++) {
        int row = ty + i * 8;
        size_t dst = ((size_t)b * KVDIM + k0 + row) * SEQ + s0 + tx;
        vth[dst] = th[tx][row];
        vtl[dst] = tl[tx][row];
    }
}

// ======================= HMMA flash attention (3-term) ======================
#define QROWB 272
#define KROWB 272
#define VROWB 144
#define SQ_L      34816
#define SKV_BASE  69632
#define SKV_STRIDE 71680
#define OFF_KH 0
#define OFF_KL 17408
#define OFF_VTH 34816
#define OFF_VTL 53248
#define FLASH_SMEM 212992

__global__ __launch_bounds__(256, 1) void flash_hmma(
    const __half* __restrict__ qh, const __half* __restrict__ ql,
    const __half* __restrict__ kh, const __half* __restrict__ kl,
    const __half* __restrict__ vth, const __half* __restrict__ vtl,
    __half* __restrict__ aoh, __half* __restrict__ aol)
{
    extern __shared__ char smraw[];
    const uint32_t sb = smem_u32(smraw);
    const int tid = threadIdx.x, wid = tid >> 5, lane = tid & 31;
    const int qb = (int)(gridDim.x - 1 - blockIdx.x);
    const int hq = blockIdx.y, b = blockIdx.z;
    const int kvh = hq >> 2;
    const int qrow0 = qb * 128;
    const int g = lane >> 2, tig = lane & 3;
    const float scale = 0.08838834764831845f;

    const __half* qhg = qh + (size_t)(b * SEQ + qrow0) * HIDDEN + hq * HD;
    const __half* qlg = ql + (size_t)(b * SEQ + qrow0) * HIDDEN + hq * HD;
#pragma unroll
    for (int t = 0; t < 8; t++) {
        int idx = tid + t * 256;
        int r = idx >> 4, c = idx & 15;
        uint32_t d = (uint32_t)(r * QROWB + c * 16);
        size_t s = (size_t)r * HIDDEN + c * 8;
        cp16(sb + d, qhg + s);
        cp16(sb + SQ_L + d, qlg + s);
    }
    cp_commit();

    const __half* khg = kh + (size_t)(b * SEQ) * KVDIM + kvh * HD;
    const __half* klg = kl + (size_t)(b * SEQ) * KVDIM + kvh * HD;
    const __half* vthg = vth + ((size_t)b * KVDIM + kvh * HD) * SEQ;
    const __half* vtlg = vtl + ((size_t)b * KVDIM + kvh * HD) * SEQ;

    auto load_kv = [&](int stage, int j) {
        uint32_t base = sb + SKV_BASE + stage * SKV_STRIDE;
        int c0 = j * 64;
#pragma unroll
        for (int t = 0; t < 4; t++) {
            int idx = tid + t * 256;
            int r = idx >> 4, c = idx & 15;
            uint32_t d = (uint32_t)(r * KROWB + c * 16);
            size_t s = (size_t)(c0 + r) * KVDIM + c * 8;
            cp16(base + OFF_KH + d, khg + s);
            cp16(base + OFF_KL + d, klg + s);
        }
#pragma unroll
        for (int t = 0; t < 4; t++) {
            int idx = tid + t * 256;
            int r = idx >> 3, c = idx & 7;
            uint32_t d = (uint32_t)(r * VROWB + c * 16);
            size_t s = (size_t)r * SEQ + c0 + c * 8;
            cp16(base + OFF_VTH + d, vthg + s);
            cp16(base + OFF_VTL + d, vtlg + s);
        }
    };

    const int nb = 2 * qb + 2;
    load_kv(0, 0);
    cp_commit();

    float oacc[16][4];
#pragma unroll
    for (int i = 0; i < 16; i++)
#pragma unroll
        for (int t = 0; t < 4; t++) oacc[i][t] = 0.f;
    float m0 = -1e30f, m1 = -1e30f, l0 = 0.f, l1 = 0.f;

    const int aRow = lane & 15;
    const int aKof = (lane >> 4) * 16;
    const int bRow = (lane & 7) + ((lane & 16) ? 8 : 0);
    const int bKof = (lane & 8) ? 16 : 0;

    const int rg0 = qrow0 + 16 * wid + g;
    const int rg1 = rg0 + 8;

    for (int j = 0; j < nb; j++) {
        const int buf = j & 1;
        if (j + 1 < nb) {
            load_kv(1 - buf, j + 1);
            cp_commit();
            cp_wait<1>();
        } else {
            cp_wait<0>();
        }
        __syncthreads();

        const uint32_t kbase = sb + SKV_BASE + buf * SKV_STRIDE;

        float sacc[8][4];
#pragma unroll
        for (int i = 0; i < 8; i++)
#pragma unroll
            for (int t = 0; t < 4; t++) sacc[i][t] = 0.f;

#pragma unroll
        for (int kd = 0; kd < 8; kd++) {
            uint32_t aa = (uint32_t)((16 * wid + aRow) * QROWB + kd * 32 + aKof);
            uint32_t ah[4], al[4];
            ldm_x4(ah, sb + aa);
            ldm_x4(al, sb + SQ_L + aa);
            uint32_t bh[4][4], bl[4][4];
#pragma unroll
            for (int np = 0; np < 4; np++) {
                uint32_t ba = (uint32_t)((np * 16 + bRow) * KROWB + kd * 32 + bKof);
                ldm_x4(bh[np], kbase + OFF_KH + ba);
                ldm_x4(bl[np], kbase + OFF_KL + ba);
            }
#pragma unroll
            for (int ni = 0; ni < 8; ni++) {
                uint32_t b0h = bh[ni >> 1][(ni & 1) * 2], b1h = bh[ni >> 1][(ni & 1) * 2 + 1];
                mma16816(sacc[ni], ah, b0h, b1h);
            }
#pragma unroll
            for (int ni = 0; ni < 8; ni++) {
                uint32_t b0l = bl[ni >> 1][(ni & 1) * 2], b1l = bl[ni >> 1][(ni & 1) * 2 + 1];
                mma16816(sacc[ni], ah, b0l, b1l);
            }
#pragma unroll
            for (int ni = 0; ni < 8; ni++) {
                uint32_t b0h = bh[ni >> 1][(ni & 1) * 2], b1h = bh[ni >> 1][(ni & 1) * 2 + 1];
                mma16816(sacc[ni], al, b0h, b1h);
            }
        }

        const int c0 = j * 64;
#pragma unroll
        for (int ni = 0; ni < 8; ni++)
#pragma unroll
            for (int t = 0; t < 4; t++) sacc[ni][t] *= scale;
        if (j >= 2 * qb) {
#pragma unroll
            for (int ni = 0; ni < 8; ni++) {
                int cg = c0 + ni * 8 + 2 * tig;
                if (cg     > rg0) sacc[ni][0] = -1e30f;
                if (cg + 1 > rg0) sacc[ni][1] = -1e30f;
                if (cg     > rg1) sacc[ni][2] = -1e30f;
                if (cg + 1 > rg1) sacc[ni][3] = -1e30f;
            }
        }

        float vm0 = -1e30f, vm1 = -1e30f;
#pragma unroll
        for (int ni = 0; ni < 8; ni++) {
            vm0 = fmaxf(vm0, fmaxf(sacc[ni][0], sacc[ni][1]));
            vm1 = fmaxf(vm1, fmaxf(sacc[ni][2], sacc[ni][3]));
        }
        vm0 = fmaxf(vm0, __shfl_xor_sync(0xffffffffu, vm0, 1));
        vm0 = fmaxf(vm0, __shfl_xor_sync(0xffffffffu, vm0, 2));
        vm1 = fmaxf(vm1, __shfl_xor_sync(0xffffffffu, vm1, 1));
        vm1 = fmaxf(vm1, __shfl_xor_sync(0xffffffffu, vm1, 2));
        float mn0 = fmaxf(m0, vm0), mn1 = fmaxf(m1, vm1);
        float al0 = __expf(m0 - mn0), al1 = __expf(m1 - mn1);
        float sum0 = 0.f, sum1 = 0.f;
#pragma unroll
        for (int ni = 0; ni < 8; ni++) {
            sacc[ni][0] = __expf(sacc[ni][0] - mn0);
            sacc[ni][1] = __expf(sacc[ni][1] - mn0);
            sacc[ni][2] = __expf(sacc[ni][2] - mn1);
            sacc[ni][3] = __expf(sacc[ni][3] - mn1);
            sum0 += sacc[ni][0] + sacc[ni][1];
            sum1 += sacc[ni][2] + sacc[ni][3];
        }
        sum0 += __shfl_xor_sync(0xffffffffu, sum0, 1);
        sum0 += __shfl_xor_sync(0xffffffffu, sum0, 2);
        sum1 += __shfl_xor_sync(0xffffffffu, sum1, 1);
        sum1 += __shfl_xor_sync(0xffffffffu, sum1, 2);
        l0 = l0 * al0 + sum0;  l1 = l1 * al1 + sum1;
        m0 = mn0;  m1 = mn1;

#pragma unroll
        for (int nd = 0; nd < 16; nd++) {
            oacc[nd][0] *= al0;  oacc[nd][1] *= al0;
            oacc[nd][2] *= al1;  oacc[nd][3] *= al1;
        }

        uint32_t pah[4][4], pal[4][4];
#pragma unroll
        for (int t = 0; t < 4; t++) {
            float p00 = sacc[2 * t][0],     p01 = sacc[2 * t][1];
            float p10 = sacc[2 * t][2],     p11 = sacc[2 * t][3];
            float p20 = sacc[2 * t + 1][0], p21 = sacc[2 * t + 1][1];
            float p30 = sacc[2 * t + 1][2], p31 = sacc[2 * t + 1][3];
            __half h00 = __float2half_rn(p00), h01 = __float2half_rn(p01);
            __half h10 = __float2half_rn(p10), h11 = __float2half_rn(p11);
            __half h20 = __float2half_rn(p20), h21 = __float2half_rn(p21);
            __half h30 = __float2half_rn(p30), h31 = __float2half_rn(p31);
            pah[t][0] = pack_h2(h00, h01);
            pah[t][1] = pack_h2(h10, h11);
            pah[t][2] = pack_h2(h20, h21);
            pah[t][3] = pack_h2(h30, h31);
            pal[t][0] = pack_h2(__float2half_rn(p00 - __half2float(h00)),
                                __float2half_rn(p01 - __half2float(h01)));
            pal[t][1] = pack_h2(__float2half_rn(p10 - __half2float(h10)),
                                __float2half_rn(p11 - __half2float(h11)));
            pal[t][2] = pack_h2(__float2half_rn(p20 - __half2float(h20)),
                                __float2half_rn(p21 - __half2float(h21)));
            pal[t][3] = pack_h2(__float2half_rn(p30 - __half2float(h30)),
                                __float2half_rn(p31 - __half2float(h31)));
        }

#pragma unroll
        for (int t = 0; t < 4; t++) {
#pragma unroll
            for (int np = 0; np < 8; np++) {
                uint32_t ba = (uint32_t)((np * 16 + bRow) * VROWB + t * 32 + bKof);
                uint32_t vbh[4], vbl[4];
                ldm_x4(vbh, kbase + OFF_VTH + ba);
                ldm_x4(vbl, kbase + OFF_VTL + ba);
#pragma unroll
                for (int q = 0; q < 2; q++) {
                    int nd = np * 2 + q;
                    uint32_t b0h = vbh[q * 2], b1h = vbh[q * 2 + 1];
                    uint32_t b0l = vbl[q * 2], b1l = vbl[q * 2 + 1];
                    mma16816(oacc[nd], pah[t], b0h, b1h);
                    mma16816(oacc[nd], pah[t], b0l, b1l);
                    mma16816(oacc[nd], pal[t], b0h, b1h);
                }
            }
        }
        __syncthreads();
    }

    float inv0 = 1.f / l0, inv1 = 1.f / l1;
    size_t row0 = (size_t)(b * SEQ + qrow0 + 16 * wid + g) * HIDDEN + hq * HD;
    size_t row1 = row0 + (size_t)8 * HIDDEN;
#pragma unroll
    for (int nd = 0; nd < 16; nd++) {
        int col = nd * 8 + 2 * tig;
        float v0 = oacc[nd][0] * inv0, v1 = oacc[nd][1] * inv0;
        float v2 = oacc[nd][2] * inv1, v3 = oacc[nd][3] * inv1;
        __half h0 = __float2half_rn(v0), h1 = __float2half_rn(v1);
        __half h2 = __float2half_rn(v2), h3 = __float2half_rn(v3);
        *(uint32_t*)(aoh + row0 + col) = pack_h2(h0, h1);
        *(uint32_t*)(aoh + row1 + col) = pack_h2(h2, h3);
        *(uint32_t*)(aol + row0 + col) = pack_h2(
            __float2half_rn(v0 - __half2float(h0)),
            __float2half_rn(v1 - __half2float(h1)));
        *(uint32_t*)(aol + row1 + col) = pack_h2(
            __float2half_rn(v2 - __half2float(h2)),
            __float2half_rn(v3 - __half2float(h3)));
    }
}

// ============================================================================
extern "C" void kernel_launch(void* const* d_in, const int* in_sizes, int n_in,
                              void* d_out, int out_size)
{
    const float* x  = (const float*)d_in[0];
    const float* Wq = (const float*)d_in[1];
    const float* Wk = (const float*)d_in[2];
    const float* Wv = (const float*)d_in[3];
    const float* Wo = (const float*)d_in[4];
    float* out = (float*)d_out;

    __half *xh, *xl, *wqh, *wkh, *wvh, *woh;
    __half *qh, *ql, *kh, *kl, *vh, *vl, *vth, *vtl, *aoh, *aol;
    cudaGetSymbolAddress((void**)&xh,  g_xh);  cudaGetSymbolAddress((void**)&xl,  g_xl);
    cudaGetSymbolAddress((void**)&wqh, g_wqh);
    cudaGetSymbolAddress((void**)&wkh, g_wkh);
    cudaGetSymbolAddress((void**)&wvh, g_wvh);
    cudaGetSymbolAddress((void**)&woh, g_woh);
    cudaGetSymbolAddress((void**)&qh,  g_qh);  cudaGetSymbolAddress((void**)&ql,  g_ql);
    cudaGetSymbolAddress((void**)&kh,  g_kh);  cudaGetSymbolAddress((void**)&kl,  g_kl);
    cudaGetSymbolAddress((void**)&vh,  g_vh);  cudaGetSymbolAddress((void**)&vl,  g_vl);
    cudaGetSymbolAddress((void**)&vth, g_vth); cudaGetSymbolAddress((void**)&vtl, g_vtl);
    cudaGetSymbolAddress((void**)&aoh, g_aoh); cudaGetSymbolAddress((void**)&aol, g_aol);

    cudaFuncSetAttribute(qkv_hmma,   cudaFuncAttributeMaxDynamicSharedMemorySize, GEMM_SMEM);
    cudaFuncSetAttribute(gemm_hmma2, cudaFuncAttributeMaxDynamicSharedMemorySize, GEMM_SMEM);
    cudaFuncSetAttribute(flash_hmma, cudaFuncAttributeMaxDynamicSharedMemorySize, FLASH_SMEM);

    const int XN4 = TOKENS * HIDDEN / 4;
    const int WN4 = HIDDEN * HIDDEN / 4;
    const int KN4 = KVDIM * HIDDEN / 4;

    split_f32<<<(XN4 + 255) / 256, 256>>>((const float4*)x,  (__half2*)xh,  (__half2*)xl, XN4);
    split_f32<<<(WN4 + 255) / 256, 256>>>((const float4*)Wq, (__half2*)wqh, nullptr, WN4);
    split_f32<<<(KN4 + 255) / 256, 256>>>((const float4*)Wk, (__half2*)wkh, nullptr, KN4);
    split_f32<<<(KN4 + 255) / 256, 256>>>((const float4*)Wv, (__half2*)wvh, nullptr, KN4);
    split_f32<<<(WN4 + 255) / 256, 256>>>((const float4*)Wo, (__half2*)woh, nullptr, WN4);

    qkv_hmma<<<dim3(6144 / BN, TOKENS / BM), 256, GEMM_SMEM>>>(
        xh, xl, wqh, wkh, wvh, qh, ql, kh, kl, vh, vl);

    transpose_v<<<dim3(SEQ / 32, KVDIM / 32, BATCH), 256>>>(vh, vl, vth, vtl);

    flash_hmma<<<dim3(SEQ / 128, NH, BATCH), 256, FLASH_SMEM>>>(
        qh, ql, kh, kl, vth, vtl, aoh, aol);

    gemm_hmma2<<<dim3(HIDDEN / BN, TOKENS / BM), 256, GEMM_SMEM>>>(
        aoh, aol, woh, out, HIDDEN, HIDDEN);
}

// round 9
// speedup vs baseline: 4.7490x; 1.0752x over previous
#include <cuda_runtime.h>
#include <cuda_fp16.h>
#include <cstdint>
#include <math.h>

#define HIDDEN   4096
#define NKV      8
#define NH       32
#define HD       128
#define BATCH    2
#define SEQ      2048
#define TOKENS   (BATCH*SEQ)   // 4096
#define KVDIM    (NKV*HD)      // 1024

// ---------------- scratch (device globals; no runtime allocation) ----------
__device__ __half g_xh [TOKENS*HIDDEN], g_xl [TOKENS*HIDDEN];
__device__ __half g_wqh[HIDDEN*HIDDEN];
__device__ __half g_wkh[KVDIM*HIDDEN];
__device__ __half g_wvh[KVDIM*HIDDEN];
__device__ __half g_woh[HIDDEN*HIDDEN];
__device__ __half g_qh [TOKENS*HIDDEN];
__device__ __half g_kh [TOKENS*KVDIM],  g_kl [TOKENS*KVDIM];
__device__ __half g_vh [TOKENS*KVDIM],  g_vl [TOKENS*KVDIM];
__device__ __half g_vth[TOKENS*KVDIM],  g_vtl[TOKENS*KVDIM];  // [B][KVDIM][SEQ]
__device__ __half g_aoh[TOKENS*HIDDEN], g_aol[TOKENS*HIDDEN];

// ======================= helpers ============================================
__device__ __forceinline__ uint32_t smem_u32(const void* p) {
    uint32_t a;
    asm("{ .reg .u64 t; cvta.to.shared.u64 t, %1; cvt.u32.u64 %0, t; }"
        : "=r"(a) : "l"(p));
    return a;
}
__device__ __forceinline__ void cp16(uint32_t dst, const void* src) {
    asm volatile("cp.async.cg.shared.global [%0], [%1], 16;" :: "r"(dst), "l"(src));
}
__device__ __forceinline__ void cp_commit() { asm volatile("cp.async.commit_group;" ::: "memory"); }
template<int N> __device__ __forceinline__ void cp_wait() {
    asm volatile("cp.async.wait_group %0;" :: "n"(N) : "memory");
}
__device__ __forceinline__ void ldm_x4(uint32_t* r, uint32_t addr) {
    asm volatile("ldmatrix.sync.aligned.m8n8.x4.shared.b16 {%0,%1,%2,%3}, [%4];"
        : "=r"(r[0]), "=r"(r[1]), "=r"(r[2]), "=r"(r[3]) : "r"(addr));
}
__device__ __forceinline__ void mma16816(float* d, const uint32_t* a,
                                         uint32_t b0, uint32_t b1) {
    asm volatile(
        "mma.sync.aligned.m16n8k16.row.col.f32.f16.f16.f32 "
        "{%0,%1,%2,%3}, {%4,%5,%6,%7}, {%8,%9}, {%0,%1,%2,%3};"
        : "+f"(d[0]), "+f"(d[1]), "+f"(d[2]), "+f"(d[3])
        : "r"(a[0]), "r"(a[1]), "r"(a[2]), "r"(a[3]), "r"(b0), "r"(b1));
}
__device__ __forceinline__ uint32_t pack_h2(__half a, __half b) {
    __half2 h = __halves2half2(a, b);
    return *(uint32_t*)&h;
}

// ======================= split fp32 -> fp16 hi/lo ==========================
__global__ __launch_bounds__(256) void split_f32(
    const float4* __restrict__ x, __half2* __restrict__ hi,
    __half2* __restrict__ lo, int n4)
{
    int i = blockIdx.x * blockDim.x + threadIdx.x;
    if (i >= n4) return;
    float4 v = x[i];
    __half h0 = __float2half_rn(v.x), h1 = __float2half_rn(v.y);
    __half h2 = __float2half_rn(v.z), h3 = __float2half_rn(v.w);
    hi[2 * i]     = __halves2half2(h0, h1);
    hi[2 * i + 1] = __halves2half2(h2, h3);
    if (lo) {
        lo[2 * i] = __halves2half2(__float2half_rn(v.x - __half2float(h0)),
                                   __float2half_rn(v.y - __half2float(h1)));
        lo[2 * i + 1] = __halves2half2(__float2half_rn(v.z - __half2float(h2)),
                                       __float2half_rn(v.w - __half2float(h3)));
    }
}

// ======================= HMMA GEMM core (A-split, 2-term) ===================
// C = A @ B^T with A hi/lo (activations), B hi only (weights).
// Tile 128x256xBK64, 8 warps, warp tile 64x64, 3-stage cp.async.
#define BM 128
#define BN 256
#define BK 64
#define ROWB 144                       // 128B data + 16B pad, conflict-free
#define A_ST (BM*ROWB)                 // 18432
#define B_ST (BN*ROWB)                 // 36864
#define STAGE_B (2*A_ST + B_ST)        // 73728
#define NSTAGE 3
#define GEMM_SMEM (NSTAGE*STAGE_B)     // 221184

struct GemmOut {
    float* C;
    __half* Ch;
    __half* Cl;
    int Nout;
    int split;   // 0 = fp32, 1 = fp16 hi+lo, 2 = fp16 hi only
};

__device__ __forceinline__ void gemm2_core(
    uint32_t sbase, const __half* A0h, const __half* A0l, const __half* B0h,
    int m0, int ncol0, int K, const GemmOut& o)
{
    const int tid  = threadIdx.x;
    const int wid  = tid >> 5;
    const int lane = tid & 31;
    const int wm   = wid & 1;
    const int wn   = wid >> 1;

    auto bAh = [&](int s) { return sbase + s * STAGE_B; };
    auto bAl = [&](int s) { return sbase + s * STAGE_B + A_ST; };
    auto bB  = [&](int s) { return sbase + s * STAGE_B + 2 * A_ST; };

    auto load_stage = [&](int s, int k0) {
#pragma unroll
        for (int t = 0; t < 4; t++) {
            int idx = tid + t * 256;
            int r = idx >> 3, c = idx & 7;
            uint32_t d = (uint32_t)(r * ROWB + c * 16);
            size_t so = (size_t)r * K + k0 + c * 8;
            cp16(bAh(s) + d, A0h + so);
            cp16(bAl(s) + d, A0l + so);
        }
#pragma unroll
        for (int t = 0; t < 8; t++) {
            int idx = tid + t * 256;
            int r = idx >> 3, c = idx & 7;
            uint32_t d = (uint32_t)(r * ROWB + c * 16);
            cp16(bB(s) + d, B0h + (size_t)r * K + k0 + c * 8);
        }
    };

    float acc[4][8][4];
#pragma unroll
    for (int i = 0; i < 4; i++)
#pragma unroll
        for (int j = 0; j < 8; j++)
#pragma unroll
            for (int t = 0; t < 4; t++) acc[i][j][t] = 0.f;

    const int aRow = lane & 15;
    const int aKof = (lane >> 4) * 16;
    const int bRow = (lane & 7) + ((lane & 16) ? 8 : 0);
    const int bKof = (lane & 8) ? 16 : 0;
    const int warpM = wm * 64;
    const int warpN = wn * 64;

    const int nst = K / BK;
    load_stage(0, 0);
    cp_commit();
    load_stage(1, BK);
    cp_commit();

    for (int s = 0; s < nst; s++) {
        const int buf = s % NSTAGE;
        if (s + 1 < nst) cp_wait<1>(); else cp_wait<0>();
        __syncthreads();

        const uint32_t sAh = bAh(buf), sAl = bAl(buf), sB = bB(buf);

#pragma unroll
        for (int ks = 0; ks < 4; ks++) {
            const int kb = ks * 32;
            uint32_t ah[4][4], al[4][4], bh[4][4];
#pragma unroll
            for (int mi = 0; mi < 4; mi++) {
                uint32_t ad = (uint32_t)((warpM + mi * 16 + aRow) * ROWB + kb + aKof);
                ldm_x4(ah[mi], sAh + ad);
                ldm_x4(al[mi], sAl + ad);
            }
#pragma unroll
            for (int np = 0; np < 4; np++) {
                uint32_t bd = (uint32_t)((warpN + np * 16 + bRow) * ROWB + kb + bKof);
                ldm_x4(bh[np], sB + bd);
            }
#pragma unroll
            for (int np = 0; np < 4; np++)
#pragma unroll
                for (int q = 0; q < 2; q++) {
                    const int ni = np * 2 + q;
                    const uint32_t b0 = bh[np][q * 2], b1 = bh[np][q * 2 + 1];
#pragma unroll
                    for (int mi = 0; mi < 4; mi++)
                        mma16816(acc[mi][ni], ah[mi], b0, b1);
                }
#pragma unroll
            for (int np = 0; np < 4; np++)
#pragma unroll
                for (int q = 0; q < 2; q++) {
                    const int ni = np * 2 + q;
                    const uint32_t b0 = bh[np][q * 2], b1 = bh[np][q * 2 + 1];
#pragma unroll
                    for (int mi = 0; mi < 4; mi++)
                        mma16816(acc[mi][ni], al[mi], b0, b1);
                }
        }

        if (s + 2 < nst) {
            load_stage((s + 2) % NSTAGE, (s + 2) * BK);
            cp_commit();
        }
    }

    const int er = lane >> 2;
    const int ec = (lane & 3) * 2;
    if (o.split == 0) {
#pragma unroll
        for (int mi = 0; mi < 4; mi++)
#pragma unroll
            for (int ni = 0; ni < 8; ni++) {
                float* p = o.C + (size_t)(m0 + warpM + mi * 16 + er) * o.Nout
                               + (ncol0 + warpN + ni * 8 + ec);
                p[0] = acc[mi][ni][0];
                p[1] = acc[mi][ni][1];
                float* q = p + (size_t)8 * o.Nout;
                q[0] = acc[mi][ni][2];
                q[1] = acc[mi][ni][3];
            }
    } else if (o.split == 2) {
#pragma unroll
        for (int mi = 0; mi < 4; mi++)
#pragma unroll
            for (int ni = 0; ni < 8; ni++) {
                size_t off0 = (size_t)(m0 + warpM + mi * 16 + er) * o.Nout
                            + (ncol0 + warpN + ni * 8 + ec);
                size_t off1 = off0 + (size_t)8 * o.Nout;
                *(uint32_t*)(o.Ch + off0) = pack_h2(
                    __float2half_rn(acc[mi][ni][0]), __float2half_rn(acc[mi][ni][1]));
                *(uint32_t*)(o.Ch + off1) = pack_h2(
                    __float2half_rn(acc[mi][ni][2]), __float2half_rn(acc[mi][ni][3]));
            }
    } else {
#pragma unroll
        for (int mi = 0; mi < 4; mi++)
#pragma unroll
            for (int ni = 0; ni < 8; ni++) {
                size_t off0 = (size_t)(m0 + warpM + mi * 16 + er) * o.Nout
                            + (ncol0 + warpN + ni * 8 + ec);
                size_t off1 = off0 + (size_t)8 * o.Nout;
                float v0 = acc[mi][ni][0], v1 = acc[mi][ni][1];
                float v2 = acc[mi][ni][2], v3 = acc[mi][ni][3];
                __half h0 = __float2half_rn(v0), h1 = __float2half_rn(v1);
                __half h2 = __float2half_rn(v2), h3 = __float2half_rn(v3);
                *(uint32_t*)(o.Ch + off0) = pack_h2(h0, h1);
                *(uint32_t*)(o.Ch + off1) = pack_h2(h2, h3);
                *(uint32_t*)(o.Cl + off0) = pack_h2(
                    __float2half_rn(v0 - __half2float(h0)),
                    __float2half_rn(v1 - __half2float(h1)));
                *(uint32_t*)(o.Cl + off1) = pack_h2(
                    __float2half_rn(v2 - __half2float(h2)),
                    __float2half_rn(v3 - __half2float(h3)));
            }
    }
}

// swizzled block mapping (supertiles of 8 m-blocks)
__device__ __forceinline__ void cta_map(int gx, int gy, int& mb, int& nb) {
    int lin = blockIdx.y * gx + blockIdx.x;
    const int SW = 8;
    int per  = SW * gx;
    int band = lin / per;
    int rem  = lin - band * per;
    int h    = gy - band * SW; if (h > SW) h = SW;
    mb = band * SW + rem % h;
    nb = rem / h;
}

// fused QKV projection: virtual N = 6144 (Q 4096 | K 1024 | V 1024)
__global__ __launch_bounds__(256, 1) void qkv_hmma(
    const __half* __restrict__ xh, const __half* __restrict__ xl,
    const __half* __restrict__ wqh,
    const __half* __restrict__ wkh,
    const __half* __restrict__ wvh,
    __half* __restrict__ qh,
    __half* __restrict__ kh, __half* __restrict__ kl,
    __half* __restrict__ vh, __half* __restrict__ vl)
{
    extern __shared__ char smraw[];
    const uint32_t sbase = smem_u32(smraw);
    int mb, nb;
    cta_map(gridDim.x, gridDim.y, mb, nb);
    const int m0 = mb * BM;

    const __half* Bh_;
    GemmOut o; o.C = nullptr;
    int ncol;
    if (nb < 16)      { Bh_ = wqh; o.Ch = qh; o.Cl = nullptr; o.split = 2; o.Nout = HIDDEN; ncol = nb * BN; }
    else if (nb < 20) { Bh_ = wkh; o.Ch = kh; o.Cl = kl; o.split = 1; o.Nout = KVDIM; ncol = (nb - 16) * BN; }
    else              { Bh_ = wvh; o.Ch = vh; o.Cl = vl; o.split = 1; o.Nout = KVDIM; ncol = (nb - 20) * BN; }

    gemm2_core(sbase, xh + (size_t)m0 * HIDDEN, xl + (size_t)m0 * HIDDEN,
               Bh_ + (size_t)ncol * HIDDEN, m0, ncol, HIDDEN, o);
}

// output GEMM (fp32 out): A = AO hi/lo, B = Wo hi
__global__ __launch_bounds__(256, 1) void gemm_hmma2(
    const __half* __restrict__ Ah, const __half* __restrict__ Al,
    const __half* __restrict__ Bh,
    float* __restrict__ C, int N, int K)
{
    extern __shared__ char smraw[];
    const uint32_t sbase = smem_u32(smraw);
    int mb, nb;
    cta_map(gridDim.x, gridDim.y, mb, nb);
    const int m0 = mb * BM, n0 = nb * BN;
    GemmOut o; o.C = C; o.Ch = nullptr; o.Cl = nullptr; o.Nout = N; o.split = 0;
    gemm2_core(sbase, Ah + (size_t)m0 * K, Al + (size_t)m0 * K,
               Bh + (size_t)n0 * K, m0, n0, K, o);
}

// ======================= V transpose (halves) ===============================
__global__ __launch_bounds__(256) void transpose_v(
    const __half* __restrict__ vh, const __half* __restrict__ vl,
    __half* __restrict__ vth, __half* __restrict__ vtl)
{
    __shared__ __half th[32][33], tl[32][33];
    const int b  = blockIdx.z;
    const int k0 = blockIdx.y * 32;
    const int s0 = blockIdx.x * 32;
    const int tx = threadIdx.x & 31;
    const int ty = threadIdx.x >> 5;
#pragma unroll
    for (int i = 0; i < 4; i++) {
        int row = ty + i * 8;
        size_t src = (size_t)(b * SEQ + s0 + row) * KVDIM + k0 + tx;
        th[row][tx] = vh[src];
        tl[row][tx] = vl[src];
    }
    __syncthreads();
#pragma unroll
    for (int i = 0; i < 4; i++) {
        int row = ty + i * 8;
        size_t dst = ((size_t)b * KVDIM + k0 + row) * SEQ + s0 + tx;
        vth[dst] = th[tx][row];
        vtl[dst] = tl[tx][row];
    }
}

// ======================= HMMA flash attention (trimmed split) ===============
// QK: Qh*Kh + Qh*Kl (Q hi-only).  PV: Ph*Vh + Ph*Vl.
#define QROWB 272
#define KROWB 272
#define VROWB 144
#define SKV_BASE  34816
#define SKV_STRIDE 71680
#define OFF_KH 0
#define OFF_KL 17408
#define OFF_VTH 34816
#define OFF_VTL 53248
#define FLASH_SMEM (SKV_BASE + 2*SKV_STRIDE)   // 178176

__global__ __launch_bounds__(256, 1) void flash_hmma(
    const __half* __restrict__ qh,
    const __half* __restrict__ kh, const __half* __restrict__ kl,
    const __half* __restrict__ vth, const __half* __restrict__ vtl,
    __half* __restrict__ aoh, __half* __restrict__ aol)
{
    extern __shared__ char smraw[];
    const uint32_t sb = smem_u32(smraw);
    const int tid = threadIdx.x, wid = tid >> 5, lane = tid & 31;
    const int qb = (int)(gridDim.x - 1 - blockIdx.x);
    const int hq = blockIdx.y, b = blockIdx.z;
    const int kvh = hq >> 2;
    const int qrow0 = qb * 128;
    const int g = lane >> 2, tig = lane & 3;
    const float scale = 0.08838834764831845f;

    const __half* qhg = qh + (size_t)(b * SEQ + qrow0) * HIDDEN + hq * HD;
#pragma unroll
    for (int t = 0; t < 8; t++) {
        int idx = tid + t * 256;
        int r = idx >> 4, c = idx & 15;
        cp16(sb + (uint32_t)(r * QROWB + c * 16), qhg + (size_t)r * HIDDEN + c * 8);
    }
    cp_commit();

    const __half* khg = kh + (size_t)(b * SEQ) * KVDIM + kvh * HD;
    const __half* klg = kl + (size_t)(b * SEQ) * KVDIM + kvh * HD;
    const __half* vthg = vth + ((size_t)b * KVDIM + kvh * HD) * SEQ;
    const __half* vtlg = vtl + ((size_t)b * KVDIM + kvh * HD) * SEQ;

    auto load_kv = [&](int stage, int j) {
        uint32_t base = sb + SKV_BASE + stage * SKV_STRIDE;
        int c0 = j * 64;
#pragma unroll
        for (int t = 0; t < 4; t++) {
            int idx = tid + t * 256;
            int r = idx >> 4, c = idx & 15;
            uint32_t d = (uint32_t)(r * KROWB + c * 16);
            size_t s = (size_t)(c0 + r) * KVDIM + c * 8;
            cp16(base + OFF_KH + d, khg + s);
            cp16(base + OFF_KL + d, klg + s);
        }
#pragma unroll
        for (int t = 0; t < 4; t++) {
            int idx = tid + t * 256;
            int r = idx >> 3, c = idx & 7;
            uint32_t d = (uint32_t)(r * VROWB + c * 16);
            size_t s = (size_t)r * SEQ + c0 + c * 8;
            cp16(base + OFF_VTH + d, vthg + s);
            cp16(base + OFF_VTL + d, vtlg + s);
        }
    };

    const int nb = 2 * qb + 2;
    load_kv(0, 0);
    cp_commit();

    float oacc[16][4];
#pragma unroll
    for (int i = 0; i < 16; i++)
#pragma unroll
        for (int t = 0; t < 4; t++) oacc[i][t] = 0.f;
    float m0 = -1e30f, m1 = -1e30f, l0 = 0.f, l1 = 0.f;

    const int aRow = lane & 15;
    const int aKof = (lane >> 4) * 16;
    const int bRow = (lane & 7) + ((lane & 16) ? 8 : 0);
    const int bKof = (lane & 8) ? 16 : 0;

    const int rg0 = qrow0 + 16 * wid + g;
    const int rg1 = rg0 + 8;

    for (int j = 0; j < nb; j++) {
        const int buf = j & 1;
        if (j + 1 < nb) {
            load_kv(1 - buf, j + 1);
            cp_commit();
            cp_wait<1>();
        } else {
            cp_wait<0>();
        }
        __syncthreads();

        const uint32_t kbase = sb + SKV_BASE + buf * SKV_STRIDE;

        float sacc[8][4];
#pragma unroll
        for (int i = 0; i < 8; i++)
#pragma unroll
            for (int t = 0; t < 4; t++) sacc[i][t] = 0.f;

#pragma unroll
        for (int kd = 0; kd < 8; kd++) {
            uint32_t aa = (uint32_t)((16 * wid + aRow) * QROWB + kd * 32 + aKof);
            uint32_t ah[4];
            ldm_x4(ah, sb + aa);
            uint32_t bh[4][4], bl[4][4];
#pragma unroll
            for (int np = 0; np < 4; np++) {
                uint32_t ba = (uint32_t)((np * 16 + bRow) * KROWB + kd * 32 + bKof);
                ldm_x4(bh[np], kbase + OFF_KH + ba);
                ldm_x4(bl[np], kbase + OFF_KL + ba);
            }
#pragma unroll
            for (int ni = 0; ni < 8; ni++) {
                uint32_t b0h = bh[ni >> 1][(ni & 1) * 2], b1h = bh[ni >> 1][(ni & 1) * 2 + 1];
                mma16816(sacc[ni], ah, b0h, b1h);
            }
#pragma unroll
            for (int ni = 0; ni < 8; ni++) {
                uint32_t b0l = bl[ni >> 1][(ni & 1) * 2], b1l = bl[ni >> 1][(ni & 1) * 2 + 1];
                mma16816(sacc[ni], ah, b0l, b1l);
            }
        }

        const int c0 = j * 64;
#pragma unroll
        for (int ni = 0; ni < 8; ni++)
#pragma unroll
            for (int t = 0; t < 4; t++) sacc[ni][t] *= scale;
        if (j >= 2 * qb) {
#pragma unroll
            for (int ni = 0; ni < 8; ni++) {
                int cg = c0 + ni * 8 + 2 * tig;
                if (cg     > rg0) sacc[ni][0] = -1e30f;
                if (cg + 1 > rg0) sacc[ni][1] = -1e30f;
                if (cg     > rg1) sacc[ni][2] = -1e30f;
                if (cg + 1 > rg1) sacc[ni][3] = -1e30f;
            }
        }

        float vm0 = -1e30f, vm1 = -1e30f;
#pragma unroll
        for (int ni = 0; ni < 8; ni++) {
            vm0 = fmaxf(vm0, fmaxf(sacc[ni][0], sacc[ni][1]));
            vm1 = fmaxf(vm1, fmaxf(sacc[ni][2], sacc[ni][3]));
        }
        vm0 = fmaxf(vm0, __shfl_xor_sync(0xffffffffu, vm0, 1));
        vm0 = fmaxf(vm0, __shfl_xor_sync(0xffffffffu, vm0, 2));
        vm1 = fmaxf(vm1, __shfl_xor_sync(0xffffffffu, vm1, 1));
        vm1 = fmaxf(vm1, __shfl_xor_sync(0xffffffffu, vm1, 2));
        float mn0 = fmaxf(m0, vm0), mn1 = fmaxf(m1, vm1);
        float al0 = __expf(m0 - mn0), al1 = __expf(m1 - mn1);
        float sum0 = 0.f, sum1 = 0.f;
#pragma unroll
        for (int ni = 0; ni < 8; ni++) {
            sacc[ni][0] = __expf(sacc[ni][0] - mn0);
            sacc[ni][1] = __expf(sacc[ni][1] - mn0);
            sacc[ni][2] = __expf(sacc[ni][2] - mn1);
            sacc[ni][3] = __expf(sacc[ni][3] - mn1);
            sum0 += sacc[ni][0] + sacc[ni][1];
            sum1 += sacc[ni][2] + sacc[ni][3];
        }
        sum0 += __shfl_xor_sync(0xffffffffu, sum0, 1);
        sum0 += __shfl_xor_sync(0xffffffffu, sum0, 2);
        sum1 += __shfl_xor_sync(0xffffffffu, sum1, 1);
        sum1 += __shfl_xor_sync(0xffffffffu, sum1, 2);
        l0 = l0 * al0 + sum0;  l1 = l1 * al1 + sum1;
        m0 = mn0;  m1 = mn1;

#pragma unroll
        for (int nd = 0; nd < 16; nd++) {
            oacc[nd][0] *= al0;  oacc[nd][1] *= al0;
            oacc[nd][2] *= al1;  oacc[nd][3] *= al1;
        }

        // ---- P fragments (hi only; Pl*Vh term dropped) ----
        uint32_t pah[4][4];
#pragma unroll
        for (int t = 0; t < 4; t++) {
            pah[t][0] = pack_h2(__float2half_rn(sacc[2 * t][0]),
                                __float2half_rn(sacc[2 * t][1]));
            pah[t][1] = pack_h2(__float2half_rn(sacc[2 * t][2]),
                                __float2half_rn(sacc[2 * t][3]));
            pah[t][2] = pack_h2(__float2half_rn(sacc[2 * t + 1][0]),
                                __float2half_rn(sacc[2 * t + 1][1]));
            pah[t][3] = pack_h2(__float2half_rn(sacc[2 * t + 1][2]),
                                __float2half_rn(sacc[2 * t + 1][3]));
        }

#pragma unroll
        for (int t = 0; t < 4; t++) {
#pragma unroll
            for (int np = 0; np < 8; np++) {
                uint32_t ba = (uint32_t)((np * 16 + bRow) * VROWB + t * 32 + bKof);
                uint32_t vbh[4], vbl[4];
                ldm_x4(vbh, kbase + OFF_VTH + ba);
                ldm_x4(vbl, kbase + OFF_VTL + ba);
#pragma unroll
                for (int q = 0; q < 2; q++) {
                    int nd = np * 2 + q;
                    mma16816(oacc[nd], pah[t], vbh[q * 2], vbh[q * 2 + 1]);
                    mma16816(oacc[nd], pah[t], vbl[q * 2], vbl[q * 2 + 1]);
                }
            }
        }
        __syncthreads();
    }

    float inv0 = 1.f / l0, inv1 = 1.f / l1;
    size_t row0 = (size_t)(b * SEQ + qrow0 + 16 * wid + g) * HIDDEN + hq * HD;
    size_t row1 = row0 + (size_t)8 * HIDDEN;
#pragma unroll
    for (int nd = 0; nd < 16; nd++) {
        int col = nd * 8 + 2 * tig;
        float v0 = oacc[nd][0] * inv0, v1 = oacc[nd][1] * inv0;
        float v2 = oacc[nd][2] * inv1, v3 = oacc[nd][3] * inv1;
        __half h0 = __float2half_rn(v0), h1 = __float2half_rn(v1);
        __half h2 = __float2half_rn(v2), h3 = __float2half_rn(v3);
        *(uint32_t*)(aoh + row0 + col) = pack_h2(h0, h1);
        *(uint32_t*)(aoh + row1 + col) = pack_h2(h2, h3);
        *(uint32_t*)(aol + row0 + col) = pack_h2(
            __float2half_rn(v0 - __half2float(h0)),
            __float2half_rn(v1 - __half2float(h1)));
        *(uint32_t*)(aol + row1 + col) = pack_h2(
            __float2half_rn(v2 - __half2float(h2)),
            __float2half_rn(v3 - __half2float(h3)));
    }
}

// ============================================================================
extern "C" void kernel_launch(void* const* d_in, const int* in_sizes, int n_in,
                              void* d_out, int out_size)
{
    const float* x  = (const float*)d_in[0];
    const float* Wq = (const float*)d_in[1];
    const float* Wk = (const float*)d_in[2];
    const float* Wv = (const float*)d_in[3];
    const float* Wo = (const float*)d_in[4];
    float* out = (float*)d_out;

    __half *xh, *xl, *wqh, *wkh, *wvh, *woh;
    __half *qh, *kh, *kl, *vh, *vl, *vth, *vtl, *aoh, *aol;
    cudaGetSymbolAddress((void**)&xh,  g_xh);  cudaGetSymbolAddress((void**)&xl,  g_xl);
    cudaGetSymbolAddress((void**)&wqh, g_wqh);
    cudaGetSymbolAddress((void**)&wkh, g_wkh);
    cudaGetSymbolAddress((void**)&wvh, g_wvh);
    cudaGetSymbolAddress((void**)&woh, g_woh);
    cudaGetSymbolAddress((void**)&qh,  g_qh);
    cudaGetSymbolAddress((void**)&kh,  g_kh);  cudaGetSymbolAddress((void**)&kl,  g_kl);
    cudaGetSymbolAddress((void**)&vh,  g_vh);  cudaGetSymbolAddress((void**)&vl,  g_vl);
    cudaGetSymbolAddress((void**)&vth, g_vth); cudaGetSymbolAddress((void**)&vtl, g_vtl);
    cudaGetSymbolAddress((void**)&aoh, g_aoh); cudaGetSymbolAddress((void**)&aol, g_aol);

    cudaFuncSetAttribute(qkv_hmma,   cudaFuncAttributeMaxDynamicSharedMemorySize, GEMM_SMEM);
    cudaFuncSetAttribute(gemm_hmma2, cudaFuncAttributeMaxDynamicSharedMemorySize, GEMM_SMEM);
    cudaFuncSetAttribute(flash_hmma, cudaFuncAttributeMaxDynamicSharedMemorySize, FLASH_SMEM);

    const int XN4 = TOKENS * HIDDEN / 4;
    const int WN4 = HIDDEN * HIDDEN / 4;
    const int KN4 = KVDIM * HIDDEN / 4;

    split_f32<<<(XN4 + 255) / 256, 256>>>((const float4*)x,  (__half2*)xh,  (__half2*)xl, XN4);
    split_f32<<<(WN4 + 255) / 256, 256>>>((const float4*)Wq, (__half2*)wqh, nullptr, WN4);
    split_f32<<<(KN4 + 255) / 256, 256>>>((const float4*)Wk, (__half2*)wkh, nullptr, KN4);
    split_f32<<<(KN4 + 255) / 256, 256>>>((const float4*)Wv, (__half2*)wvh, nullptr, KN4);
    split_f32<<<(WN4 + 255) / 256, 256>>>((const float4*)Wo, (__half2*)woh, nullptr, WN4);

    qkv_hmma<<<dim3(6144 / BN, TOKENS / BM), 256, GEMM_SMEM>>>(
        xh, xl, wqh, wkh, wvh, qh, kh, kl, vh, vl);

    transpose_v<<<dim3(SEQ / 32, KVDIM / 32, BATCH), 256>>>(vh, vl, vth, vtl);

    flash_hmma<<<dim3(SEQ / 128, NH, BATCH), 256, FLASH_SMEM>>>(
        qh, kh, kl, vth, vtl, aoh, aol);

    gemm_hmma2<<<dim3(HIDDEN / BN, TOKENS / BM), 256, GEMM_SMEM>>>(
        aoh, aol, woh, out, HIDDEN, HIDDEN);
}

// round 10
// speedup vs baseline: 4.9808x; 1.0488x over previous
#include <cuda_runtime.h>
#include <cuda_fp16.h>
#include <cstdint>
#include <math.h>

#define HIDDEN   4096
#define NKV      8
#define NH       32
#define HD       128
#define BATCH    2
#define SEQ      2048
#define TOKENS   (BATCH*SEQ)   // 4096
#define KVDIM    (NKV*HD)      // 1024

// ---------------- scratch (device globals; no runtime allocation) ----------
__device__ __half g_xh [TOKENS*HIDDEN], g_xl [TOKENS*HIDDEN];
__device__ __half g_wqh[HIDDEN*HIDDEN];
__device__ __half g_wkh[KVDIM*HIDDEN];
__device__ __half g_wvh[KVDIM*HIDDEN];
__device__ __half g_woh[HIDDEN*HIDDEN];
__device__ __half g_qh [TOKENS*HIDDEN];
__device__ __half g_kh [TOKENS*KVDIM],  g_kl [TOKENS*KVDIM];
__device__ __half g_vh [TOKENS*KVDIM];
__device__ __half g_vth[TOKENS*KVDIM];                    // [B][KVDIM][SEQ]
__device__ __half g_aoh[TOKENS*HIDDEN], g_aol[TOKENS*HIDDEN];

// ======================= helpers ============================================
__device__ __forceinline__ uint32_t smem_u32(const void* p) {
    uint32_t a;
    asm("{ .reg .u64 t; cvta.to.shared.u64 t, %1; cvt.u32.u64 %0, t; }"
        : "=r"(a) : "l"(p));
    return a;
}
__device__ __forceinline__ void cp16(uint32_t dst, const void* src) {
    asm volatile("cp.async.cg.shared.global [%0], [%1], 16;" :: "r"(dst), "l"(src));
}
__device__ __forceinline__ void cp_commit() { asm volatile("cp.async.commit_group;" ::: "memory"); }
template<int N> __device__ __forceinline__ void cp_wait() {
    asm volatile("cp.async.wait_group %0;" :: "n"(N) : "memory");
}
__device__ __forceinline__ void ldm_x4(uint32_t* r, uint32_t addr) {
    asm volatile("ldmatrix.sync.aligned.m8n8.x4.shared.b16 {%0,%1,%2,%3}, [%4];"
        : "=r"(r[0]), "=r"(r[1]), "=r"(r[2]), "=r"(r[3]) : "r"(addr));
}
__device__ __forceinline__ void mma16816(float* d, const uint32_t* a,
                                         uint32_t b0, uint32_t b1) {
    asm volatile(
        "mma.sync.aligned.m16n8k16.row.col.f32.f16.f16.f32 "
        "{%0,%1,%2,%3}, {%4,%5,%6,%7}, {%8,%9}, {%0,%1,%2,%3};"
        : "+f"(d[0]), "+f"(d[1]), "+f"(d[2]), "+f"(d[3])
        : "r"(a[0]), "r"(a[1]), "r"(a[2]), "r"(a[3]), "r"(b0), "r"(b1));
}
__device__ __forceinline__ uint32_t pack_h2(__half a, __half b) {
    __half2 h = __halves2half2(a, b);
    return *(uint32_t*)&h;
}

// ======================= split fp32 -> fp16 (hi[/lo]) =======================
__global__ __launch_bounds__(256) void split_f32(
    const float4* __restrict__ x, __half2* __restrict__ hi,
    __half2* __restrict__ lo, int n4)
{
    int i = blockIdx.x * blockDim.x + threadIdx.x;
    if (i >= n4) return;
    float4 v = x[i];
    __half h0 = __float2half_rn(v.x), h1 = __float2half_rn(v.y);
    __half h2 = __float2half_rn(v.z), h3 = __float2half_rn(v.w);
    hi[2 * i]     = __halves2half2(h0, h1);
    hi[2 * i + 1] = __halves2half2(h2, h3);
    if (lo) {
        lo[2 * i] = __halves2half2(__float2half_rn(v.x - __half2float(h0)),
                                   __float2half_rn(v.y - __half2float(h1)));
        lo[2 * i + 1] = __halves2half2(__float2half_rn(v.z - __half2float(h2)),
                                       __float2half_rn(v.w - __half2float(h3)));
    }
}

// all 4 weights, hi-only, single launch
#define WN4 (HIDDEN*HIDDEN/4)
#define KN4 (KVDIM*HIDDEN/4)
__global__ __launch_bounds__(256) void split_w4(
    const float4* __restrict__ wq, const float4* __restrict__ wk,
    const float4* __restrict__ wv, const float4* __restrict__ wo,
    __half2* __restrict__ qo, __half2* __restrict__ ko,
    __half2* __restrict__ vo, __half2* __restrict__ oo)
{
    int i = blockIdx.x * blockDim.x + threadIdx.x;
    const float4* src;
    __half2* dst;
    int idx;
    if (i < WN4)                 { src = wq; dst = qo; idx = i; }
    else if (i < WN4 + KN4)      { src = wk; dst = ko; idx = i - WN4; }
    else if (i < WN4 + 2 * KN4)  { src = wv; dst = vo; idx = i - WN4 - KN4; }
    else if (i < 2 * WN4 + 2 * KN4) { src = wo; dst = oo; idx = i - WN4 - 2 * KN4; }
    else return;
    float4 v = src[idx];
    dst[2 * idx]     = __halves2half2(__float2half_rn(v.x), __float2half_rn(v.y));
    dst[2 * idx + 1] = __halves2half2(__float2half_rn(v.z), __float2half_rn(v.w));
}

// ======================= HMMA GEMM core (A-split, 2-term) ===================
#define BM 128
#define BN 256
#define BK 64
#define ROWB 144
#define A_ST (BM*ROWB)                 // 18432
#define B_ST (BN*ROWB)                 // 36864
#define STAGE_B (2*A_ST + B_ST)        // 73728
#define NSTAGE 3
#define GEMM_SMEM (NSTAGE*STAGE_B)     // 221184

struct GemmOut {
    float* C;
    __half* Ch;
    __half* Cl;
    int Nout;
    int split;   // 0 = fp32, 1 = fp16 hi+lo, 2 = fp16 hi only
};

__device__ __forceinline__ void gemm2_core(
    uint32_t sbase, const __half* A0h, const __half* A0l, const __half* B0h,
    int m0, int ncol0, int K, const GemmOut& o)
{
    const int tid  = threadIdx.x;
    const int wid  = tid >> 5;
    const int lane = tid & 31;
    const int wm   = wid & 1;
    const int wn   = wid >> 1;

    auto bAh = [&](int s) { return sbase + s * STAGE_B; };
    auto bAl = [&](int s) { return sbase + s * STAGE_B + A_ST; };
    auto bB  = [&](int s) { return sbase + s * STAGE_B + 2 * A_ST; };

    auto load_stage = [&](int s, int k0) {
#pragma unroll
        for (int t = 0; t < 4; t++) {
            int idx = tid + t * 256;
            int r = idx >> 3, c = idx & 7;
            uint32_t d = (uint32_t)(r * ROWB + c * 16);
            size_t so = (size_t)r * K + k0 + c * 8;
            cp16(bAh(s) + d, A0h + so);
            cp16(bAl(s) + d, A0l + so);
        }
#pragma unroll
        for (int t = 0; t < 8; t++) {
            int idx = tid + t * 256;
            int r = idx >> 3, c = idx & 7;
            uint32_t d = (uint32_t)(r * ROWB + c * 16);
            cp16(bB(s) + d, B0h + (size_t)r * K + k0 + c * 8);
        }
    };

    float acc[4][8][4];
#pragma unroll
    for (int i = 0; i < 4; i++)
#pragma unroll
        for (int j = 0; j < 8; j++)
#pragma unroll
            for (int t = 0; t < 4; t++) acc[i][j][t] = 0.f;

    const int aRow = lane & 15;
    const int aKof = (lane >> 4) * 16;
    const int bRow = (lane & 7) + ((lane & 16) ? 8 : 0);
    const int bKof = (lane & 8) ? 16 : 0;
    const int warpM = wm * 64;
    const int warpN = wn * 64;

    const int nst = K / BK;
    load_stage(0, 0);
    cp_commit();
    load_stage(1, BK);
    cp_commit();

    for (int s = 0; s < nst; s++) {
        const int buf = s % NSTAGE;
        if (s + 1 < nst) cp_wait<1>(); else cp_wait<0>();
        __syncthreads();

        const uint32_t sAh = bAh(buf), sAl = bAl(buf), sB = bB(buf);

#pragma unroll
        for (int ks = 0; ks < 4; ks++) {
            const int kb = ks * 32;
            uint32_t ah[4][4], al[4][4], bh[4][4];
#pragma unroll
            for (int mi = 0; mi < 4; mi++) {
                uint32_t ad = (uint32_t)((warpM + mi * 16 + aRow) * ROWB + kb + aKof);
                ldm_x4(ah[mi], sAh + ad);
                ldm_x4(al[mi], sAl + ad);
            }
#pragma unroll
            for (int np = 0; np < 4; np++) {
                uint32_t bd = (uint32_t)((warpN + np * 16 + bRow) * ROWB + kb + bKof);
                ldm_x4(bh[np], sB + bd);
            }
#pragma unroll
            for (int np = 0; np < 4; np++)
#pragma unroll
                for (int q = 0; q < 2; q++) {
                    const int ni = np * 2 + q;
                    const uint32_t b0 = bh[np][q * 2], b1 = bh[np][q * 2 + 1];
#pragma unroll
                    for (int mi = 0; mi < 4; mi++)
                        mma16816(acc[mi][ni], ah[mi], b0, b1);
                }
#pragma unroll
            for (int np = 0; np < 4; np++)
#pragma unroll
                for (int q = 0; q < 2; q++) {
                    const int ni = np * 2 + q;
                    const uint32_t b0 = bh[np][q * 2], b1 = bh[np][q * 2 + 1];
#pragma unroll
                    for (int mi = 0; mi < 4; mi++)
                        mma16816(acc[mi][ni], al[mi], b0, b1);
                }
        }

        if (s + 2 < nst) {
            load_stage((s + 2) % NSTAGE, (s + 2) * BK);
            cp_commit();
        }
    }

    const int er = lane >> 2;
    const int ec = (lane & 3) * 2;
    if (o.split == 0) {
#pragma unroll
        for (int mi = 0; mi < 4; mi++)
#pragma unroll
            for (int ni = 0; ni < 8; ni++) {
                float* p = o.C + (size_t)(m0 + warpM + mi * 16 + er) * o.Nout
                               + (ncol0 + warpN + ni * 8 + ec);
                p[0] = acc[mi][ni][0];
                p[1] = acc[mi][ni][1];
                float* q = p + (size_t)8 * o.Nout;
                q[0] = acc[mi][ni][2];
                q[1] = acc[mi][ni][3];
            }
    } else if (o.split == 2) {
#pragma unroll
        for (int mi = 0; mi < 4; mi++)
#pragma unroll
            for (int ni = 0; ni < 8; ni++) {
                size_t off0 = (size_t)(m0 + warpM + mi * 16 + er) * o.Nout
                            + (ncol0 + warpN + ni * 8 + ec);
                size_t off1 = off0 + (size_t)8 * o.Nout;
                *(uint32_t*)(o.Ch + off0) = pack_h2(
                    __float2half_rn(acc[mi][ni][0]), __float2half_rn(acc[mi][ni][1]));
                *(uint32_t*)(o.Ch + off1) = pack_h2(
                    __float2half_rn(acc[mi][ni][2]), __float2half_rn(acc[mi][ni][3]));
            }
    } else {
#pragma unroll
        for (int mi = 0; mi < 4; mi++)
#pragma unroll
            for (int ni = 0; ni < 8; ni++) {
                size_t off0 = (size_t)(m0 + warpM + mi * 16 + er) * o.Nout
                            + (ncol0 + warpN + ni * 8 + ec);
                size_t off1 = off0 + (size_t)8 * o.Nout;
                float v0 = acc[mi][ni][0], v1 = acc[mi][ni][1];
                float v2 = acc[mi][ni][2], v3 = acc[mi][ni][3];
                __half h0 = __float2half_rn(v0), h1 = __float2half_rn(v1);
                __half h2 = __float2half_rn(v2), h3 = __float2half_rn(v3);
                *(uint32_t*)(o.Ch + off0) = pack_h2(h0, h1);
                *(uint32_t*)(o.Ch + off1) = pack_h2(h2, h3);
                *(uint32_t*)(o.Cl + off0) = pack_h2(
                    __float2half_rn(v0 - __half2float(h0)),
                    __float2half_rn(v1 - __half2float(h1)));
                *(uint32_t*)(o.Cl + off1) = pack_h2(
                    __float2half_rn(v2 - __half2float(h2)),
                    __float2half_rn(v3 - __half2float(h3)));
            }
    }
}

// swizzled block mapping (supertiles of 8 m-blocks)
__device__ __forceinline__ void cta_map(int gx, int gy, int& mb, int& nb) {
    int lin = blockIdx.y * gx + blockIdx.x;
    const int SW = 8;
    int per  = SW * gx;
    int band = lin / per;
    int rem  = lin - band * per;
    int h    = gy - band * SW; if (h > SW) h = SW;
    mb = band * SW + rem % h;
    nb = rem / h;
}

// fused QKV projection: virtual N = 6144 (Q 4096 | K 1024 | V 1024)
__global__ __launch_bounds__(256, 1) void qkv_hmma(
    const __half* __restrict__ xh, const __half* __restrict__ xl,
    const __half* __restrict__ wqh,
    const __half* __restrict__ wkh,
    const __half* __restrict__ wvh,
    __half* __restrict__ qh,
    __half* __restrict__ kh, __half* __restrict__ kl,
    __half* __restrict__ vh)
{
    extern __shared__ char smraw[];
    const uint32_t sbase = smem_u32(smraw);
    int mb, nb;
    cta_map(gridDim.x, gridDim.y, mb, nb);
    const int m0 = mb * BM;

    const __half* Bh_;
    GemmOut o; o.C = nullptr;
    int ncol;
    if (nb < 16)      { Bh_ = wqh; o.Ch = qh; o.Cl = nullptr; o.split = 2; o.Nout = HIDDEN; ncol = nb * BN; }
    else if (nb < 20) { Bh_ = wkh; o.Ch = kh; o.Cl = kl; o.split = 1; o.Nout = KVDIM; ncol = (nb - 16) * BN; }
    else              { Bh_ = wvh; o.Ch = vh; o.Cl = nullptr; o.split = 2; o.Nout = KVDIM; ncol = (nb - 20) * BN; }

    gemm2_core(sbase, xh + (size_t)m0 * HIDDEN, xl + (size_t)m0 * HIDDEN,
               Bh_ + (size_t)ncol * HIDDEN, m0, ncol, HIDDEN, o);
}

// output GEMM (fp32 out): A = AO hi/lo, B = Wo hi
__global__ __launch_bounds__(256, 1) void gemm_hmma2(
    const __half* __restrict__ Ah, const __half* __restrict__ Al,
    const __half* __restrict__ Bh,
    float* __restrict__ C, int N, int K)
{
    extern __shared__ char smraw[];
    const uint32_t sbase = smem_u32(smraw);
    int mb, nb;
    cta_map(gridDim.x, gridDim.y, mb, nb);
    const int m0 = mb * BM, n0 = nb * BN;
    GemmOut o; o.C = C; o.Ch = nullptr; o.Cl = nullptr; o.Nout = N; o.split = 0;
    gemm2_core(sbase, Ah + (size_t)m0 * K, Al + (size_t)m0 * K,
               Bh + (size_t)n0 * K, m0, n0, K, o);
}

// ======================= V transpose (hi only) ==============================
__global__ __launch_bounds__(256) void transpose_v(
    const __half* __restrict__ vh, __half* __restrict__ vth)
{
    __shared__ __half th[32][33];
    const int b  = blockIdx.z;
    const int k0 = blockIdx.y * 32;
    const int s0 = blockIdx.x * 32;
    const int tx = threadIdx.x & 31;
    const int ty = threadIdx.x >> 5;
#pragma unroll
    for (int i = 0; i < 4; i++) {
        int row = ty + i * 8;
        th[row][tx] = vh[(size_t)(b * SEQ + s0 + row) * KVDIM + k0 + tx];
    }
    __syncthreads();
#pragma unroll
    for (int i = 0; i < 4; i++) {
        int row = ty + i * 8;
        vth[((size_t)b * KVDIM + k0 + row) * SEQ + s0 + tx] = th[tx][row];
    }
}

// ======================= HMMA flash attention ================================
// QK: Qh*Kh + Qh*Kl.  PV: Ph*Vh.
#define QROWB 272
#define KROWB 272
#define VROWB 144
#define SKV_BASE  34816
#define SKV_STRIDE 53248
#define OFF_KH 0
#define OFF_KL 17408
#define OFF_VTH 34816
#define FLASH_SMEM (SKV_BASE + 2*SKV_STRIDE)   // 141312

__global__ __launch_bounds__(256, 1) void flash_hmma(
    const __half* __restrict__ qh,
    const __half* __restrict__ kh, const __half* __restrict__ kl,
    const __half* __restrict__ vth,
    __half* __restrict__ aoh, __half* __restrict__ aol)
{
    extern __shared__ char smraw[];
    const uint32_t sb = smem_u32(smraw);
    const int tid = threadIdx.x, wid = tid >> 5, lane = tid & 31;
    const int qb = (int)(gridDim.x - 1 - blockIdx.x);
    const int hq = blockIdx.y, b = blockIdx.z;
    const int kvh = hq >> 2;
    const int qrow0 = qb * 128;
    const int g = lane >> 2, tig = lane & 3;
    const float scale = 0.08838834764831845f;

    const __half* qhg = qh + (size_t)(b * SEQ + qrow0) * HIDDEN + hq * HD;
#pragma unroll
    for (int t = 0; t < 8; t++) {
        int idx = tid + t * 256;
        int r = idx >> 4, c = idx & 15;
        cp16(sb + (uint32_t)(r * QROWB + c * 16), qhg + (size_t)r * HIDDEN + c * 8);
    }
    cp_commit();

    const __half* khg = kh + (size_t)(b * SEQ) * KVDIM + kvh * HD;
    const __half* klg = kl + (size_t)(b * SEQ) * KVDIM + kvh * HD;
    const __half* vthg = vth + ((size_t)b * KVDIM + kvh * HD) * SEQ;

    auto load_kv = [&](int stage, int j) {
        uint32_t base = sb + SKV_BASE + stage * SKV_STRIDE;
        int c0 = j * 64;
#pragma unroll
        for (int t = 0; t < 4; t++) {
            int idx = tid + t * 256;
            int r = idx >> 4, c = idx & 15;
            uint32_t d = (uint32_t)(r * KROWB + c * 16);
            size_t s = (size_t)(c0 + r) * KVDIM + c * 8;
            cp16(base + OFF_KH + d, khg + s);
            cp16(base + OFF_KL + d, klg + s);
        }
#pragma unroll
        for (int t = 0; t < 4; t++) {
            int idx = tid + t * 256;
            int r = idx >> 3, c = idx & 7;
            uint32_t d = (uint32_t)(r * VROWB + c * 16);
            cp16(base + OFF_VTH + d, vthg + (size_t)r * SEQ + c0 + c * 8);
        }
    };

    const int nb = 2 * qb + 2;
    load_kv(0, 0);
    cp_commit();

    float oacc[16][4];
#pragma unroll
    for (int i = 0; i < 16; i++)
#pragma unroll
        for (int t = 0; t < 4; t++) oacc[i][t] = 0.f;
    float m0 = -1e30f, m1 = -1e30f, l0 = 0.f, l1 = 0.f;

    const int aRow = lane & 15;
    const int aKof = (lane >> 4) * 16;
    const int bRow = (lane & 7) + ((lane & 16) ? 8 : 0);
    const int bKof = (lane & 8) ? 16 : 0;

    const int rg0 = qrow0 + 16 * wid + g;
    const int rg1 = rg0 + 8;

    for (int j = 0; j < nb; j++) {
        const int buf = j & 1;
        if (j + 1 < nb) {
            load_kv(1 - buf, j + 1);
            cp_commit();
            cp_wait<1>();
        } else {
            cp_wait<0>();
        }
        __syncthreads();

        const uint32_t kbase = sb + SKV_BASE + buf * SKV_STRIDE;

        float sacc[8][4];
#pragma unroll
        for (int i = 0; i < 8; i++)
#pragma unroll
            for (int t = 0; t < 4; t++) sacc[i][t] = 0.f;

#pragma unroll
        for (int kd = 0; kd < 8; kd++) {
            uint32_t aa = (uint32_t)((16 * wid + aRow) * QROWB + kd * 32 + aKof);
            uint32_t ah[4];
            ldm_x4(ah, sb + aa);
            uint32_t bh[4][4], bl[4][4];
#pragma unroll
            for (int np = 0; np < 4; np++) {
                uint32_t ba = (uint32_t)((np * 16 + bRow) * KROWB + kd * 32 + bKof);
                ldm_x4(bh[np], kbase + OFF_KH + ba);
                ldm_x4(bl[np], kbase + OFF_KL + ba);
            }
#pragma unroll
            for (int ni = 0; ni < 8; ni++) {
                uint32_t b0h = bh[ni >> 1][(ni & 1) * 2], b1h = bh[ni >> 1][(ni & 1) * 2 + 1];
                mma16816(sacc[ni], ah, b0h, b1h);
            }
#pragma unroll
            for (int ni = 0; ni < 8; ni++) {
                uint32_t b0l = bl[ni >> 1][(ni & 1) * 2], b1l = bl[ni >> 1][(ni & 1) * 2 + 1];
                mma16816(sacc[ni], ah, b0l, b1l);
            }
        }

        const int c0 = j * 64;
#pragma unroll
        for (int ni = 0; ni < 8; ni++)
#pragma unroll
            for (int t = 0; t < 4; t++) sacc[ni][t] *= scale;
        if (j >= 2 * qb) {
#pragma unroll
            for (int ni = 0; ni < 8; ni++) {
                int cg = c0 + ni * 8 + 2 * tig;
                if (cg     > rg0) sacc[ni][0] = -1e30f;
                if (cg + 1 > rg0) sacc[ni][1] = -1e30f;
                if (cg     > rg1) sacc[ni][2] = -1e30f;
                if (cg + 1 > rg1) sacc[ni][3] = -1e30f;
            }
        }

        float vm0 = -1e30f, vm1 = -1e30f;
#pragma unroll
        for (int ni = 0; ni < 8; ni++) {
            vm0 = fmaxf(vm0, fmaxf(sacc[ni][0], sacc[ni][1]));
            vm1 = fmaxf(vm1, fmaxf(sacc[ni][2], sacc[ni][3]));
        }
        vm0 = fmaxf(vm0, __shfl_xor_sync(0xffffffffu, vm0, 1));
        vm0 = fmaxf(vm0, __shfl_xor_sync(0xffffffffu, vm0, 2));
        vm1 = fmaxf(vm1, __shfl_xor_sync(0xffffffffu, vm1, 1));
        vm1 = fmaxf(vm1, __shfl_xor_sync(0xffffffffu, vm1, 2));
        float mn0 = fmaxf(m0, vm0), mn1 = fmaxf(m1, vm1);
        float al0 = __expf(m0 - mn0), al1 = __expf(m1 - mn1);
        float sum0 = 0.f, sum1 = 0.f;
#pragma unroll
        for (int ni = 0; ni < 8; ni++) {
            sacc[ni][0] = __expf(sacc[ni][0] - mn0);
            sacc[ni][1] = __expf(sacc[ni][1] - mn0);
            sacc[ni][2] = __expf(sacc[ni][2] - mn1);
            sacc[ni][3] = __expf(sacc[ni][3] - mn1);
            sum0 += sacc[ni][0] + sacc[ni][1];
            sum1 += sacc[ni][2] + sacc[ni][3];
        }
        sum0 += __shfl_xor_sync(0xffffffffu, sum0, 1);
        sum0 += __shfl_xor_sync(0xffffffffu, sum0, 2);
        sum1 += __shfl_xor_sync(0xffffffffu, sum1, 1);
        sum1 += __shfl_xor_sync(0xffffffffu, sum1, 2);
        l0 = l0 * al0 + sum0;  l1 = l1 * al1 + sum1;
        m0 = mn0;  m1 = mn1;

#pragma unroll
        for (int nd = 0; nd < 16; nd++) {
            oacc[nd][0] *= al0;  oacc[nd][1] *= al0;
            oacc[nd][2] *= al1;  oacc[nd][3] *= al1;
        }

        uint32_t pah[4][4];
#pragma unroll
        for (int t = 0; t < 4; t++) {
            pah[t][0] = pack_h2(__float2half_rn(sacc[2 * t][0]),
                                __float2half_rn(sacc[2 * t][1]));
            pah[t][1] = pack_h2(__float2half_rn(sacc[2 * t][2]),
                                __float2half_rn(sacc[2 * t][3]));
            pah[t][2] = pack_h2(__float2half_rn(sacc[2 * t + 1][0]),
                                __float2half_rn(sacc[2 * t + 1][1]));
            pah[t][3] = pack_h2(__float2half_rn(sacc[2 * t + 1][2]),
                                __float2half_rn(sacc[2 * t + 1][3]));
        }

#pragma unroll
        for (int t = 0; t < 4; t++) {
#pragma unroll
            for (int np = 0; np < 8; np++) {
                uint32_t ba = (uint32_t)((np * 16 + bRow) * VROWB + t * 32 + bKof);
                uint32_t vbh[4];
                ldm_x4(vbh, kbase + OFF_VTH + ba);
#pragma unroll
                for (int q = 0; q < 2; q++) {
                    int nd = np * 2 + q;
                    mma16816(oacc[nd], pah[t], vbh[q * 2], vbh[q * 2 + 1]);
                }
            }
        }
        __syncthreads();
    }

    float inv0 = 1.f / l0, inv1 = 1.f / l1;
    size_t row0 = (size_t)(b * SEQ + qrow0 + 16 * wid + g) * HIDDEN + hq * HD;
    size_t row1 = row0 + (size_t)8 * HIDDEN;
#pragma unroll
    for (int nd = 0; nd < 16; nd++) {
        int col = nd * 8 + 2 * tig;
        float v0 = oacc[nd][0] * inv0, v1 = oacc[nd][1] * inv0;
        float v2 = oacc[nd][2] * inv1, v3 = oacc[nd][3] * inv1;
        __half h0 = __float2half_rn(v0), h1 = __float2half_rn(v1);
        __half h2 = __float2half_rn(v2), h3 = __float2half_rn(v3);
        *(uint32_t*)(aoh + row0 + col) = pack_h2(h0, h1);
        *(uint32_t*)(aoh + row1 + col) = pack_h2(h2, h3);
        *(uint32_t*)(aol + row0 + col) = pack_h2(
            __float2half_rn(v0 - __half2float(h0)),
            __float2half_rn(v1 - __half2float(h1)));
        *(uint32_t*)(aol + row1 + col) = pack_h2(
            __float2half_rn(v2 - __half2float(h2)),
            __float2half_rn(v3 - __half2float(h3)));
    }
}

// ============================================================================
extern "C" void kernel_launch(void* const* d_in, const int* in_sizes, int n_in,
                              void* d_out, int out_size)
{
    const float* x  = (const float*)d_in[0];
    const float* Wq = (const float*)d_in[1];
    const float* Wk = (const float*)d_in[2];
    const float* Wv = (const float*)d_in[3];
    const float* Wo = (const float*)d_in[4];
    float* out = (float*)d_out;

    __half *xh, *xl, *wqh, *wkh, *wvh, *woh;
    __half *qh, *kh, *kl, *vh, *vth, *aoh, *aol;
    cudaGetSymbolAddress((void**)&xh,  g_xh);  cudaGetSymbolAddress((void**)&xl,  g_xl);
    cudaGetSymbolAddress((void**)&wqh, g_wqh);
    cudaGetSymbolAddress((void**)&wkh, g_wkh);
    cudaGetSymbolAddress((void**)&wvh, g_wvh);
    cudaGetSymbolAddress((void**)&woh, g_woh);
    cudaGetSymbolAddress((void**)&qh,  g_qh);
    cudaGetSymbolAddress((void**)&kh,  g_kh);  cudaGetSymbolAddress((void**)&kl,  g_kl);
    cudaGetSymbolAddress((void**)&vh,  g_vh);
    cudaGetSymbolAddress((void**)&vth, g_vth);
    cudaGetSymbolAddress((void**)&aoh, g_aoh); cudaGetSymbolAddress((void**)&aol, g_aol);

    cudaFuncSetAttribute(qkv_hmma,   cudaFuncAttributeMaxDynamicSharedMemorySize, GEMM_SMEM);
    cudaFuncSetAttribute(gemm_hmma2, cudaFuncAttributeMaxDynamicSharedMemorySize, GEMM_SMEM);
    cudaFuncSetAttribute(flash_hmma, cudaFuncAttributeMaxDynamicSharedMemorySize, FLASH_SMEM);

    const int XN4 = TOKENS * HIDDEN / 4;
    const int WTOT = 2 * WN4 + 2 * KN4;

    split_f32<<<(XN4 + 255) / 256, 256>>>((const float4*)x, (__half2*)xh, (__half2*)xl, XN4);
    split_w4<<<(WTOT + 255) / 256, 256>>>(
        (const float4*)Wq, (const float4*)Wk, (const float4*)Wv, (const float4*)Wo,
        (__half2*)wqh, (__half2*)wkh, (__half2*)wvh, (__half2*)woh);

    qkv_hmma<<<dim3(6144 / BN, TOKENS / BM), 256, GEMM_SMEM>>>(
        xh, xl, wqh, wkh, wvh, qh, kh, kl, vh);

    transpose_v<<<dim3(SEQ / 32, KVDIM / 32, BATCH), 256>>>(vh, vth);

    flash_hmma<<<dim3(SEQ / 128, NH, BATCH), 256, FLASH_SMEM>>>(
        qh, kh, kl, vth, aoh, aol);

    gemm_hmma2<<<dim3(HIDDEN / BN, TOKENS / BM), 256, GEMM_SMEM>>>(
        aoh, aol, woh, out, HIDDEN, HIDDEN);
}

// round 11
// speedup vs baseline: 5.8138x; 1.1672x over previous
#include <cuda_runtime.h>
#include <cuda_fp16.h>
#include <cstdint>
#include <math.h>

#define HIDDEN   4096
#define NKV      8
#define NH       32
#define HD       128
#define BATCH    2
#define SEQ      2048
#define TOKENS   (BATCH*SEQ)   // 4096
#define KVDIM    (NKV*HD)      // 1024

// ---------------- scratch (device globals; no runtime allocation) ----------
__device__ __half g_xh [TOKENS*HIDDEN], g_xl [TOKENS*HIDDEN];
__device__ __half g_wqh[HIDDEN*HIDDEN];
__device__ __half g_wkh[KVDIM*HIDDEN];
__device__ __half g_wvh[KVDIM*HIDDEN];
__device__ __half g_woh[HIDDEN*HIDDEN];
__device__ __half g_qh [TOKENS*HIDDEN];
__device__ __half g_kh [TOKENS*KVDIM],  g_kl [TOKENS*KVDIM];
__device__ __half g_vh [TOKENS*KVDIM];
__device__ __half g_vth[TOKENS*KVDIM];                    // [B][KVDIM][SEQ]
__device__ __half g_aoh[TOKENS*HIDDEN];

// ======================= helpers ============================================
__device__ __forceinline__ uint32_t smem_u32(const void* p) {
    uint32_t a;
    asm("{ .reg .u64 t; cvta.to.shared.u64 t, %1; cvt.u32.u64 %0, t; }"
        : "=r"(a) : "l"(p));
    return a;
}
__device__ __forceinline__ void cp16(uint32_t dst, const void* src) {
    asm volatile("cp.async.cg.shared.global [%0], [%1], 16;" :: "r"(dst), "l"(src));
}
__device__ __forceinline__ void cp_commit() { asm volatile("cp.async.commit_group;" ::: "memory"); }
template<int N> __device__ __forceinline__ void cp_wait() {
    asm volatile("cp.async.wait_group %0;" :: "n"(N) : "memory");
}
__device__ __forceinline__ void ldm_x4(uint32_t* r, uint32_t addr) {
    asm volatile("ldmatrix.sync.aligned.m8n8.x4.shared.b16 {%0,%1,%2,%3}, [%4];"
        : "=r"(r[0]), "=r"(r[1]), "=r"(r[2]), "=r"(r[3]) : "r"(addr));
}
__device__ __forceinline__ void mma16816(float* d, const uint32_t* a,
                                         uint32_t b0, uint32_t b1) {
    asm volatile(
        "mma.sync.aligned.m16n8k16.row.col.f32.f16.f16.f32 "
        "{%0,%1,%2,%3}, {%4,%5,%6,%7}, {%8,%9}, {%0,%1,%2,%3};"
        : "+f"(d[0]), "+f"(d[1]), "+f"(d[2]), "+f"(d[3])
        : "r"(a[0]), "r"(a[1]), "r"(a[2]), "r"(a[3]), "r"(b0), "r"(b1));
}
__device__ __forceinline__ uint32_t pack_h2(__half a, __half b) {
    __half2 h = __halves2half2(a, b);
    return *(uint32_t*)&h;
}

// ======================= split fp32 -> fp16 (hi[/lo]) =======================
__global__ __launch_bounds__(256) void split_f32(
    const float4* __restrict__ x, __half2* __restrict__ hi,
    __half2* __restrict__ lo, int n4)
{
    int i = blockIdx.x * blockDim.x + threadIdx.x;
    if (i >= n4) return;
    float4 v = x[i];
    __half h0 = __float2half_rn(v.x), h1 = __float2half_rn(v.y);
    __half h2 = __float2half_rn(v.z), h3 = __float2half_rn(v.w);
    hi[2 * i]     = __halves2half2(h0, h1);
    hi[2 * i + 1] = __halves2half2(h2, h3);
    if (lo) {
        lo[2 * i] = __halves2half2(__float2half_rn(v.x - __half2float(h0)),
                                   __float2half_rn(v.y - __half2float(h1)));
        lo[2 * i + 1] = __halves2half2(__float2half_rn(v.z - __half2float(h2)),
                                       __float2half_rn(v.w - __half2float(h3)));
    }
}

// all 4 weights, hi-only, single launch
#define WN4 (HIDDEN*HIDDEN/4)
#define KN4 (KVDIM*HIDDEN/4)
__global__ __launch_bounds__(256) void split_w4(
    const float4* __restrict__ wq, const float4* __restrict__ wk,
    const float4* __restrict__ wv, const float4* __restrict__ wo,
    __half2* __restrict__ qo, __half2* __restrict__ ko,
    __half2* __restrict__ vo, __half2* __restrict__ oo)
{
    int i = blockIdx.x * blockDim.x + threadIdx.x;
    const float4* src;
    __half2* dst;
    int idx;
    if (i < WN4)                 { src = wq; dst = qo; idx = i; }
    else if (i < WN4 + KN4)      { src = wk; dst = ko; idx = i - WN4; }
    else if (i < WN4 + 2 * KN4)  { src = wv; dst = vo; idx = i - WN4 - KN4; }
    else if (i < 2 * WN4 + 2 * KN4) { src = wo; dst = oo; idx = i - WN4 - 2 * KN4; }
    else return;
    float4 v = src[idx];
    dst[2 * idx]     = __halves2half2(__float2half_rn(v.x), __float2half_rn(v.y));
    dst[2 * idx + 1] = __halves2half2(__float2half_rn(v.z), __float2half_rn(v.w));
}

// ======================= QKV GEMM (A-split, 2-term) =========================
#define BM 128
#define BN 256
#define BK 64
#define ROWB 144
#define A_ST (BM*ROWB)                 // 18432
#define B_ST (BN*ROWB)                 // 36864
#define STAGE_B (2*A_ST + B_ST)        // 73728
#define NSTAGE 3
#define GEMM_SMEM (NSTAGE*STAGE_B)     // 221184

// swizzled block mapping (supertiles of 8 m-blocks)
__device__ __forceinline__ void cta_map(int gx, int gy, int& mb, int& nb) {
    int lin = blockIdx.y * gx + blockIdx.x;
    const int SW = 8;
    int per  = SW * gx;
    int band = lin / per;
    int rem  = lin - band * per;
    int h    = gy - band * SW; if (h > SW) h = SW;
    mb = band * SW + rem % h;
    nb = rem / h;
}

__global__ __launch_bounds__(256, 1) void qkv_hmma(
    const __half* __restrict__ xh, const __half* __restrict__ xl,
    const __half* __restrict__ wqh,
    const __half* __restrict__ wkh,
    const __half* __restrict__ wvh,
    __half* __restrict__ qh,
    __half* __restrict__ kh, __half* __restrict__ kl,
    __half* __restrict__ vh)
{
    extern __shared__ char smraw[];
    const uint32_t sbase = smem_u32(smraw);
    const int tid  = threadIdx.x;
    const int wid  = tid >> 5;
    const int lane = tid & 31;
    const int wm   = wid & 1;
    const int wn   = wid >> 1;

    int mb, nb;
    cta_map(gridDim.x, gridDim.y, mb, nb);
    const int m0 = mb * BM;

    const __half* Bh_;
    __half *Ch, *Cl = nullptr;
    int Nout, split, ncol;
    if (nb < 16)      { Bh_ = wqh; Ch = qh; split = 2; Nout = HIDDEN; ncol = nb * BN; }
    else if (nb < 20) { Bh_ = wkh; Ch = kh; Cl = kl; split = 1; Nout = KVDIM; ncol = (nb - 16) * BN; }
    else              { Bh_ = wvh; Ch = vh; split = 2; Nout = KVDIM; ncol = (nb - 20) * BN; }

    const __half* A0h = xh + (size_t)m0 * HIDDEN;
    const __half* A0l = xl + (size_t)m0 * HIDDEN;
    const __half* B0h = Bh_ + (size_t)ncol * HIDDEN;
    const int K = HIDDEN;

    auto bAh = [&](int s) { return sbase + s * STAGE_B; };
    auto bAl = [&](int s) { return sbase + s * STAGE_B + A_ST; };
    auto bB  = [&](int s) { return sbase + s * STAGE_B + 2 * A_ST; };

    auto load_stage = [&](int s, int k0) {
#pragma unroll
        for (int t = 0; t < 4; t++) {
            int idx = tid + t * 256;
            int r = idx >> 3, c = idx & 7;
            uint32_t d = (uint32_t)(r * ROWB + c * 16);
            size_t so = (size_t)r * K + k0 + c * 8;
            cp16(bAh(s) + d, A0h + so);
            cp16(bAl(s) + d, A0l + so);
        }
#pragma unroll
        for (int t = 0; t < 8; t++) {
            int idx = tid + t * 256;
            int r = idx >> 3, c = idx & 7;
            uint32_t d = (uint32_t)(r * ROWB + c * 16);
            cp16(bB(s) + d, B0h + (size_t)r * K + k0 + c * 8);
        }
    };

    float acc[4][8][4];
#pragma unroll
    for (int i = 0; i < 4; i++)
#pragma unroll
        for (int j = 0; j < 8; j++)
#pragma unroll
            for (int t = 0; t < 4; t++) acc[i][j][t] = 0.f;

    const int aRow = lane & 15;
    const int aKof = (lane >> 4) * 16;
    const int bRow = (lane & 7) + ((lane & 16) ? 8 : 0);
    const int bKof = (lane & 8) ? 16 : 0;
    const int warpM = wm * 64;
    const int warpN = wn * 64;

    const int nst = K / BK;
    load_stage(0, 0);
    cp_commit();
    load_stage(1, BK);
    cp_commit();

    for (int s = 0; s < nst; s++) {
        const int buf = s % NSTAGE;
        if (s + 1 < nst) cp_wait<1>(); else cp_wait<0>();
        __syncthreads();

        const uint32_t sAh = bAh(buf), sAl = bAl(buf), sB = bB(buf);

#pragma unroll
        for (int ks = 0; ks < 4; ks++) {
            const int kb = ks * 32;
            uint32_t ah[4][4], al[4][4], bh[4][4];
#pragma unroll
            for (int mi = 0; mi < 4; mi++) {
                uint32_t ad = (uint32_t)((warpM + mi * 16 + aRow) * ROWB + kb + aKof);
                ldm_x4(ah[mi], sAh + ad);
                ldm_x4(al[mi], sAl + ad);
            }
#pragma unroll
            for (int np = 0; np < 4; np++) {
                uint32_t bd = (uint32_t)((warpN + np * 16 + bRow) * ROWB + kb + bKof);
                ldm_x4(bh[np], sB + bd);
            }
#pragma unroll
            for (int np = 0; np < 4; np++)
#pragma unroll
                for (int q = 0; q < 2; q++) {
                    const int ni = np * 2 + q;
                    const uint32_t b0 = bh[np][q * 2], b1 = bh[np][q * 2 + 1];
#pragma unroll
                    for (int mi = 0; mi < 4; mi++)
                        mma16816(acc[mi][ni], ah[mi], b0, b1);
                }
#pragma unroll
            for (int np = 0; np < 4; np++)
#pragma unroll
                for (int q = 0; q < 2; q++) {
                    const int ni = np * 2 + q;
                    const uint32_t b0 = bh[np][q * 2], b1 = bh[np][q * 2 + 1];
#pragma unroll
                    for (int mi = 0; mi < 4; mi++)
                        mma16816(acc[mi][ni], al[mi], b0, b1);
                }
        }

        if (s + 2 < nst) {
            load_stage((s + 2) % NSTAGE, (s + 2) * BK);
            cp_commit();
        }
    }

    const int er = lane >> 2;
    const int ec = (lane & 3) * 2;
    if (split == 2) {
#pragma unroll
        for (int mi = 0; mi < 4; mi++)
#pragma unroll
            for (int ni = 0; ni < 8; ni++) {
                size_t off0 = (size_t)(m0 + warpM + mi * 16 + er) * Nout
                            + (ncol + warpN + ni * 8 + ec);
                size_t off1 = off0 + (size_t)8 * Nout;
                *(uint32_t*)(Ch + off0) = pack_h2(
                    __float2half_rn(acc[mi][ni][0]), __float2half_rn(acc[mi][ni][1]));
                *(uint32_t*)(Ch + off1) = pack_h2(
                    __float2half_rn(acc[mi][ni][2]), __float2half_rn(acc[mi][ni][3]));
            }
    } else {
#pragma unroll
        for (int mi = 0; mi < 4; mi++)
#pragma unroll
            for (int ni = 0; ni < 8; ni++) {
                size_t off0 = (size_t)(m0 + warpM + mi * 16 + er) * Nout
                            + (ncol + warpN + ni * 8 + ec);
                size_t off1 = off0 + (size_t)8 * Nout;
                float v0 = acc[mi][ni][0], v1 = acc[mi][ni][1];
                float v2 = acc[mi][ni][2], v3 = acc[mi][ni][3];
                __half h0 = __float2half_rn(v0), h1 = __float2half_rn(v1);
                __half h2 = __float2half_rn(v2), h3 = __float2half_rn(v3);
                *(uint32_t*)(Ch + off0) = pack_h2(h0, h1);
                *(uint32_t*)(Ch + off1) = pack_h2(h2, h3);
                *(uint32_t*)(Cl + off0) = pack_h2(
                    __float2half_rn(v0 - __half2float(h0)),
                    __float2half_rn(v1 - __half2float(h1)));
                *(uint32_t*)(Cl + off1) = pack_h2(
                    __float2half_rn(v2 - __half2float(h2)),
                    __float2half_rn(v3 - __half2float(h3)));
            }
    }
}

// ======================= Wo GEMM (single-term, 256x128 tile) ================
#define WOM 256
#define WON 128
#define WO_A_ST (WOM*ROWB)             // 36864
#define WO_B_ST (WON*ROWB)             // 18432
#define WO_STAGE (WO_A_ST + WO_B_ST)   // 55296
#define WO_SMEM (NSTAGE*WO_STAGE)      // 165888

__global__ __launch_bounds__(256, 1) void gemm_wo(
    const __half* __restrict__ Ah, const __half* __restrict__ Bh,
    float* __restrict__ C, int N, int K)
{
    extern __shared__ char smraw[];
    const uint32_t sbase = smem_u32(smraw);
    const int tid  = threadIdx.x;
    const int wid  = tid >> 5;
    const int lane = tid & 31;
    const int wm   = wid & 3;           // 4 m-quarters of 64
    const int wn   = wid >> 2;          // 2 n-halves of 64

    int mb, nb;
    cta_map(gridDim.x, gridDim.y, mb, nb);
    const int m0 = mb * WOM, n0 = nb * WON;

    const __half* A0 = Ah + (size_t)m0 * K;
    const __half* B0 = Bh + (size_t)n0 * K;

    auto bA = [&](int s) { return sbase + s * WO_STAGE; };
    auto bB = [&](int s) { return sbase + s * WO_STAGE + WO_A_ST; };

    auto load_stage = [&](int s, int k0) {
#pragma unroll
        for (int t = 0; t < 8; t++) {               // A: 2048 chunks
            int idx = tid + t * 256;
            int r = idx >> 3, c = idx & 7;
            uint32_t d = (uint32_t)(r * ROWB + c * 16);
            cp16(bA(s) + d, A0 + (size_t)r * K + k0 + c * 8);
        }
#pragma unroll
        for (int t = 0; t < 4; t++) {               // B: 1024 chunks
            int idx = tid + t * 256;
            int r = idx >> 3, c = idx & 7;
            uint32_t d = (uint32_t)(r * ROWB + c * 16);
            cp16(bB(s) + d, B0 + (size_t)r * K + k0 + c * 8);
        }
    };

    float acc[4][8][4];
#pragma unroll
    for (int i = 0; i < 4; i++)
#pragma unroll
        for (int j = 0; j < 8; j++)
#pragma unroll
            for (int t = 0; t < 4; t++) acc[i][j][t] = 0.f;

    const int aRow = lane & 15;
    const int aKof = (lane >> 4) * 16;
    const int bRow = (lane & 7) + ((lane & 16) ? 8 : 0);
    const int bKof = (lane & 8) ? 16 : 0;
    const int warpM = wm * 64;
    const int warpN = wn * 64;

    const int nst = K / BK;
    load_stage(0, 0);
    cp_commit();
    load_stage(1, BK);
    cp_commit();

    for (int s = 0; s < nst; s++) {
        const int buf = s % NSTAGE;
        if (s + 1 < nst) cp_wait<1>(); else cp_wait<0>();
        __syncthreads();

        const uint32_t sA = bA(buf), sB = bB(buf);

#pragma unroll
        for (int ks = 0; ks < 4; ks++) {
            const int kb = ks * 32;
            uint32_t ah[4][4], bh[4][4];
#pragma unroll
            for (int mi = 0; mi < 4; mi++) {
                uint32_t ad = (uint32_t)((warpM + mi * 16 + aRow) * ROWB + kb + aKof);
                ldm_x4(ah[mi], sA + ad);
            }
#pragma unroll
            for (int np = 0; np < 4; np++) {
                uint32_t bd = (uint32_t)((warpN + np * 16 + bRow) * ROWB + kb + bKof);
                ldm_x4(bh[np], sB + bd);
            }
#pragma unroll
            for (int np = 0; np < 4; np++)
#pragma unroll
                for (int q = 0; q < 2; q++) {
                    const int ni = np * 2 + q;
                    const uint32_t b0 = bh[np][q * 2], b1 = bh[np][q * 2 + 1];
#pragma unroll
                    for (int mi = 0; mi < 4; mi++)
                        mma16816(acc[mi][ni], ah[mi], b0, b1);
                }
        }

        if (s + 2 < nst) {
            load_stage((s + 2) % NSTAGE, (s + 2) * BK);
            cp_commit();
        }
    }

    const int er = lane >> 2;
    const int ec = (lane & 3) * 2;
#pragma unroll
    for (int mi = 0; mi < 4; mi++)
#pragma unroll
        for (int ni = 0; ni < 8; ni++) {
            float* p = C + (size_t)(m0 + warpM + mi * 16 + er) * N
                         + (n0 + warpN + ni * 8 + ec);
            p[0] = acc[mi][ni][0];
            p[1] = acc[mi][ni][1];
            float* q = p + (size_t)8 * N;
            q[0] = acc[mi][ni][2];
            q[1] = acc[mi][ni][3];
        }
}

// ======================= V transpose (hi only) ==============================
__global__ __launch_bounds__(256) void transpose_v(
    const __half* __restrict__ vh, __half* __restrict__ vth)
{
    __shared__ __half th[32][33];
    const int b  = blockIdx.z;
    const int k0 = blockIdx.y * 32;
    const int s0 = blockIdx.x * 32;
    const int tx = threadIdx.x & 31;
    const int ty = threadIdx.x >> 5;
#pragma unroll
    for (int i = 0; i < 4; i++) {
        int row = ty + i * 8;
        th[row][tx] = vh[(size_t)(b * SEQ + s0 + row) * KVDIM + k0 + tx];
    }
    __syncthreads();
#pragma unroll
    for (int i = 0; i < 4; i++) {
        int row = ty + i * 8;
        vth[((size_t)b * KVDIM + k0 + row) * SEQ + s0 + tx] = th[tx][row];
    }
}

// ======================= HMMA flash attention ================================
// QK: Qh*Kh + Qh*Kl.  PV: Ph*Vh.  Softmax in log2 domain (exp2f).
#define QROWB 272
#define KROWB 272
#define VROWB 144
#define SKV_BASE  34816
#define SKV_STRIDE 53248
#define OFF_KH 0
#define OFF_KL 17408
#define OFF_VTH 34816
#define FLASH_SMEM (SKV_BASE + 2*SKV_STRIDE)   // 141312

__global__ __launch_bounds__(256, 1) void flash_hmma(
    const __half* __restrict__ qh,
    const __half* __restrict__ kh, const __half* __restrict__ kl,
    const __half* __restrict__ vth,
    __half* __restrict__ aoh)
{
    extern __shared__ char smraw[];
    const uint32_t sb = smem_u32(smraw);
    const int tid = threadIdx.x, wid = tid >> 5, lane = tid & 31;
    const int qb = (int)(gridDim.x - 1 - blockIdx.x);
    const int hq = blockIdx.y, b = blockIdx.z;
    const int kvh = hq >> 2;
    const int qrow0 = qb * 128;
    const int g = lane >> 2, tig = lane & 3;
    // scale * log2(e): softmax tracked in log2 domain
    const float cs = 0.08838834764831845f * 1.4426950408889634f;

    const __half* qhg = qh + (size_t)(b * SEQ + qrow0) * HIDDEN + hq * HD;
#pragma unroll
    for (int t = 0; t < 8; t++) {
        int idx = tid + t * 256;
        int r = idx >> 4, c = idx & 15;
        cp16(sb + (uint32_t)(r * QROWB + c * 16), qhg + (size_t)r * HIDDEN + c * 8);
    }
    cp_commit();

    const __half* khg = kh + (size_t)(b * SEQ) * KVDIM + kvh * HD;
    const __half* klg = kl + (size_t)(b * SEQ) * KVDIM + kvh * HD;
    const __half* vthg = vth + ((size_t)b * KVDIM + kvh * HD) * SEQ;

    auto load_kv = [&](int stage, int j) {
        uint32_t base = sb + SKV_BASE + stage * SKV_STRIDE;
        int c0 = j * 64;
#pragma unroll
        for (int t = 0; t < 4; t++) {
            int idx = tid + t * 256;
            int r = idx >> 4, c = idx & 15;
            uint32_t d = (uint32_t)(r * KROWB + c * 16);
            size_t s = (size_t)(c0 + r) * KVDIM + c * 8;
            cp16(base + OFF_KH + d, khg + s);
            cp16(base + OFF_KL + d, klg + s);
        }
#pragma unroll
        for (int t = 0; t < 4; t++) {
            int idx = tid + t * 256;
            int r = idx >> 3, c = idx & 7;
            uint32_t d = (uint32_t)(r * VROWB + c * 16);
            cp16(base + OFF_VTH + d, vthg + (size_t)r * SEQ + c0 + c * 8);
        }
    };

    const int nb = 2 * qb + 2;
    load_kv(0, 0);
    cp_commit();

    float oacc[16][4];
#pragma unroll
    for (int i = 0; i < 16; i++)
#pragma unroll
        for (int t = 0; t < 4; t++) oacc[i][t] = 0.f;
    float m0 = -1e30f, m1 = -1e30f, l0 = 0.f, l1 = 0.f;   // m in log2 domain

    const int aRow = lane & 15;
    const int aKof = (lane >> 4) * 16;
    const int bRow = (lane & 7) + ((lane & 16) ? 8 : 0);
    const int bKof = (lane & 8) ? 16 : 0;

    const int rg0 = qrow0 + 16 * wid + g;
    const int rg1 = rg0 + 8;

    for (int j = 0; j < nb; j++) {
        const int buf = j & 1;
        if (j + 1 < nb) {
            load_kv(1 - buf, j + 1);
            cp_commit();
            cp_wait<1>();
        } else {
            cp_wait<0>();
        }
        __syncthreads();

        const uint32_t kbase = sb + SKV_BASE + buf * SKV_STRIDE;

        float sacc[8][4];
#pragma unroll
        for (int i = 0; i < 8; i++)
#pragma unroll
            for (int t = 0; t < 4; t++) sacc[i][t] = 0.f;

#pragma unroll
        for (int kd = 0; kd < 8; kd++) {
            uint32_t aa = (uint32_t)((16 * wid + aRow) * QROWB + kd * 32 + aKof);
            uint32_t ah[4];
            ldm_x4(ah, sb + aa);
            uint32_t bh[4][4], bl[4][4];
#pragma unroll
            for (int np = 0; np < 4; np++) {
                uint32_t ba = (uint32_t)((np * 16 + bRow) * KROWB + kd * 32 + bKof);
                ldm_x4(bh[np], kbase + OFF_KH + ba);
                ldm_x4(bl[np], kbase + OFF_KL + ba);
            }
#pragma unroll
            for (int ni = 0; ni < 8; ni++) {
                uint32_t b0h = bh[ni >> 1][(ni & 1) * 2], b1h = bh[ni >> 1][(ni & 1) * 2 + 1];
                mma16816(sacc[ni], ah, b0h, b1h);
            }
#pragma unroll
            for (int ni = 0; ni < 8; ni++) {
                uint32_t b0l = bl[ni >> 1][(ni & 1) * 2], b1l = bl[ni >> 1][(ni & 1) * 2 + 1];
                mma16816(sacc[ni], ah, b0l, b1l);
            }
        }

        // causal mask on raw scores
        const int c0 = j * 64;
        if (j >= 2 * qb) {
#pragma unroll
            for (int ni = 0; ni < 8; ni++) {
                int cg = c0 + ni * 8 + 2 * tig;
                if (cg     > rg0) sacc[ni][0] = -1e30f;
                if (cg + 1 > rg0) sacc[ni][1] = -1e30f;
                if (cg     > rg1) sacc[ni][2] = -1e30f;
                if (cg + 1 > rg1) sacc[ni][3] = -1e30f;
            }
        }

        // row max (raw), then scale into log2 domain
        float vm0 = -1e30f, vm1 = -1e30f;
#pragma unroll
        for (int ni = 0; ni < 8; ni++) {
            vm0 = fmaxf(vm0, fmaxf(sacc[ni][0], sacc[ni][1]));
            vm1 = fmaxf(vm1, fmaxf(sacc[ni][2], sacc[ni][3]));
        }
        vm0 = fmaxf(vm0, __shfl_xor_sync(0xffffffffu, vm0, 1));
        vm0 = fmaxf(vm0, __shfl_xor_sync(0xffffffffu, vm0, 2));
        vm1 = fmaxf(vm1, __shfl_xor_sync(0xffffffffu, vm1, 1));
        vm1 = fmaxf(vm1, __shfl_xor_sync(0xffffffffu, vm1, 2));
        float mn0 = fmaxf(m0, vm0 * cs), mn1 = fmaxf(m1, vm1 * cs);
        float al0 = exp2f(m0 - mn0), al1 = exp2f(m1 - mn1);
        float sum0 = 0.f, sum1 = 0.f;
#pragma unroll
        for (int ni = 0; ni < 8; ni++) {
            sacc[ni][0] = exp2f(fmaf(sacc[ni][0], cs, -mn0));
            sacc[ni][1] = exp2f(fmaf(sacc[ni][1], cs, -mn0));
            sacc[ni][2] = exp2f(fmaf(sacc[ni][2], cs, -mn1));
            sacc[ni][3] = exp2f(fmaf(sacc[ni][3], cs, -mn1));
            sum0 += sacc[ni][0] + sacc[ni][1];
            sum1 += sacc[ni][2] + sacc[ni][3];
        }
        sum0 += __shfl_xor_sync(0xffffffffu, sum0, 1);
        sum0 += __shfl_xor_sync(0xffffffffu, sum0, 2);
        sum1 += __shfl_xor_sync(0xffffffffu, sum1, 1);
        sum1 += __shfl_xor_sync(0xffffffffu, sum1, 2);
        l0 = l0 * al0 + sum0;  l1 = l1 * al1 + sum1;
        m0 = mn0;  m1 = mn1;

#pragma unroll
        for (int nd = 0; nd < 16; nd++) {
            oacc[nd][0] *= al0;  oacc[nd][1] *= al0;
            oacc[nd][2] *= al1;  oacc[nd][3] *= al1;
        }

        uint32_t pah[4][4];
#pragma unroll
        for (int t = 0; t < 4; t++) {
            pah[t][0] = pack_h2(__float2half_rn(sacc[2 * t][0]),
                                __float2half_rn(sacc[2 * t][1]));
            pah[t][1] = pack_h2(__float2half_rn(sacc[2 * t][2]),
                                __float2half_rn(sacc[2 * t][3]));
            pah[t][2] = pack_h2(__float2half_rn(sacc[2 * t + 1][0]),
                                __float2half_rn(sacc[2 * t + 1][1]));
            pah[t][3] = pack_h2(__float2half_rn(sacc[2 * t + 1][2]),
                                __float2half_rn(sacc[2 * t + 1][3]));
        }

#pragma unroll
        for (int t = 0; t < 4; t++) {
#pragma unroll
            for (int np = 0; np < 8; np++) {
                uint32_t ba = (uint32_t)((np * 16 + bRow) * VROWB + t * 32 + bKof);
                uint32_t vbh[4];
                ldm_x4(vbh, kbase + OFF_VTH + ba);
#pragma unroll
                for (int q = 0; q < 2; q++) {
                    int nd = np * 2 + q;
                    mma16816(oacc[nd], pah[t], vbh[q * 2], vbh[q * 2 + 1]);
                }
            }
        }
        __syncthreads();
    }

    float inv0 = 1.f / l0, inv1 = 1.f / l1;
    size_t row0 = (size_t)(b * SEQ + qrow0 + 16 * wid + g) * HIDDEN + hq * HD;
    size_t row1 = row0 + (size_t)8 * HIDDEN;
#pragma unroll
    for (int nd = 0; nd < 16; nd++) {
        int col = nd * 8 + 2 * tig;
        *(uint32_t*)(aoh + row0 + col) = pack_h2(
            __float2half_rn(oacc[nd][0] * inv0), __float2half_rn(oacc[nd][1] * inv0));
        *(uint32_t*)(aoh + row1 + col) = pack_h2(
            __float2half_rn(oacc[nd][2] * inv1), __float2half_rn(oacc[nd][3] * inv1));
    }
}

// ============================================================================
extern "C" void kernel_launch(void* const* d_in, const int* in_sizes, int n_in,
                              void* d_out, int out_size)
{
    const float* x  = (const float*)d_in[0];
    const float* Wq = (const float*)d_in[1];
    const float* Wk = (const float*)d_in[2];
    const float* Wv = (const float*)d_in[3];
    const float* Wo = (const float*)d_in[4];
    float* out = (float*)d_out;

    __half *xh, *xl, *wqh, *wkh, *wvh, *woh;
    __half *qh, *kh, *kl, *vh, *vth, *aoh;
    cudaGetSymbolAddress((void**)&xh,  g_xh);  cudaGetSymbolAddress((void**)&xl,  g_xl);
    cudaGetSymbolAddress((void**)&wqh, g_wqh);
    cudaGetSymbolAddress((void**)&wkh, g_wkh);
    cudaGetSymbolAddress((void**)&wvh, g_wvh);
    cudaGetSymbolAddress((void**)&woh, g_woh);
    cudaGetSymbolAddress((void**)&qh,  g_qh);
    cudaGetSymbolAddress((void**)&kh,  g_kh);  cudaGetSymbolAddress((void**)&kl,  g_kl);
    cudaGetSymbolAddress((void**)&vh,  g_vh);
    cudaGetSymbolAddress((void**)&vth, g_vth);
    cudaGetSymbolAddress((void**)&aoh, g_aoh);

    cudaFuncSetAttribute(qkv_hmma,   cudaFuncAttributeMaxDynamicSharedMemorySize, GEMM_SMEM);
    cudaFuncSetAttribute(gemm_wo,    cudaFuncAttributeMaxDynamicSharedMemorySize, WO_SMEM);
    cudaFuncSetAttribute(flash_hmma, cudaFuncAttributeMaxDynamicSharedMemorySize, FLASH_SMEM);

    const int XN4 = TOKENS * HIDDEN / 4;
    const int WTOT = 2 * WN4 + 2 * KN4;

    split_f32<<<(XN4 + 255) / 256, 256>>>((const float4*)x, (__half2*)xh, (__half2*)xl, XN4);
    split_w4<<<(WTOT + 255) / 256, 256>>>(
        (const float4*)Wq, (const float4*)Wk, (const float4*)Wv, (const float4*)Wo,
        (__half2*)wqh, (__half2*)wkh, (__half2*)wvh, (__half2*)woh);

    qkv_hmma<<<dim3(6144 / BN, TOKENS / BM), 256, GEMM_SMEM>>>(
        xh, xl, wqh, wkh, wvh, qh, kh, kl, vh);

    transpose_v<<<dim3(SEQ / 32, KVDIM / 32, BATCH), 256>>>(vh, vth);

    flash_hmma<<<dim3(SEQ / 128, NH, BATCH), 256, FLASH_SMEM>>>(
        qh, kh, kl, vth, aoh);

    gemm_wo<<<dim3(HIDDEN / WON, TOKENS / WOM), 256, WO_SMEM>>>(
        aoh, woh, out, HIDDEN, HIDDEN);
}

// round 12
// speedup vs baseline: 7.5615x; 1.3006x over previous
#include <cuda_runtime.h>
#include <cuda_fp16.h>
#include <cstdint>
#include <math.h>

#define HIDDEN   4096
#define NKV      8
#define NH       32
#define HD       128
#define BATCH    2
#define SEQ      2048
#define TOKENS   (BATCH*SEQ)   // 4096
#define KVDIM    (NKV*HD)      // 1024

// ---------------- scratch (device globals; no runtime allocation) ----------
__device__ __half g_xh [TOKENS*HIDDEN];
__device__ __half g_wqh[HIDDEN*HIDDEN];
__device__ __half g_wkh[KVDIM*HIDDEN];
__device__ __half g_wvh[KVDIM*HIDDEN];
__device__ __half g_woh[HIDDEN*HIDDEN];
__device__ __half g_qh [TOKENS*HIDDEN];
__device__ __half g_kh [TOKENS*KVDIM],  g_kl [TOKENS*KVDIM];
__device__ __half g_vh [TOKENS*KVDIM];
__device__ __half g_vth[TOKENS*KVDIM];                    // [B][KVDIM][SEQ]
__device__ __half g_aoh[TOKENS*HIDDEN];

// ======================= helpers ============================================
__device__ __forceinline__ uint32_t smem_u32(const void* p) {
    uint32_t a;
    asm("{ .reg .u64 t; cvta.to.shared.u64 t, %1; cvt.u32.u64 %0, t; }"
        : "=r"(a) : "l"(p));
    return a;
}
__device__ __forceinline__ void cp16(uint32_t dst, const void* src) {
    asm volatile("cp.async.cg.shared.global [%0], [%1], 16;" :: "r"(dst), "l"(src));
}
__device__ __forceinline__ void cp_commit() { asm volatile("cp.async.commit_group;" ::: "memory"); }
template<int N> __device__ __forceinline__ void cp_wait() {
    asm volatile("cp.async.wait_group %0;" :: "n"(N) : "memory");
}
__device__ __forceinline__ void ldm_x4(uint32_t* r, uint32_t addr) {
    asm volatile("ldmatrix.sync.aligned.m8n8.x4.shared.b16 {%0,%1,%2,%3}, [%4];"
        : "=r"(r[0]), "=r"(r[1]), "=r"(r[2]), "=r"(r[3]) : "r"(addr));
}
__device__ __forceinline__ void mma16816(float* d, const uint32_t* a,
                                         uint32_t b0, uint32_t b1) {
    asm volatile(
        "mma.sync.aligned.m16n8k16.row.col.f32.f16.f16.f32 "
        "{%0,%1,%2,%3}, {%4,%5,%6,%7}, {%8,%9}, {%0,%1,%2,%3};"
        : "+f"(d[0]), "+f"(d[1]), "+f"(d[2]), "+f"(d[3])
        : "r"(a[0]), "r"(a[1]), "r"(a[2]), "r"(a[3]), "r"(b0), "r"(b1));
}
__device__ __forceinline__ uint32_t pack_h2(__half a, __half b) {
    __half2 h = __halves2half2(a, b);
    return *(uint32_t*)&h;
}

// ======================= split fp32 -> fp16 (hi only) =======================
__global__ __launch_bounds__(256) void split_hi(
    const float4* __restrict__ x, __half2* __restrict__ hi, int n4)
{
    int i = blockIdx.x * blockDim.x + threadIdx.x;
    if (i >= n4) return;
    float4 v = x[i];
    hi[2 * i]     = __halves2half2(__float2half_rn(v.x), __float2half_rn(v.y));
    hi[2 * i + 1] = __halves2half2(__float2half_rn(v.z), __float2half_rn(v.w));
}

// all 4 weights, hi-only, single launch
#define WN4 (HIDDEN*HIDDEN/4)
#define KN4 (KVDIM*HIDDEN/4)
__global__ __launch_bounds__(256) void split_w4(
    const float4* __restrict__ wq, const float4* __restrict__ wk,
    const float4* __restrict__ wv, const float4* __restrict__ wo,
    __half2* __restrict__ qo, __half2* __restrict__ ko,
    __half2* __restrict__ vo, __half2* __restrict__ oo)
{
    int i = blockIdx.x * blockDim.x + threadIdx.x;
    const float4* src;
    __half2* dst;
    int idx;
    if (i < WN4)                 { src = wq; dst = qo; idx = i; }
    else if (i < WN4 + KN4)      { src = wk; dst = ko; idx = i - WN4; }
    else if (i < WN4 + 2 * KN4)  { src = wv; dst = vo; idx = i - WN4 - KN4; }
    else if (i < 2 * WN4 + 2 * KN4) { src = wo; dst = oo; idx = i - WN4 - 2 * KN4; }
    else return;
    float4 v = src[idx];
    dst[2 * idx]     = __halves2half2(__float2half_rn(v.x), __float2half_rn(v.y));
    dst[2 * idx + 1] = __halves2half2(__float2half_rn(v.z), __float2half_rn(v.w));
}

// ======================= QKV GEMM (single-term) =============================
#define BM 128
#define BN 256
#define BK 64
#define ROWB 144
#define A_ST (BM*ROWB)                 // 18432
#define B_ST (BN*ROWB)                 // 36864
#define STAGE_B (A_ST + B_ST)          // 55296
#define NSTAGE 3
#define GEMM_SMEM (NSTAGE*STAGE_B)     // 165888

// swizzled block mapping (supertiles of 8 m-blocks)
__device__ __forceinline__ void cta_map(int gx, int gy, int& mb, int& nb) {
    int lin = blockIdx.y * gx + blockIdx.x;
    const int SW = 8;
    int per  = SW * gx;
    int band = lin / per;
    int rem  = lin - band * per;
    int h    = gy - band * SW; if (h > SW) h = SW;
    mb = band * SW + rem % h;
    nb = rem / h;
}

__global__ __launch_bounds__(256, 1) void qkv_hmma(
    const __half* __restrict__ xh,
    const __half* __restrict__ wqh,
    const __half* __restrict__ wkh,
    const __half* __restrict__ wvh,
    __half* __restrict__ qh,
    __half* __restrict__ kh, __half* __restrict__ kl,
    __half* __restrict__ vh)
{
    extern __shared__ char smraw[];
    const uint32_t sbase = smem_u32(smraw);
    const int tid  = threadIdx.x;
    const int wid  = tid >> 5;
    const int lane = tid & 31;
    const int wm   = wid & 1;
    const int wn   = wid >> 1;

    int mb, nb;
    cta_map(gridDim.x, gridDim.y, mb, nb);
    const int m0 = mb * BM;

    const __half* Bh_;
    __half *Ch, *Cl = nullptr;
    int Nout, split, ncol;
    if (nb < 16)      { Bh_ = wqh; Ch = qh; split = 2; Nout = HIDDEN; ncol = nb * BN; }
    else if (nb < 20) { Bh_ = wkh; Ch = kh; Cl = kl; split = 1; Nout = KVDIM; ncol = (nb - 16) * BN; }
    else              { Bh_ = wvh; Ch = vh; split = 2; Nout = KVDIM; ncol = (nb - 20) * BN; }

    const __half* A0h = xh + (size_t)m0 * HIDDEN;
    const __half* B0h = Bh_ + (size_t)ncol * HIDDEN;
    const int K = HIDDEN;

    auto bA = [&](int s) { return sbase + s * STAGE_B; };
    auto bB = [&](int s) { return sbase + s * STAGE_B + A_ST; };

    auto load_stage = [&](int s, int k0) {
#pragma unroll
        for (int t = 0; t < 4; t++) {
            int idx = tid + t * 256;
            int r = idx >> 3, c = idx & 7;
            uint32_t d = (uint32_t)(r * ROWB + c * 16);
            cp16(bA(s) + d, A0h + (size_t)r * K + k0 + c * 8);
        }
#pragma unroll
        for (int t = 0; t < 8; t++) {
            int idx = tid + t * 256;
            int r = idx >> 3, c = idx & 7;
            uint32_t d = (uint32_t)(r * ROWB + c * 16);
            cp16(bB(s) + d, B0h + (size_t)r * K + k0 + c * 8);
        }
    };

    float acc[4][8][4];
#pragma unroll
    for (int i = 0; i < 4; i++)
#pragma unroll
        for (int j = 0; j < 8; j++)
#pragma unroll
            for (int t = 0; t < 4; t++) acc[i][j][t] = 0.f;

    const int aRow = lane & 15;
    const int aKof = (lane >> 4) * 16;
    const int bRow = (lane & 7) + ((lane & 16) ? 8 : 0);
    const int bKof = (lane & 8) ? 16 : 0;
    const int warpM = wm * 64;
    const int warpN = wn * 64;

    const int nst = K / BK;
    load_stage(0, 0);
    cp_commit();
    load_stage(1, BK);
    cp_commit();

    for (int s = 0; s < nst; s++) {
        const int buf = s % NSTAGE;
        if (s + 1 < nst) cp_wait<1>(); else cp_wait<0>();
        __syncthreads();

        const uint32_t sA = bA(buf), sB = bB(buf);

#pragma unroll
        for (int ks = 0; ks < 4; ks++) {
            const int kb = ks * 32;
            uint32_t ah[4][4], bh[4][4];
#pragma unroll
            for (int mi = 0; mi < 4; mi++) {
                uint32_t ad = (uint32_t)((warpM + mi * 16 + aRow) * ROWB + kb + aKof);
                ldm_x4(ah[mi], sA + ad);
            }
#pragma unroll
            for (int np = 0; np < 4; np++) {
                uint32_t bd = (uint32_t)((warpN + np * 16 + bRow) * ROWB + kb + bKof);
                ldm_x4(bh[np], sB + bd);
            }
#pragma unroll
            for (int np = 0; np < 4; np++)
#pragma unroll
                for (int q = 0; q < 2; q++) {
                    const int ni = np * 2 + q;
                    const uint32_t b0 = bh[np][q * 2], b1 = bh[np][q * 2 + 1];
#pragma unroll
                    for (int mi = 0; mi < 4; mi++)
                        mma16816(acc[mi][ni], ah[mi], b0, b1);
                }
        }

        if (s + 2 < nst) {
            load_stage((s + 2) % NSTAGE, (s + 2) * BK);
            cp_commit();
        }
    }

    const int er = lane >> 2;
    const int ec = (lane & 3) * 2;
    if (split == 2) {
#pragma unroll
        for (int mi = 0; mi < 4; mi++)
#pragma unroll
            for (int ni = 0; ni < 8; ni++) {
                size_t off0 = (size_t)(m0 + warpM + mi * 16 + er) * Nout
                            + (ncol + warpN + ni * 8 + ec);
                size_t off1 = off0 + (size_t)8 * Nout;
                *(uint32_t*)(Ch + off0) = pack_h2(
                    __float2half_rn(acc[mi][ni][0]), __float2half_rn(acc[mi][ni][1]));
                *(uint32_t*)(Ch + off1) = pack_h2(
                    __float2half_rn(acc[mi][ni][2]), __float2half_rn(acc[mi][ni][3]));
            }
    } else {
#pragma unroll
        for (int mi = 0; mi < 4; mi++)
#pragma unroll
            for (int ni = 0; ni < 8; ni++) {
                size_t off0 = (size_t)(m0 + warpM + mi * 16 + er) * Nout
                            + (ncol + warpN + ni * 8 + ec);
                size_t off1 = off0 + (size_t)8 * Nout;
                float v0 = acc[mi][ni][0], v1 = acc[mi][ni][1];
                float v2 = acc[mi][ni][2], v3 = acc[mi][ni][3];
                __half h0 = __float2half_rn(v0), h1 = __float2half_rn(v1);
                __half h2 = __float2half_rn(v2), h3 = __float2half_rn(v3);
                *(uint32_t*)(Ch + off0) = pack_h2(h0, h1);
                *(uint32_t*)(Ch + off1) = pack_h2(h2, h3);
                *(uint32_t*)(Cl + off0) = pack_h2(
                    __float2half_rn(v0 - __half2float(h0)),
                    __float2half_rn(v1 - __half2float(h1)));
                *(uint32_t*)(Cl + off1) = pack_h2(
                    __float2half_rn(v2 - __half2float(h2)),
                    __float2half_rn(v3 - __half2float(h3)));
            }
    }
}

// ======================= Wo GEMM (single-term, 256x128 tile) ================
#define WOM 256
#define WON 128
#define WO_A_ST (WOM*ROWB)             // 36864
#define WO_B_ST (WON*ROWB)             // 18432
#define WO_STAGE (WO_A_ST + WO_B_ST)   // 55296
#define WO_SMEM (NSTAGE*WO_STAGE)      // 165888

__global__ __launch_bounds__(256, 1) void gemm_wo(
    const __half* __restrict__ Ah, const __half* __restrict__ Bh,
    float* __restrict__ C, int N, int K)
{
    extern __shared__ char smraw[];
    const uint32_t sbase = smem_u32(smraw);
    const int tid  = threadIdx.x;
    const int wid  = tid >> 5;
    const int lane = tid & 31;
    const int wm   = wid & 3;
    const int wn   = wid >> 2;

    int mb, nb;
    cta_map(gridDim.x, gridDim.y, mb, nb);
    const int m0 = mb * WOM, n0 = nb * WON;

    const __half* A0 = Ah + (size_t)m0 * K;
    const __half* B0 = Bh + (size_t)n0 * K;

    auto bA = [&](int s) { return sbase + s * WO_STAGE; };
    auto bB = [&](int s) { return sbase + s * WO_STAGE + WO_A_ST; };

    auto load_stage = [&](int s, int k0) {
#pragma unroll
        for (int t = 0; t < 8; t++) {
            int idx = tid + t * 256;
            int r = idx >> 3, c = idx & 7;
            uint32_t d = (uint32_t)(r * ROWB + c * 16);
            cp16(bA(s) + d, A0 + (size_t)r * K + k0 + c * 8);
        }
#pragma unroll
        for (int t = 0; t < 4; t++) {
            int idx = tid + t * 256;
            int r = idx >> 3, c = idx & 7;
            uint32_t d = (uint32_t)(r * ROWB + c * 16);
            cp16(bB(s) + d, B0 + (size_t)r * K + k0 + c * 8);
        }
    };

    float acc[4][8][4];
#pragma unroll
    for (int i = 0; i < 4; i++)
#pragma unroll
        for (int j = 0; j < 8; j++)
#pragma unroll
            for (int t = 0; t < 4; t++) acc[i][j][t] = 0.f;

    const int aRow = lane & 15;
    const int aKof = (lane >> 4) * 16;
    const int bRow = (lane & 7) + ((lane & 16) ? 8 : 0);
    const int bKof = (lane & 8) ? 16 : 0;
    const int warpM = wm * 64;
    const int warpN = wn * 64;

    const int nst = K / BK;
    load_stage(0, 0);
    cp_commit();
    load_stage(1, BK);
    cp_commit();

    for (int s = 0; s < nst; s++) {
        const int buf = s % NSTAGE;
        if (s + 1 < nst) cp_wait<1>(); else cp_wait<0>();
        __syncthreads();

        const uint32_t sA = bA(buf), sB = bB(buf);

#pragma unroll
        for (int ks = 0; ks < 4; ks++) {
            const int kb = ks * 32;
            uint32_t ah[4][4], bh[4][4];
#pragma unroll
            for (int mi = 0; mi < 4; mi++) {
                uint32_t ad = (uint32_t)((warpM + mi * 16 + aRow) * ROWB + kb + aKof);
                ldm_x4(ah[mi], sA + ad);
            }
#pragma unroll
            for (int np = 0; np < 4; np++) {
                uint32_t bd = (uint32_t)((warpN + np * 16 + bRow) * ROWB + kb + bKof);
                ldm_x4(bh[np], sB + bd);
            }
#pragma unroll
            for (int np = 0; np < 4; np++)
#pragma unroll
                for (int q = 0; q < 2; q++) {
                    const int ni = np * 2 + q;
                    const uint32_t b0 = bh[np][q * 2], b1 = bh[np][q * 2 + 1];
#pragma unroll
                    for (int mi = 0; mi < 4; mi++)
                        mma16816(acc[mi][ni], ah[mi], b0, b1);
                }
        }

        if (s + 2 < nst) {
            load_stage((s + 2) % NSTAGE, (s + 2) * BK);
            cp_commit();
        }
    }

    const int er = lane >> 2;
    const int ec = (lane & 3) * 2;
#pragma unroll
    for (int mi = 0; mi < 4; mi++)
#pragma unroll
        for (int ni = 0; ni < 8; ni++) {
            float* p = C + (size_t)(m0 + warpM + mi * 16 + er) * N
                         + (n0 + warpN + ni * 8 + ec);
            p[0] = acc[mi][ni][0];
            p[1] = acc[mi][ni][1];
            float* q = p + (size_t)8 * N;
            q[0] = acc[mi][ni][2];
            q[1] = acc[mi][ni][3];
        }
}

// ======================= V transpose (hi only) ==============================
__global__ __launch_bounds__(256) void transpose_v(
    const __half* __restrict__ vh, __half* __restrict__ vth)
{
    __shared__ __half th[32][33];
    const int b  = blockIdx.z;
    const int k0 = blockIdx.y * 32;
    const int s0 = blockIdx.x * 32;
    const int tx = threadIdx.x & 31;
    const int ty = threadIdx.x >> 5;
#pragma unroll
    for (int i = 0; i < 4; i++) {
        int row = ty + i * 8;
        th[row][tx] = vh[(size_t)(b * SEQ + s0 + row) * KVDIM + k0 + tx];
    }
    __syncthreads();
#pragma unroll
    for (int i = 0; i < 4; i++) {
        int row = ty + i * 8;
        vth[((size_t)b * KVDIM + k0 + row) * SEQ + s0 + tx] = th[tx][row];
    }
}

// ======================= HMMA flash attention ================================
// QK: Qh*Kh + Qh*Kl.  PV: Ph*Vh.  Softmax in log2 domain (exp2f).
#define QROWB 272
#define KROWB 272
#define VROWB 144
#define SKV_BASE  34816
#define SKV_STRIDE 53248
#define OFF_KH 0
#define OFF_KL 17408
#define OFF_VTH 34816
#define FLASH_SMEM (SKV_BASE + 2*SKV_STRIDE)   // 141312

__global__ __launch_bounds__(256, 1) void flash_hmma(
    const __half* __restrict__ qh,
    const __half* __restrict__ kh, const __half* __restrict__ kl,
    const __half* __restrict__ vth,
    __half* __restrict__ aoh)
{
    extern __shared__ char smraw[];
    const uint32_t sb = smem_u32(smraw);
    const int tid = threadIdx.x, wid = tid >> 5, lane = tid & 31;
    const int qb = (int)(gridDim.x - 1 - blockIdx.x);
    const int hq = blockIdx.y, b = blockIdx.z;
    const int kvh = hq >> 2;
    const int qrow0 = qb * 128;
    const int g = lane >> 2, tig = lane & 3;
    const float cs = 0.08838834764831845f * 1.4426950408889634f;

    const __half* qhg = qh + (size_t)(b * SEQ + qrow0) * HIDDEN + hq * HD;
#pragma unroll
    for (int t = 0; t < 8; t++) {
        int idx = tid + t * 256;
        int r = idx >> 4, c = idx & 15;
        cp16(sb + (uint32_t)(r * QROWB + c * 16), qhg + (size_t)r * HIDDEN + c * 8);
    }
    cp_commit();

    const __half* khg = kh + (size_t)(b * SEQ) * KVDIM + kvh * HD;
    const __half* klg = kl + (size_t)(b * SEQ) * KVDIM + kvh * HD;
    const __half* vthg = vth + ((size_t)b * KVDIM + kvh * HD) * SEQ;

    auto load_kv = [&](int stage, int j) {
        uint32_t base = sb + SKV_BASE + stage * SKV_STRIDE;
        int c0 = j * 64;
#pragma unroll
        for (int t = 0; t < 4; t++) {
            int idx = tid + t * 256;
            int r = idx >> 4, c = idx & 15;
            uint32_t d = (uint32_t)(r * KROWB + c * 16);
            size_t s = (size_t)(c0 + r) * KVDIM + c * 8;
            cp16(base + OFF_KH + d, khg + s);
            cp16(base + OFF_KL + d, klg + s);
        }
#pragma unroll
        for (int t = 0; t < 4; t++) {
            int idx = tid + t * 256;
            int r = idx >> 3, c = idx & 7;
            uint32_t d = (uint32_t)(r * VROWB + c * 16);
            cp16(base + OFF_VTH + d, vthg + (size_t)r * SEQ + c0 + c * 8);
        }
    };

    const int nb = 2 * qb + 2;
    load_kv(0, 0);
    cp_commit();

    float oacc[16][4];
#pragma unroll
    for (int i = 0; i < 16; i++)
#pragma unroll
        for (int t = 0; t < 4; t++) oacc[i][t] = 0.f;
    float m0 = -1e30f, m1 = -1e30f, l0 = 0.f, l1 = 0.f;

    const int aRow = lane & 15;
    const int aKof = (lane >> 4) * 16;
    const int bRow = (lane & 7) + ((lane & 16) ? 8 : 0);
    const int bKof = (lane & 8) ? 16 : 0;

    const int rg0 = qrow0 + 16 * wid + g;
    const int rg1 = rg0 + 8;

    for (int j = 0; j < nb; j++) {
        const int buf = j & 1;
        if (j + 1 < nb) {
            load_kv(1 - buf, j + 1);
            cp_commit();
            cp_wait<1>();
        } else {
            cp_wait<0>();
        }
        __syncthreads();

        const uint32_t kbase = sb + SKV_BASE + buf * SKV_STRIDE;

        float sacc[8][4];
#pragma unroll
        for (int i = 0; i < 8; i++)
#pragma unroll
            for (int t = 0; t < 4; t++) sacc[i][t] = 0.f;

#pragma unroll
        for (int kd = 0; kd < 8; kd++) {
            uint32_t aa = (uint32_t)((16 * wid + aRow) * QROWB + kd * 32 + aKof);
            uint32_t ah[4];
            ldm_x4(ah, sb + aa);
            uint32_t bh[4][4], bl[4][4];
#pragma unroll
            for (int np = 0; np < 4; np++) {
                uint32_t ba = (uint32_t)((np * 16 + bRow) * KROWB + kd * 32 + bKof);
                ldm_x4(bh[np], kbase + OFF_KH + ba);
                ldm_x4(bl[np], kbase + OFF_KL + ba);
            }
#pragma unroll
            for (int ni = 0; ni < 8; ni++) {
                uint32_t b0h = bh[ni >> 1][(ni & 1) * 2], b1h = bh[ni >> 1][(ni & 1) * 2 + 1];
                mma16816(sacc[ni], ah, b0h, b1h);
            }
#pragma unroll
            for (int ni = 0; ni < 8; ni++) {
                uint32_t b0l = bl[ni >> 1][(ni & 1) * 2], b1l = bl[ni >> 1][(ni & 1) * 2 + 1];
                mma16816(sacc[ni], ah, b0l, b1l);
            }
        }

        const int c0 = j * 64;
        if (j >= 2 * qb) {
#pragma unroll
            for (int ni = 0; ni < 8; ni++) {
                int cg = c0 + ni * 8 + 2 * tig;
                if (cg     > rg0) sacc[ni][0] = -1e30f;
                if (cg + 1 > rg0) sacc[ni][1] = -1e30f;
                if (cg     > rg1) sacc[ni][2] = -1e30f;
                if (cg + 1 > rg1) sacc[ni][3] = -1e30f;
            }
        }

        float vm0 = -1e30f, vm1 = -1e30f;
#pragma unroll
        for (int ni = 0; ni < 8; ni++) {
            vm0 = fmaxf(vm0, fmaxf(sacc[ni][0], sacc[ni][1]));
            vm1 = fmaxf(vm1, fmaxf(sacc[ni][2], sacc[ni][3]));
        }
        vm0 = fmaxf(vm0, __shfl_xor_sync(0xffffffffu, vm0, 1));
        vm0 = fmaxf(vm0, __shfl_xor_sync(0xffffffffu, vm0, 2));
        vm1 = fmaxf(vm1, __shfl_xor_sync(0xffffffffu, vm1, 1));
        vm1 = fmaxf(vm1, __shfl_xor_sync(0xffffffffu, vm1, 2));
        float mn0 = fmaxf(m0, vm0 * cs), mn1 = fmaxf(m1, vm1 * cs);
        float al0 = exp2f(m0 - mn0), al1 = exp2f(m1 - mn1);
        float sum0 = 0.f, sum1 = 0.f;
#pragma unroll
        for (int ni = 0; ni < 8; ni++) {
            sacc[ni][0] = exp2f(fmaf(sacc[ni][0], cs, -mn0));
            sacc[ni][1] = exp2f(fmaf(sacc[ni][1], cs, -mn0));
            sacc[ni][2] = exp2f(fmaf(sacc[ni][2], cs, -mn1));
            sacc[ni][3] = exp2f(fmaf(sacc[ni][3], cs, -mn1));
            sum0 += sacc[ni][0] + sacc[ni][1];
            sum1 += sacc[ni][2] + sacc[ni][3];
        }
        sum0 += __shfl_xor_sync(0xffffffffu, sum0, 1);
        sum0 += __shfl_xor_sync(0xffffffffu, sum0, 2);
        sum1 += __shfl_xor_sync(0xffffffffu, sum1, 1);
        sum1 += __shfl_xor_sync(0xffffffffu, sum1, 2);
        l0 = l0 * al0 + sum0;  l1 = l1 * al1 + sum1;
        m0 = mn0;  m1 = mn1;

#pragma unroll
        for (int nd = 0; nd < 16; nd++) {
            oacc[nd][0] *= al0;  oacc[nd][1] *= al0;
            oacc[nd][2] *= al1;  oacc[nd][3] *= al1;
        }

        uint32_t pah[4][4];
#pragma unroll
        for (int t = 0; t < 4; t++) {
            pah[t][0] = pack_h2(__float2half_rn(sacc[2 * t][0]),
                                __float2half_rn(sacc[2 * t][1]));
            pah[t][1] = pack_h2(__float2half_rn(sacc[2 * t][2]),
                                __float2half_rn(sacc[2 * t][3]));
            pah[t][2] = pack_h2(__float2half_rn(sacc[2 * t + 1][0]),
                                __float2half_rn(sacc[2 * t + 1][1]));
            pah[t][3] = pack_h2(__float2half_rn(sacc[2 * t + 1][2]),
                                __float2half_rn(sacc[2 * t + 1][3]));
        }

#pragma unroll
        for (int t = 0; t < 4; t++) {
#pragma unroll
            for (int np = 0; np < 8; np++) {
                uint32_t ba = (uint32_t)((np * 16 + bRow) * VROWB + t * 32 + bKof);
                uint32_t vbh[4];
                ldm_x4(vbh, kbase + OFF_VTH + ba);
#pragma unroll
                for (int q = 0; q < 2; q++) {
                    int nd = np * 2 + q;
                    mma16816(oacc[nd], pah[t], vbh[q * 2], vbh[q * 2 + 1]);
                }
            }
        }
        __syncthreads();
    }

    float inv0 = 1.f / l0, inv1 = 1.f / l1;
    size_t row0 = (size_t)(b * SEQ + qrow0 + 16 * wid + g) * HIDDEN + hq * HD;
    size_t row1 = row0 + (size_t)8 * HIDDEN;
#pragma unroll
    for (int nd = 0; nd < 16; nd++) {
        int col = nd * 8 + 2 * tig;
        *(uint32_t*)(aoh + row0 + col) = pack_h2(
            __float2half_rn(oacc[nd][0] * inv0), __float2half_rn(oacc[nd][1] * inv0));
        *(uint32_t*)(aoh + row1 + col) = pack_h2(
            __float2half_rn(oacc[nd][2] * inv1), __float2half_rn(oacc[nd][3] * inv1));
    }
}

// ============================================================================
extern "C" void kernel_launch(void* const* d_in, const int* in_sizes, int n_in,
                              void* d_out, int out_size)
{
    const float* x  = (const float*)d_in[0];
    const float* Wq = (const float*)d_in[1];
    const float* Wk = (const float*)d_in[2];
    const float* Wv = (const float*)d_in[3];
    const float* Wo = (const float*)d_in[4];
    float* out = (float*)d_out;

    __half *xh, *wqh, *wkh, *wvh, *woh;
    __half *qh, *kh, *kl, *vh, *vth, *aoh;
    cudaGetSymbolAddress((void**)&xh,  g_xh);
    cudaGetSymbolAddress((void**)&wqh, g_wqh);
    cudaGetSymbolAddress((void**)&wkh, g_wkh);
    cudaGetSymbolAddress((void**)&wvh, g_wvh);
    cudaGetSymbolAddress((void**)&woh, g_woh);
    cudaGetSymbolAddress((void**)&qh,  g_qh);
    cudaGetSymbolAddress((void**)&kh,  g_kh);  cudaGetSymbolAddress((void**)&kl,  g_kl);
    cudaGetSymbolAddress((void**)&vh,  g_vh);
    cudaGetSymbolAddress((void**)&vth, g_vth);
    cudaGetSymbolAddress((void**)&aoh, g_aoh);

    cudaFuncSetAttribute(qkv_hmma,   cudaFuncAttributeMaxDynamicSharedMemorySize, GEMM_SMEM);
    cudaFuncSetAttribute(gemm_wo,    cudaFuncAttributeMaxDynamicSharedMemorySize, WO_SMEM);
    cudaFuncSetAttribute(flash_hmma, cudaFuncAttributeMaxDynamicSharedMemorySize, FLASH_SMEM);

    const int XN4 = TOKENS * HIDDEN / 4;
    const int WTOT = 2 * WN4 + 2 * KN4;

    split_hi<<<(XN4 + 255) / 256, 256>>>((const float4*)x, (__half2*)xh, XN4);
    split_w4<<<(WTOT + 255) / 256, 256>>>(
        (const float4*)Wq, (const float4*)Wk, (const float4*)Wv, (const float4*)Wo,
        (__half2*)wqh, (__half2*)wkh, (__half2*)wvh, (__half2*)woh);

    qkv_hmma<<<dim3(6144 / BN, TOKENS / BM), 256, GEMM_SMEM>>>(
        xh, wqh, wkh, wvh, qh, kh, kl, vh);

    transpose_v<<<dim3(SEQ / 32, KVDIM / 32, BATCH), 256>>>(vh, vth);

    flash_hmma<<<dim3(SEQ / 128, NH, BATCH), 256, FLASH_SMEM>>>(
        qh, kh, kl, vth, aoh);

    gemm_wo<<<dim3(HIDDEN / WON, TOKENS / WOM), 256, WO_SMEM>>>(
        aoh, woh, out, HIDDEN, HIDDEN);
}

// round 13
// speedup vs baseline: 8.1167x; 1.0734x over previous
#include <cuda_runtime.h>
#include <cuda_fp16.h>
#include <cstdint>
#include <math.h>

#define HIDDEN   4096
#define NKV      8
#define NH       32
#define HD       128
#define BATCH    2
#define SEQ      2048
#define TOKENS   (BATCH*SEQ)   // 4096
#define KVDIM    (NKV*HD)      // 1024

// ---------------- scratch (device globals; no runtime allocation) ----------
__device__ __half g_xh [TOKENS*HIDDEN];
__device__ __half g_wqh[HIDDEN*HIDDEN];
__device__ __half g_wkh[KVDIM*HIDDEN];
__device__ __half g_wvh[KVDIM*HIDDEN];
__device__ __half g_woh[HIDDEN*HIDDEN];
__device__ __half g_qh [TOKENS*HIDDEN];
__device__ __half g_kh [TOKENS*KVDIM];
__device__ __half g_vh [TOKENS*KVDIM];
__device__ __half g_vth[TOKENS*KVDIM];                    // [B][KVDIM][SEQ]
__device__ __half g_aoh[TOKENS*HIDDEN];

// ======================= helpers ============================================
__device__ __forceinline__ uint32_t smem_u32(const void* p) {
    uint32_t a;
    asm("{ .reg .u64 t; cvta.to.shared.u64 t, %1; cvt.u32.u64 %0, t; }"
        : "=r"(a) : "l"(p));
    return a;
}
__device__ __forceinline__ void cp16(uint32_t dst, const void* src) {
    asm volatile("cp.async.cg.shared.global [%0], [%1], 16;" :: "r"(dst), "l"(src));
}
__device__ __forceinline__ void cp_commit() { asm volatile("cp.async.commit_group;" ::: "memory"); }
template<int N> __device__ __forceinline__ void cp_wait() {
    asm volatile("cp.async.wait_group %0;" :: "n"(N) : "memory");
}
__device__ __forceinline__ void ldm_x4(uint32_t* r, uint32_t addr) {
    asm volatile("ldmatrix.sync.aligned.m8n8.x4.shared.b16 {%0,%1,%2,%3}, [%4];"
        : "=r"(r[0]), "=r"(r[1]), "=r"(r[2]), "=r"(r[3]) : "r"(addr));
}
__device__ __forceinline__ void mma16816(float* d, const uint32_t* a,
                                         uint32_t b0, uint32_t b1) {
    asm volatile(
        "mma.sync.aligned.m16n8k16.row.col.f32.f16.f16.f32 "
        "{%0,%1,%2,%3}, {%4,%5,%6,%7}, {%8,%9}, {%0,%1,%2,%3};"
        : "+f"(d[0]), "+f"(d[1]), "+f"(d[2]), "+f"(d[3])
        : "r"(a[0]), "r"(a[1]), "r"(a[2]), "r"(a[3]), "r"(b0), "r"(b1));
}
__device__ __forceinline__ uint32_t pack_h2(__half a, __half b) {
    __half2 h = __halves2half2(a, b);
    return *(uint32_t*)&h;
}

// ======================= fp32 -> fp16 conversion (all tensors, one launch) ==
#define XN4 (TOKENS*HIDDEN/4)
#define WN4 (HIDDEN*HIDDEN/4)
#define KN4 (KVDIM*HIDDEN/4)
#define CVT_TOT (XN4 + 2*WN4 + 2*KN4)
__global__ __launch_bounds__(256) void split_all(
    const float4* __restrict__ x,
    const float4* __restrict__ wq, const float4* __restrict__ wk,
    const float4* __restrict__ wv, const float4* __restrict__ wo,
    __half2* __restrict__ xo,
    __half2* __restrict__ qo, __half2* __restrict__ ko,
    __half2* __restrict__ vo, __half2* __restrict__ oo)
{
    int i = blockIdx.x * blockDim.x + threadIdx.x;
    const float4* src;
    __half2* dst;
    int idx;
    if (i < XN4)                          { src = x;  dst = xo; idx = i; }
    else if (i < XN4 + WN4)               { src = wq; dst = qo; idx = i - XN4; }
    else if (i < XN4 + WN4 + KN4)         { src = wk; dst = ko; idx = i - XN4 - WN4; }
    else if (i < XN4 + WN4 + 2 * KN4)     { src = wv; dst = vo; idx = i - XN4 - WN4 - KN4; }
    else if (i < CVT_TOT)                 { src = wo; dst = oo; idx = i - XN4 - WN4 - 2 * KN4; }
    else return;
    float4 v = src[idx];
    dst[2 * idx]     = __halves2half2(__float2half_rn(v.x), __float2half_rn(v.y));
    dst[2 * idx + 1] = __halves2half2(__float2half_rn(v.z), __float2half_rn(v.w));
}

// ======================= QKV GEMM (single-term, hi out) =====================
#define BM 128
#define BN 256
#define BK 64
#define ROWB 144
#define A_ST (BM*ROWB)                 // 18432
#define B_ST (BN*ROWB)                 // 36864
#define STAGE_B (A_ST + B_ST)          // 55296
#define NSTAGE 3
#define GEMM_SMEM (NSTAGE*STAGE_B)     // 165888

// swizzled block mapping (supertiles of 8 m-blocks)
__device__ __forceinline__ void cta_map(int gx, int gy, int& mb, int& nb) {
    int lin = blockIdx.y * gx + blockIdx.x;
    const int SW = 8;
    int per  = SW * gx;
    int band = lin / per;
    int rem  = lin - band * per;
    int h    = gy - band * SW; if (h > SW) h = SW;
    mb = band * SW + rem % h;
    nb = rem / h;
}

__global__ __launch_bounds__(256, 1) void qkv_hmma(
    const __half* __restrict__ xh,
    const __half* __restrict__ wqh,
    const __half* __restrict__ wkh,
    const __half* __restrict__ wvh,
    __half* __restrict__ qh,
    __half* __restrict__ kh,
    __half* __restrict__ vh)
{
    extern __shared__ char smraw[];
    const uint32_t sbase = smem_u32(smraw);
    const int tid  = threadIdx.x;
    const int wid  = tid >> 5;
    const int lane = tid & 31;
    const int wm   = wid & 1;
    const int wn   = wid >> 1;

    int mb, nb;
    cta_map(gridDim.x, gridDim.y, mb, nb);
    const int m0 = mb * BM;

    const __half* Bh_;
    __half* Ch;
    int Nout, ncol;
    if (nb < 16)      { Bh_ = wqh; Ch = qh; Nout = HIDDEN; ncol = nb * BN; }
    else if (nb < 20) { Bh_ = wkh; Ch = kh; Nout = KVDIM;  ncol = (nb - 16) * BN; }
    else              { Bh_ = wvh; Ch = vh; Nout = KVDIM;  ncol = (nb - 20) * BN; }

    const __half* A0h = xh + (size_t)m0 * HIDDEN;
    const __half* B0h = Bh_ + (size_t)ncol * HIDDEN;
    const int K = HIDDEN;

    auto bA = [&](int s) { return sbase + s * STAGE_B; };
    auto bB = [&](int s) { return sbase + s * STAGE_B + A_ST; };

    auto load_stage = [&](int s, int k0) {
#pragma unroll
        for (int t = 0; t < 4; t++) {
            int idx = tid + t * 256;
            int r = idx >> 3, c = idx & 7;
            uint32_t d = (uint32_t)(r * ROWB + c * 16);
            cp16(bA(s) + d, A0h + (size_t)r * K + k0 + c * 8);
        }
#pragma unroll
        for (int t = 0; t < 8; t++) {
            int idx = tid + t * 256;
            int r = idx >> 3, c = idx & 7;
            uint32_t d = (uint32_t)(r * ROWB + c * 16);
            cp16(bB(s) + d, B0h + (size_t)r * K + k0 + c * 8);
        }
    };

    float acc[4][8][4];
#pragma unroll
    for (int i = 0; i < 4; i++)
#pragma unroll
        for (int j = 0; j < 8; j++)
#pragma unroll
            for (int t = 0; t < 4; t++) acc[i][j][t] = 0.f;

    const int aRow = lane & 15;
    const int aKof = (lane >> 4) * 16;
    const int bRow = (lane & 7) + ((lane & 16) ? 8 : 0);
    const int bKof = (lane & 8) ? 16 : 0;
    const int warpM = wm * 64;
    const int warpN = wn * 64;

    const int nst = K / BK;
    load_stage(0, 0);
    cp_commit();
    load_stage(1, BK);
    cp_commit();

    for (int s = 0; s < nst; s++) {
        const int buf = s % NSTAGE;
        if (s + 1 < nst) cp_wait<1>(); else cp_wait<0>();
        __syncthreads();

        const uint32_t sA = bA(buf), sB = bB(buf);

#pragma unroll
        for (int ks = 0; ks < 4; ks++) {
            const int kb = ks * 32;
            uint32_t ah[4][4], bh[4][4];
#pragma unroll
            for (int mi = 0; mi < 4; mi++) {
                uint32_t ad = (uint32_t)((warpM + mi * 16 + aRow) * ROWB + kb + aKof);
                ldm_x4(ah[mi], sA + ad);
            }
#pragma unroll
            for (int np = 0; np < 4; np++) {
                uint32_t bd = (uint32_t)((warpN + np * 16 + bRow) * ROWB + kb + bKof);
                ldm_x4(bh[np], sB + bd);
            }
#pragma unroll
            for (int np = 0; np < 4; np++)
#pragma unroll
                for (int q = 0; q < 2; q++) {
                    const int ni = np * 2 + q;
                    const uint32_t b0 = bh[np][q * 2], b1 = bh[np][q * 2 + 1];
#pragma unroll
                    for (int mi = 0; mi < 4; mi++)
                        mma16816(acc[mi][ni], ah[mi], b0, b1);
                }
        }

        if (s + 2 < nst) {
            load_stage((s + 2) % NSTAGE, (s + 2) * BK);
            cp_commit();
        }
    }

    const int er = lane >> 2;
    const int ec = (lane & 3) * 2;
#pragma unroll
    for (int mi = 0; mi < 4; mi++)
#pragma unroll
        for (int ni = 0; ni < 8; ni++) {
            size_t off0 = (size_t)(m0 + warpM + mi * 16 + er) * Nout
                        + (ncol + warpN + ni * 8 + ec);
            size_t off1 = off0 + (size_t)8 * Nout;
            *(uint32_t*)(Ch + off0) = pack_h2(
                __float2half_rn(acc[mi][ni][0]), __float2half_rn(acc[mi][ni][1]));
            *(uint32_t*)(Ch + off1) = pack_h2(
                __float2half_rn(acc[mi][ni][2]), __float2half_rn(acc[mi][ni][3]));
        }
}

// ======================= Wo GEMM (single-term, 256x128 tile) ================
#define WOM 256
#define WON 128
#define WO_A_ST (WOM*ROWB)             // 36864
#define WO_B_ST (WON*ROWB)             // 18432
#define WO_STAGE (WO_A_ST + WO_B_ST)   // 55296
#define WO_SMEM (NSTAGE*WO_STAGE)      // 165888

__global__ __launch_bounds__(256, 1) void gemm_wo(
    const __half* __restrict__ Ah, const __half* __restrict__ Bh,
    float* __restrict__ C, int N, int K)
{
    extern __shared__ char smraw[];
    const uint32_t sbase = smem_u32(smraw);
    const int tid  = threadIdx.x;
    const int wid  = tid >> 5;
    const int lane = tid & 31;
    const int wm   = wid & 3;
    const int wn   = wid >> 2;

    int mb, nb;
    cta_map(gridDim.x, gridDim.y, mb, nb);
    const int m0 = mb * WOM, n0 = nb * WON;

    const __half* A0 = Ah + (size_t)m0 * K;
    const __half* B0 = Bh + (size_t)n0 * K;

    auto bA = [&](int s) { return sbase + s * WO_STAGE; };
    auto bB = [&](int s) { return sbase + s * WO_STAGE + WO_A_ST; };

    auto load_stage = [&](int s, int k0) {
#pragma unroll
        for (int t = 0; t < 8; t++) {
            int idx = tid + t * 256;
            int r = idx >> 3, c = idx & 7;
            uint32_t d = (uint32_t)(r * ROWB + c * 16);
            cp16(bA(s) + d, A0 + (size_t)r * K + k0 + c * 8);
        }
#pragma unroll
        for (int t = 0; t < 4; t++) {
            int idx = tid + t * 256;
            int r = idx >> 3, c = idx & 7;
            uint32_t d = (uint32_t)(r * ROWB + c * 16);
            cp16(bB(s) + d, B0 + (size_t)r * K + k0 + c * 8);
        }
    };

    float acc[4][8][4];
#pragma unroll
    for (int i = 0; i < 4; i++)
#pragma unroll
        for (int j = 0; j < 8; j++)
#pragma unroll
            for (int t = 0; t < 4; t++) acc[i][j][t] = 0.f;

    const int aRow = lane & 15;
    const int aKof = (lane >> 4) * 16;
    const int bRow = (lane & 7) + ((lane & 16) ? 8 : 0);
    const int bKof = (lane & 8) ? 16 : 0;
    const int warpM = wm * 64;
    const int warpN = wn * 64;

    const int nst = K / BK;
    load_stage(0, 0);
    cp_commit();
    load_stage(1, BK);
    cp_commit();

    for (int s = 0; s < nst; s++) {
        const int buf = s % NSTAGE;
        if (s + 1 < nst) cp_wait<1>(); else cp_wait<0>();
        __syncthreads();

        const uint32_t sA = bA(buf), sB = bB(buf);

#pragma unroll
        for (int ks = 0; ks < 4; ks++) {
            const int kb = ks * 32;
            uint32_t ah[4][4], bh[4][4];
#pragma unroll
            for (int mi = 0; mi < 4; mi++) {
                uint32_t ad = (uint32_t)((warpM + mi * 16 + aRow) * ROWB + kb + aKof);
                ldm_x4(ah[mi], sA + ad);
            }
#pragma unroll
            for (int np = 0; np < 4; np++) {
                uint32_t bd = (uint32_t)((warpN + np * 16 + bRow) * ROWB + kb + bKof);
                ldm_x4(bh[np], sB + bd);
            }
#pragma unroll
            for (int np = 0; np < 4; np++)
#pragma unroll
                for (int q = 0; q < 2; q++) {
                    const int ni = np * 2 + q;
                    const uint32_t b0 = bh[np][q * 2], b1 = bh[np][q * 2 + 1];
#pragma unroll
                    for (int mi = 0; mi < 4; mi++)
                        mma16816(acc[mi][ni], ah[mi], b0, b1);
                }
        }

        if (s + 2 < nst) {
            load_stage((s + 2) % NSTAGE, (s + 2) * BK);
            cp_commit();
        }
    }

    const int er = lane >> 2;
    const int ec = (lane & 3) * 2;
#pragma unroll
    for (int mi = 0; mi < 4; mi++)
#pragma unroll
        for (int ni = 0; ni < 8; ni++) {
            float* p = C + (size_t)(m0 + warpM + mi * 16 + er) * N
                         + (n0 + warpN + ni * 8 + ec);
            p[0] = acc[mi][ni][0];
            p[1] = acc[mi][ni][1];
            float* q = p + (size_t)8 * N;
            q[0] = acc[mi][ni][2];
            q[1] = acc[mi][ni][3];
        }
}

// ======================= V transpose (hi only) ==============================
__global__ __launch_bounds__(256) void transpose_v(
    const __half* __restrict__ vh, __half* __restrict__ vth)
{
    __shared__ __half th[32][33];
    const int b  = blockIdx.z;
    const int k0 = blockIdx.y * 32;
    const int s0 = blockIdx.x * 32;
    const int tx = threadIdx.x & 31;
    const int ty = threadIdx.x >> 5;
#pragma unroll
    for (int i = 0; i < 4; i++) {
        int row = ty + i * 8;
        th[row][tx] = vh[(size_t)(b * SEQ + s0 + row) * KVDIM + k0 + tx];
    }
    __syncthreads();
#pragma unroll
    for (int i = 0; i < 4; i++) {
        int row = ty + i * 8;
        vth[((size_t)b * KVDIM + k0 + row) * SEQ + s0 + tx] = th[tx][row];
    }
}

// ======================= HMMA flash attention ================================
// QK: Qh*Kh.  PV: Ph*Vh.  Softmax in log2 domain (exp2f).
#define QROWB 272
#define KROWB 272
#define VROWB 144
#define SKV_BASE  34816
#define K_TILE_B  (64*KROWB)           // 17408
#define V_TILE_B  (128*VROWB)          // 18432
#define SKV_STRIDE (K_TILE_B + V_TILE_B)  // 35840
#define OFF_KH 0
#define OFF_VTH K_TILE_B
#define FLASH_SMEM (SKV_BASE + 2*SKV_STRIDE)   // 106496

__global__ __launch_bounds__(256, 1) void flash_hmma(
    const __half* __restrict__ qh,
    const __half* __restrict__ kh,
    const __half* __restrict__ vth,
    __half* __restrict__ aoh)
{
    extern __shared__ char smraw[];
    const uint32_t sb = smem_u32(smraw);
    const int tid = threadIdx.x, wid = tid >> 5, lane = tid & 31;
    const int qb = (int)(gridDim.x - 1 - blockIdx.x);
    const int hq = blockIdx.y, b = blockIdx.z;
    const int kvh = hq >> 2;
    const int qrow0 = qb * 128;
    const int g = lane >> 2, tig = lane & 3;
    const float cs = 0.08838834764831845f * 1.4426950408889634f;

    const __half* qhg = qh + (size_t)(b * SEQ + qrow0) * HIDDEN + hq * HD;
#pragma unroll
    for (int t = 0; t < 8; t++) {
        int idx = tid + t * 256;
        int r = idx >> 4, c = idx & 15;
        cp16(sb + (uint32_t)(r * QROWB + c * 16), qhg + (size_t)r * HIDDEN + c * 8);
    }
    cp_commit();

    const __half* khg = kh + (size_t)(b * SEQ) * KVDIM + kvh * HD;
    const __half* vthg = vth + ((size_t)b * KVDIM + kvh * HD) * SEQ;

    auto load_kv = [&](int stage, int j) {
        uint32_t base = sb + SKV_BASE + stage * SKV_STRIDE;
        int c0 = j * 64;
#pragma unroll
        for (int t = 0; t < 4; t++) {
            int idx = tid + t * 256;
            int r = idx >> 4, c = idx & 15;
            uint32_t d = (uint32_t)(r * KROWB + c * 16);
            cp16(base + OFF_KH + d, khg + (size_t)(c0 + r) * KVDIM + c * 8);
        }
#pragma unroll
        for (int t = 0; t < 4; t++) {
            int idx = tid + t * 256;
            int r = idx >> 3, c = idx & 7;
            uint32_t d = (uint32_t)(r * VROWB + c * 16);
            cp16(base + OFF_VTH + d, vthg + (size_t)r * SEQ + c0 + c * 8);
        }
    };

    const int nb = 2 * qb + 2;
    load_kv(0, 0);
    cp_commit();

    float oacc[16][4];
#pragma unroll
    for (int i = 0; i < 16; i++)
#pragma unroll
        for (int t = 0; t < 4; t++) oacc[i][t] = 0.f;
    float m0 = -1e30f, m1 = -1e30f, l0 = 0.f, l1 = 0.f;

    const int aRow = lane & 15;
    const int aKof = (lane >> 4) * 16;
    const int bRow = (lane & 7) + ((lane & 16) ? 8 : 0);
    const int bKof = (lane & 8) ? 16 : 0;

    const int rg0 = qrow0 + 16 * wid + g;
    const int rg1 = rg0 + 8;

    for (int j = 0; j < nb; j++) {
        const int buf = j & 1;
        if (j + 1 < nb) {
            load_kv(1 - buf, j + 1);
            cp_commit();
            cp_wait<1>();
        } else {
            cp_wait<0>();
        }
        __syncthreads();

        const uint32_t kbase = sb + SKV_BASE + buf * SKV_STRIDE;

        float sacc[8][4];
#pragma unroll
        for (int i = 0; i < 8; i++)
#pragma unroll
            for (int t = 0; t < 4; t++) sacc[i][t] = 0.f;

#pragma unroll
        for (int kd = 0; kd < 8; kd++) {
            uint32_t aa = (uint32_t)((16 * wid + aRow) * QROWB + kd * 32 + aKof);
            uint32_t ah[4];
            ldm_x4(ah, sb + aa);
            uint32_t bh[4][4];
#pragma unroll
            for (int np = 0; np < 4; np++) {
                uint32_t ba = (uint32_t)((np * 16 + bRow) * KROWB + kd * 32 + bKof);
                ldm_x4(bh[np], kbase + OFF_KH + ba);
            }
#pragma unroll
            for (int ni = 0; ni < 8; ni++) {
                uint32_t b0h = bh[ni >> 1][(ni & 1) * 2], b1h = bh[ni >> 1][(ni & 1) * 2 + 1];
                mma16816(sacc[ni], ah, b0h, b1h);
            }
        }

        const int c0 = j * 64;
        if (j >= 2 * qb) {
#pragma unroll
            for (int ni = 0; ni < 8; ni++) {
                int cg = c0 + ni * 8 + 2 * tig;
                if (cg     > rg0) sacc[ni][0] = -1e30f;
                if (cg + 1 > rg0) sacc[ni][1] = -1e30f;
                if (cg     > rg1) sacc[ni][2] = -1e30f;
                if (cg + 1 > rg1) sacc[ni][3] = -1e30f;
            }
        }

        float vm0 = -1e30f, vm1 = -1e30f;
#pragma unroll
        for (int ni = 0; ni < 8; ni++) {
            vm0 = fmaxf(vm0, fmaxf(sacc[ni][0], sacc[ni][1]));
            vm1 = fmaxf(vm1, fmaxf(sacc[ni][2], sacc[ni][3]));
        }
        vm0 = fmaxf(vm0, __shfl_xor_sync(0xffffffffu, vm0, 1));
        vm0 = fmaxf(vm0, __shfl_xor_sync(0xffffffffu, vm0, 2));
        vm1 = fmaxf(vm1, __shfl_xor_sync(0xffffffffu, vm1, 1));
        vm1 = fmaxf(vm1, __shfl_xor_sync(0xffffffffu, vm1, 2));
        float mn0 = fmaxf(m0, vm0 * cs), mn1 = fmaxf(m1, vm1 * cs);
        float al0 = exp2f(m0 - mn0), al1 = exp2f(m1 - mn1);
        float sum0 = 0.f, sum1 = 0.f;
#pragma unroll
        for (int ni = 0; ni < 8; ni++) {
            sacc[ni][0] = exp2f(fmaf(sacc[ni][0], cs, -mn0));
            sacc[ni][1] = exp2f(fmaf(sacc[ni][1], cs, -mn0));
            sacc[ni][2] = exp2f(fmaf(sacc[ni][2], cs, -mn1));
            sacc[ni][3] = exp2f(fmaf(sacc[ni][3], cs, -mn1));
            sum0 += sacc[ni][0] + sacc[ni][1];
            sum1 += sacc[ni][2] + sacc[ni][3];
        }
        sum0 += __shfl_xor_sync(0xffffffffu, sum0, 1);
        sum0 += __shfl_xor_sync(0xffffffffu, sum0, 2);
        sum1 += __shfl_xor_sync(0xffffffffu, sum1, 1);
        sum1 += __shfl_xor_sync(0xffffffffu, sum1, 2);
        l0 = l0 * al0 + sum0;  l1 = l1 * al1 + sum1;
        m0 = mn0;  m1 = mn1;

#pragma unroll
        for (int nd = 0; nd < 16; nd++) {
            oacc[nd][0] *= al0;  oacc[nd][1] *= al0;
            oacc[nd][2] *= al1;  oacc[nd][3] *= al1;
        }

        uint32_t pah[4][4];
#pragma unroll
        for (int t = 0; t < 4; t++) {
            pah[t][0] = pack_h2(__float2half_rn(sacc[2 * t][0]),
                                __float2half_rn(sacc[2 * t][1]));
            pah[t][1] = pack_h2(__float2half_rn(sacc[2 * t][2]),
                                __float2half_rn(sacc[2 * t][3]));
            pah[t][2] = pack_h2(__float2half_rn(sacc[2 * t + 1][0]),
                                __float2half_rn(sacc[2 * t + 1][1]));
            pah[t][3] = pack_h2(__float2half_rn(sacc[2 * t + 1][2]),
                                __float2half_rn(sacc[2 * t + 1][3]));
        }

#pragma unroll
        for (int t = 0; t < 4; t++) {
#pragma unroll
            for (int np = 0; np < 8; np++) {
                uint32_t ba = (uint32_t)((np * 16 + bRow) * VROWB + t * 32 + bKof);
                uint32_t vbh[4];
                ldm_x4(vbh, kbase + OFF_VTH + ba);
#pragma unroll
                for (int q = 0; q < 2; q++) {
                    int nd = np * 2 + q;
                    mma16816(oacc[nd], pah[t], vbh[q * 2], vbh[q * 2 + 1]);
                }
            }
        }
        __syncthreads();
    }

    float inv0 = 1.f / l0, inv1 = 1.f / l1;
    size_t row0 = (size_t)(b * SEQ + qrow0 + 16 * wid + g) * HIDDEN + hq * HD;
    size_t row1 = row0 + (size_t)8 * HIDDEN;
#pragma unroll
    for (int nd = 0; nd < 16; nd++) {
        int col = nd * 8 + 2 * tig;
        *(uint32_t*)(aoh + row0 + col) = pack_h2(
            __float2half_rn(oacc[nd][0] * inv0), __float2half_rn(oacc[nd][1] * inv0));
        *(uint32_t*)(aoh + row1 + col) = pack_h2(
            __float2half_rn(oacc[nd][2] * inv1), __float2half_rn(oacc[nd][3] * inv1));
    }
}

// ============================================================================
extern "C" void kernel_launch(void* const* d_in, const int* in_sizes, int n_in,
                              void* d_out, int out_size)
{
    const float* x  = (const float*)d_in[0];
    const float* Wq = (const float*)d_in[1];
    const float* Wk = (const float*)d_in[2];
    const float* Wv = (const float*)d_in[3];
    const float* Wo = (const float*)d_in[4];
    float* out = (float*)d_out;

    __half *xh, *wqh, *wkh, *wvh, *woh;
    __half *qh, *kh, *vh, *vth, *aoh;
    cudaGetSymbolAddress((void**)&xh,  g_xh);
    cudaGetSymbolAddress((void**)&wqh, g_wqh);
    cudaGetSymbolAddress((void**)&wkh, g_wkh);
    cudaGetSymbolAddress((void**)&wvh, g_wvh);
    cudaGetSymbolAddress((void**)&woh, g_woh);
    cudaGetSymbolAddress((void**)&qh,  g_qh);
    cudaGetSymbolAddress((void**)&kh,  g_kh);
    cudaGetSymbolAddress((void**)&vh,  g_vh);
    cudaGetSymbolAddress((void**)&vth, g_vth);
    cudaGetSymbolAddress((void**)&aoh, g_aoh);

    cudaFuncSetAttribute(qkv_hmma,   cudaFuncAttributeMaxDynamicSharedMemorySize, GEMM_SMEM);
    cudaFuncSetAttribute(gemm_wo,    cudaFuncAttributeMaxDynamicSharedMemorySize, WO_SMEM);
    cudaFuncSetAttribute(flash_hmma, cudaFuncAttributeMaxDynamicSharedMemorySize, FLASH_SMEM);

    split_all<<<(CVT_TOT + 255) / 256, 256>>>(
        (const float4*)x, (const float4*)Wq, (const float4*)Wk,
        (const float4*)Wv, (const float4*)Wo,
        (__half2*)xh, (__half2*)wqh, (__half2*)wkh, (__half2*)wvh, (__half2*)woh);

    qkv_hmma<<<dim3(6144 / BN, TOKENS / BM), 256, GEMM_SMEM>>>(
        xh, wqh, wkh, wvh, qh, kh, vh);

    transpose_v<<<dim3(SEQ / 32, KVDIM / 32, BATCH), 256>>>(vh, vth);

    flash_hmma<<<dim3(SEQ / 128, NH, BATCH), 256, FLASH_SMEM>>>(
        qh, kh, vth, aoh);

    gemm_wo<<<dim3(HIDDEN / WON, TOKENS / WOM), 256, WO_SMEM>>>(
        aoh, woh, out, HIDDEN, HIDDEN);
}

// round 14
// speedup vs baseline: 8.2766x; 1.0197x over previous
#include <cuda_runtime.h>
#include <cuda_fp16.h>
#include <cstdint>
#include <math.h>

#define HIDDEN   4096
#define NKV      8
#define NH       32
#define HD       128
#define BATCH    2
#define SEQ      2048
#define TOKENS   (BATCH*SEQ)   // 4096
#define KVDIM    (NKV*HD)      // 1024

// ---------------- scratch (device globals; no runtime allocation) ----------
__device__ __half g_xh [TOKENS*HIDDEN];
__device__ __half g_wqh[HIDDEN*HIDDEN];
__device__ __half g_wkh[KVDIM*HIDDEN];
__device__ __half g_wvh[KVDIM*HIDDEN];
__device__ __half g_woh[HIDDEN*HIDDEN];
__device__ __half g_qh [TOKENS*HIDDEN];
__device__ __half g_kh [TOKENS*KVDIM];
__device__ __half g_vh [TOKENS*KVDIM];
__device__ __half g_vth[TOKENS*KVDIM];                    // [B][KVDIM][SEQ]
__device__ __half g_aoh[TOKENS*HIDDEN];

// ======================= helpers ============================================
__device__ __forceinline__ uint32_t smem_u32(const void* p) {
    uint32_t a;
    asm("{ .reg .u64 t; cvta.to.shared.u64 t, %1; cvt.u32.u64 %0, t; }"
        : "=r"(a) : "l"(p));
    return a;
}
__device__ __forceinline__ void cp16(uint32_t dst, const void* src) {
    asm volatile("cp.async.cg.shared.global [%0], [%1], 16;" :: "r"(dst), "l"(src));
}
__device__ __forceinline__ void cp_commit() { asm volatile("cp.async.commit_group;" ::: "memory"); }
template<int N> __device__ __forceinline__ void cp_wait() {
    asm volatile("cp.async.wait_group %0;" :: "n"(N) : "memory");
}
__device__ __forceinline__ void ldm_x4(uint32_t* r, uint32_t addr) {
    asm volatile("ldmatrix.sync.aligned.m8n8.x4.shared.b16 {%0,%1,%2,%3}, [%4];"
        : "=r"(r[0]), "=r"(r[1]), "=r"(r[2]), "=r"(r[3]) : "r"(addr));
}
__device__ __forceinline__ void mma16816(float* d, const uint32_t* a,
                                         uint32_t b0, uint32_t b1) {
    asm volatile(
        "mma.sync.aligned.m16n8k16.row.col.f32.f16.f16.f32 "
        "{%0,%1,%2,%3}, {%4,%5,%6,%7}, {%8,%9}, {%0,%1,%2,%3};"
        : "+f"(d[0]), "+f"(d[1]), "+f"(d[2]), "+f"(d[3])
        : "r"(a[0]), "r"(a[1]), "r"(a[2]), "r"(a[3]), "r"(b0), "r"(b1));
}
__device__ __forceinline__ uint32_t pack_h2(__half a, __half b) {
    __half2 h = __halves2half2(a, b);
    return *(uint32_t*)&h;
}

// ======================= fp32 -> fp16 conversion (all tensors, one launch) ==
#define XN4 (TOKENS*HIDDEN/4)
#define WN4 (HIDDEN*HIDDEN/4)
#define KN4 (KVDIM*HIDDEN/4)
#define CVT_TOT (XN4 + 2*WN4 + 2*KN4)
__global__ __launch_bounds__(256) void split_all(
    const float4* __restrict__ x,
    const float4* __restrict__ wq, const float4* __restrict__ wk,
    const float4* __restrict__ wv, const float4* __restrict__ wo,
    __half2* __restrict__ xo,
    __half2* __restrict__ qo, __half2* __restrict__ ko,
    __half2* __restrict__ vo, __half2* __restrict__ oo)
{
    int i = blockIdx.x * blockDim.x + threadIdx.x;
    const float4* src;
    __half2* dst;
    int idx;
    if (i < XN4)                          { src = x;  dst = xo; idx = i; }
    else if (i < XN4 + WN4)               { src = wq; dst = qo; idx = i - XN4; }
    else if (i < XN4 + WN4 + KN4)         { src = wk; dst = ko; idx = i - XN4 - WN4; }
    else if (i < XN4 + WN4 + 2 * KN4)     { src = wv; dst = vo; idx = i - XN4 - WN4 - KN4; }
    else if (i < CVT_TOT)                 { src = wo; dst = oo; idx = i - XN4 - WN4 - 2 * KN4; }
    else return;
    float4 v = src[idx];
    dst[2 * idx]     = __halves2half2(__float2half_rn(v.x), __float2half_rn(v.y));
    dst[2 * idx + 1] = __halves2half2(__float2half_rn(v.z), __float2half_rn(v.w));
}

// ======================= QKV GEMM (single-term, hi out) =====================
#define BM 128
#define BN 256
#define BK 64
#define ROWB 144
#define A_ST (BM*ROWB)                 // 18432
#define B_ST (BN*ROWB)                 // 36864
#define STAGE_B (A_ST + B_ST)          // 55296
#define NSTAGE 3
#define GEMM_SMEM (NSTAGE*STAGE_B)     // 165888

// swizzled block mapping (supertiles of 8 m-blocks)
__device__ __forceinline__ void cta_map(int gx, int gy, int& mb, int& nb) {
    int lin = blockIdx.y * gx + blockIdx.x;
    const int SW = 8;
    int per  = SW * gx;
    int band = lin / per;
    int rem  = lin - band * per;
    int h    = gy - band * SW; if (h > SW) h = SW;
    mb = band * SW + rem % h;
    nb = rem / h;
}

__global__ __launch_bounds__(256, 1) void qkv_hmma(
    const __half* __restrict__ xh,
    const __half* __restrict__ wqh,
    const __half* __restrict__ wkh,
    const __half* __restrict__ wvh,
    __half* __restrict__ qh,
    __half* __restrict__ kh,
    __half* __restrict__ vh)
{
    extern __shared__ char smraw[];
    const uint32_t sbase = smem_u32(smraw);
    const int tid  = threadIdx.x;
    const int wid  = tid >> 5;
    const int lane = tid & 31;
    const int wm   = wid & 1;
    const int wn   = wid >> 1;

    int mb, nb;
    cta_map(gridDim.x, gridDim.y, mb, nb);
    const int m0 = mb * BM;

    const __half* Bh_;
    __half* Ch;
    int Nout, ncol;
    if (nb < 16)      { Bh_ = wqh; Ch = qh; Nout = HIDDEN; ncol = nb * BN; }
    else if (nb < 20) { Bh_ = wkh; Ch = kh; Nout = KVDIM;  ncol = (nb - 16) * BN; }
    else              { Bh_ = wvh; Ch = vh; Nout = KVDIM;  ncol = (nb - 20) * BN; }

    const __half* A0h = xh + (size_t)m0 * HIDDEN;
    const __half* B0h = Bh_ + (size_t)ncol * HIDDEN;
    const int K = HIDDEN;

    auto bA = [&](int s) { return sbase + s * STAGE_B; };
    auto bB = [&](int s) { return sbase + s * STAGE_B + A_ST; };

    auto load_stage = [&](int s, int k0) {
#pragma unroll
        for (int t = 0; t < 4; t++) {
            int idx = tid + t * 256;
            int r = idx >> 3, c = idx & 7;
            uint32_t d = (uint32_t)(r * ROWB + c * 16);
            cp16(bA(s) + d, A0h + (size_t)r * K + k0 + c * 8);
        }
#pragma unroll
        for (int t = 0; t < 8; t++) {
            int idx = tid + t * 256;
            int r = idx >> 3, c = idx & 7;
            uint32_t d = (uint32_t)(r * ROWB + c * 16);
            cp16(bB(s) + d, B0h + (size_t)r * K + k0 + c * 8);
        }
    };

    float acc[4][8][4];
#pragma unroll
    for (int i = 0; i < 4; i++)
#pragma unroll
        for (int j = 0; j < 8; j++)
#pragma unroll
            for (int t = 0; t < 4; t++) acc[i][j][t] = 0.f;

    const int aRow = lane & 15;
    const int aKof = (lane >> 4) * 16;
    const int bRow = (lane & 7) + ((lane & 16) ? 8 : 0);
    const int bKof = (lane & 8) ? 16 : 0;
    const int warpM = wm * 64;
    const int warpN = wn * 64;

    const int nst = K / BK;
    load_stage(0, 0);
    cp_commit();
    load_stage(1, BK);
    cp_commit();

    for (int s = 0; s < nst; s++) {
        const int buf = s % NSTAGE;
        if (s + 1 < nst) cp_wait<1>(); else cp_wait<0>();
        __syncthreads();

        const uint32_t sA = bA(buf), sB = bB(buf);

#pragma unroll
        for (int ks = 0; ks < 4; ks++) {
            const int kb = ks * 32;
            uint32_t ah[4][4], bh[4][4];
#pragma unroll
            for (int mi = 0; mi < 4; mi++) {
                uint32_t ad = (uint32_t)((warpM + mi * 16 + aRow) * ROWB + kb + aKof);
                ldm_x4(ah[mi], sA + ad);
            }
#pragma unroll
            for (int np = 0; np < 4; np++) {
                uint32_t bd = (uint32_t)((warpN + np * 16 + bRow) * ROWB + kb + bKof);
                ldm_x4(bh[np], sB + bd);
            }
#pragma unroll
            for (int np = 0; np < 4; np++)
#pragma unroll
                for (int q = 0; q < 2; q++) {
                    const int ni = np * 2 + q;
                    const uint32_t b0 = bh[np][q * 2], b1 = bh[np][q * 2 + 1];
#pragma unroll
                    for (int mi = 0; mi < 4; mi++)
                        mma16816(acc[mi][ni], ah[mi], b0, b1);
                }
        }

        if (s + 2 < nst) {
            load_stage((s + 2) % NSTAGE, (s + 2) * BK);
            cp_commit();
        }
    }

    const int er = lane >> 2;
    const int ec = (lane & 3) * 2;
#pragma unroll
    for (int mi = 0; mi < 4; mi++)
#pragma unroll
        for (int ni = 0; ni < 8; ni++) {
            size_t off0 = (size_t)(m0 + warpM + mi * 16 + er) * Nout
                        + (ncol + warpN + ni * 8 + ec);
            size_t off1 = off0 + (size_t)8 * Nout;
            *(uint32_t*)(Ch + off0) = pack_h2(
                __float2half_rn(acc[mi][ni][0]), __float2half_rn(acc[mi][ni][1]));
            *(uint32_t*)(Ch + off1) = pack_h2(
                __float2half_rn(acc[mi][ni][2]), __float2half_rn(acc[mi][ni][3]));
        }
}

// ======================= Wo GEMM (single-term, 256x128 tile) ================
#define WOM 256
#define WON 128
#define WO_A_ST (WOM*ROWB)             // 36864
#define WO_B_ST (WON*ROWB)             // 18432
#define WO_STAGE (WO_A_ST + WO_B_ST)   // 55296
#define WO_SMEM (NSTAGE*WO_STAGE)      // 165888

__global__ __launch_bounds__(256, 1) void gemm_wo(
    const __half* __restrict__ Ah, const __half* __restrict__ Bh,
    float* __restrict__ C, int N, int K)
{
    extern __shared__ char smraw[];
    const uint32_t sbase = smem_u32(smraw);
    const int tid  = threadIdx.x;
    const int wid  = tid >> 5;
    const int lane = tid & 31;
    const int wm   = wid & 3;
    const int wn   = wid >> 2;

    int mb, nb;
    cta_map(gridDim.x, gridDim.y, mb, nb);
    const int m0 = mb * WOM, n0 = nb * WON;

    const __half* A0 = Ah + (size_t)m0 * K;
    const __half* B0 = Bh + (size_t)n0 * K;

    auto bA = [&](int s) { return sbase + s * WO_STAGE; };
    auto bB = [&](int s) { return sbase + s * WO_STAGE + WO_A_ST; };

    auto load_stage = [&](int s, int k0) {
#pragma unroll
        for (int t = 0; t < 8; t++) {
            int idx = tid + t * 256;
            int r = idx >> 3, c = idx & 7;
            uint32_t d = (uint32_t)(r * ROWB + c * 16);
            cp16(bA(s) + d, A0 + (size_t)r * K + k0 + c * 8);
        }
#pragma unroll
        for (int t = 0; t < 4; t++) {
            int idx = tid + t * 256;
            int r = idx >> 3, c = idx & 7;
            uint32_t d = (uint32_t)(r * ROWB + c * 16);
            cp16(bB(s) + d, B0 + (size_t)r * K + k0 + c * 8);
        }
    };

    float acc[4][8][4];
#pragma unroll
    for (int i = 0; i < 4; i++)
#pragma unroll
        for (int j = 0; j < 8; j++)
#pragma unroll
            for (int t = 0; t < 4; t++) acc[i][j][t] = 0.f;

    const int aRow = lane & 15;
    const int aKof = (lane >> 4) * 16;
    const int bRow = (lane & 7) + ((lane & 16) ? 8 : 0);
    const int bKof = (lane & 8) ? 16 : 0;
    const int warpM = wm * 64;
    const int warpN = wn * 64;

    const int nst = K / BK;
    load_stage(0, 0);
    cp_commit();
    load_stage(1, BK);
    cp_commit();

    for (int s = 0; s < nst; s++) {
        const int buf = s % NSTAGE;
        if (s + 1 < nst) cp_wait<1>(); else cp_wait<0>();
        __syncthreads();

        const uint32_t sA = bA(buf), sB = bB(buf);

#pragma unroll
        for (int ks = 0; ks < 4; ks++) {
            const int kb = ks * 32;
            uint32_t ah[4][4], bh[4][4];
#pragma unroll
            for (int mi = 0; mi < 4; mi++) {
                uint32_t ad = (uint32_t)((warpM + mi * 16 + aRow) * ROWB + kb + aKof);
                ldm_x4(ah[mi], sA + ad);
            }
#pragma unroll
            for (int np = 0; np < 4; np++) {
                uint32_t bd = (uint32_t)((warpN + np * 16 + bRow) * ROWB + kb + bKof);
                ldm_x4(bh[np], sB + bd);
            }
#pragma unroll
            for (int np = 0; np < 4; np++)
#pragma unroll
                for (int q = 0; q < 2; q++) {
                    const int ni = np * 2 + q;
                    const uint32_t b0 = bh[np][q * 2], b1 = bh[np][q * 2 + 1];
#pragma unroll
                    for (int mi = 0; mi < 4; mi++)
                        mma16816(acc[mi][ni], ah[mi], b0, b1);
                }
        }

        if (s + 2 < nst) {
            load_stage((s + 2) % NSTAGE, (s + 2) * BK);
            cp_commit();
        }
    }

    const int er = lane >> 2;
    const int ec = (lane & 3) * 2;
#pragma unroll
    for (int mi = 0; mi < 4; mi++)
#pragma unroll
        for (int ni = 0; ni < 8; ni++) {
            float* p = C + (size_t)(m0 + warpM + mi * 16 + er) * N
                         + (n0 + warpN + ni * 8 + ec);
            p[0] = acc[mi][ni][0];
            p[1] = acc[mi][ni][1];
            float* q = p + (size_t)8 * N;
            q[0] = acc[mi][ni][2];
            q[1] = acc[mi][ni][3];
        }
}

// ======================= V transpose (hi only) ==============================
__global__ __launch_bounds__(256) void transpose_v(
    const __half* __restrict__ vh, __half* __restrict__ vth)
{
    __shared__ __half th[32][33];
    const int b  = blockIdx.z;
    const int k0 = blockIdx.y * 32;
    const int s0 = blockIdx.x * 32;
    const int tx = threadIdx.x & 31;
    const int ty = threadIdx.x >> 5;
#pragma unroll
    for (int i = 0; i < 4; i++) {
        int row = ty + i * 8;
        th[row][tx] = vh[(size_t)(b * SEQ + s0 + row) * KVDIM + k0 + tx];
    }
    __syncthreads();
#pragma unroll
    for (int i = 0; i < 4; i++) {
        int row = ty + i * 8;
        vth[((size_t)b * KVDIM + k0 + row) * SEQ + s0 + tx] = th[tx][row];
    }
}

// ======================= HMMA flash attention ================================
// QK: Qh*Kh.  PV: Ph*Vh.  Softmax in log2 domain.  128-col kv blocks.
#define QROWB 272
#define KROWB 272
#define VROWB 272
#define SKV_BASE  34816
#define K_TILE_B  (128*KROWB)          // 34816
#define V_TILE_B  (128*VROWB)          // 34816
#define SKV_STRIDE (K_TILE_B + V_TILE_B)  // 69632
#define OFF_KH 0
#define OFF_VTH K_TILE_B
#define FLASH_SMEM (SKV_BASE + 2*SKV_STRIDE)   // 174080

__global__ __launch_bounds__(256, 1) void flash_hmma(
    const __half* __restrict__ qh,
    const __half* __restrict__ kh,
    const __half* __restrict__ vth,
    __half* __restrict__ aoh)
{
    extern __shared__ char smraw[];
    const uint32_t sb = smem_u32(smraw);
    const int tid = threadIdx.x, wid = tid >> 5, lane = tid & 31;
    const int qb = (int)(gridDim.x - 1 - blockIdx.x);
    const int hq = blockIdx.y, b = blockIdx.z;
    const int kvh = hq >> 2;
    const int qrow0 = qb * 128;
    const int g = lane >> 2, tig = lane & 3;
    const float cs = 0.08838834764831845f * 1.4426950408889634f;

    const __half* qhg = qh + (size_t)(b * SEQ + qrow0) * HIDDEN + hq * HD;
#pragma unroll
    for (int t = 0; t < 8; t++) {
        int idx = tid + t * 256;
        int r = idx >> 4, c = idx & 15;
        cp16(sb + (uint32_t)(r * QROWB + c * 16), qhg + (size_t)r * HIDDEN + c * 8);
    }
    cp_commit();

    const __half* khg = kh + (size_t)(b * SEQ) * KVDIM + kvh * HD;
    const __half* vthg = vth + ((size_t)b * KVDIM + kvh * HD) * SEQ;

    auto load_kv = [&](int stage, int j) {
        uint32_t base = sb + SKV_BASE + stage * SKV_STRIDE;
        int c0 = j * 128;
#pragma unroll
        for (int t = 0; t < 8; t++) {                 // K: 128 rows x 16 chunks
            int idx = tid + t * 256;
            int r = idx >> 4, c = idx & 15;
            uint32_t d = (uint32_t)(r * KROWB + c * 16);
            cp16(base + OFF_KH + d, khg + (size_t)(c0 + r) * KVDIM + c * 8);
        }
#pragma unroll
        for (int t = 0; t < 8; t++) {                 // V^T: 128 rows x 16 chunks
            int idx = tid + t * 256;
            int r = idx >> 4, c = idx & 15;
            uint32_t d = (uint32_t)(r * VROWB + c * 16);
            cp16(base + OFF_VTH + d, vthg + (size_t)r * SEQ + c0 + c * 8);
        }
    };

    const int nb = qb + 1;
    load_kv(0, 0);
    cp_commit();

    float oacc[16][4];
#pragma unroll
    for (int i = 0; i < 16; i++)
#pragma unroll
        for (int t = 0; t < 4; t++) oacc[i][t] = 0.f;
    float m0 = -1e30f, m1 = -1e30f, l0 = 0.f, l1 = 0.f;

    const int aRow = lane & 15;
    const int aKof = (lane >> 4) * 16;
    const int bRow = (lane & 7) + ((lane & 16) ? 8 : 0);
    const int bKof = (lane & 8) ? 16 : 0;

    const int rg0 = qrow0 + 16 * wid + g;
    const int rg1 = rg0 + 8;

    for (int j = 0; j < nb; j++) {
        const int buf = j & 1;
        if (j + 1 < nb) {
            load_kv(1 - buf, j + 1);
            cp_commit();
            cp_wait<1>();
        } else {
            cp_wait<0>();
        }
        __syncthreads();

        const uint32_t kbase = sb + SKV_BASE + buf * SKV_STRIDE;

        float sacc[16][4];
#pragma unroll
        for (int i = 0; i < 16; i++)
#pragma unroll
            for (int t = 0; t < 4; t++) sacc[i][t] = 0.f;

        // ---- S = Q @ K^T over 128 cols ----
#pragma unroll
        for (int kd = 0; kd < 8; kd++) {
            uint32_t aa = (uint32_t)((16 * wid + aRow) * QROWB + kd * 32 + aKof);
            uint32_t ah[4];
            ldm_x4(ah, sb + aa);
#pragma unroll
            for (int np = 0; np < 8; np++) {
                uint32_t ba = (uint32_t)((np * 16 + bRow) * KROWB + kd * 32 + bKof);
                uint32_t bh[4];
                ldm_x4(bh, kbase + OFF_KH + ba);
                mma16816(sacc[np * 2],     ah, bh[0], bh[1]);
                mma16816(sacc[np * 2 + 1], ah, bh[2], bh[3]);
            }
        }

        const int c0 = j * 128;
        if (j == nb - 1 && j == qb) {
#pragma unroll
            for (int ni = 0; ni < 16; ni++) {
                int cg = c0 + ni * 8 + 2 * tig;
                if (cg     > rg0) sacc[ni][0] = -1e30f;
                if (cg + 1 > rg0) sacc[ni][1] = -1e30f;
                if (cg     > rg1) sacc[ni][2] = -1e30f;
                if (cg + 1 > rg1) sacc[ni][3] = -1e30f;
            }
        }

        float vm0 = -1e30f, vm1 = -1e30f;
#pragma unroll
        for (int ni = 0; ni < 16; ni++) {
            vm0 = fmaxf(vm0, fmaxf(sacc[ni][0], sacc[ni][1]));
            vm1 = fmaxf(vm1, fmaxf(sacc[ni][2], sacc[ni][3]));
        }
        vm0 = fmaxf(vm0, __shfl_xor_sync(0xffffffffu, vm0, 1));
        vm0 = fmaxf(vm0, __shfl_xor_sync(0xffffffffu, vm0, 2));
        vm1 = fmaxf(vm1, __shfl_xor_sync(0xffffffffu, vm1, 1));
        vm1 = fmaxf(vm1, __shfl_xor_sync(0xffffffffu, vm1, 2));
        float mn0 = fmaxf(m0, vm0 * cs), mn1 = fmaxf(m1, vm1 * cs);
        float al0 = exp2f(m0 - mn0), al1 = exp2f(m1 - mn1);
        float sum0 = 0.f, sum1 = 0.f;
#pragma unroll
        for (int ni = 0; ni < 16; ni++) {
            sacc[ni][0] = exp2f(fmaf(sacc[ni][0], cs, -mn0));
            sacc[ni][1] = exp2f(fmaf(sacc[ni][1], cs, -mn0));
            sacc[ni][2] = exp2f(fmaf(sacc[ni][2], cs, -mn1));
            sacc[ni][3] = exp2f(fmaf(sacc[ni][3], cs, -mn1));
            sum0 += sacc[ni][0] + sacc[ni][1];
            sum1 += sacc[ni][2] + sacc[ni][3];
        }
        sum0 += __shfl_xor_sync(0xffffffffu, sum0, 1);
        sum0 += __shfl_xor_sync(0xffffffffu, sum0, 2);
        sum1 += __shfl_xor_sync(0xffffffffu, sum1, 1);
        sum1 += __shfl_xor_sync(0xffffffffu, sum1, 2);
        l0 = l0 * al0 + sum0;  l1 = l1 * al1 + sum1;
        m0 = mn0;  m1 = mn1;

#pragma unroll
        for (int nd = 0; nd < 16; nd++) {
            oacc[nd][0] *= al0;  oacc[nd][1] *= al0;
            oacc[nd][2] *= al1;  oacc[nd][3] *= al1;
        }

        // ---- P fragments (8 k16-groups of 128 cols) ----
        uint32_t pah[8][4];
#pragma unroll
        for (int t = 0; t < 8; t++) {
            pah[t][0] = pack_h2(__float2half_rn(sacc[2 * t][0]),
                                __float2half_rn(sacc[2 * t][1]));
            pah[t][1] = pack_h2(__float2half_rn(sacc[2 * t][2]),
                                __float2half_rn(sacc[2 * t][3]));
            pah[t][2] = pack_h2(__float2half_rn(sacc[2 * t + 1][0]),
                                __float2half_rn(sacc[2 * t + 1][1]));
            pah[t][3] = pack_h2(__float2half_rn(sacc[2 * t + 1][2]),
                                __float2half_rn(sacc[2 * t + 1][3]));
        }

        // ---- O += P @ V ----
#pragma unroll
        for (int t = 0; t < 8; t++) {
#pragma unroll
            for (int np = 0; np < 8; np++) {
                uint32_t ba = (uint32_t)((np * 16 + bRow) * VROWB + t * 32 + bKof);
                uint32_t vbh[4];
                ldm_x4(vbh, kbase + OFF_VTH + ba);
                mma16816(oacc[np * 2],     pah[t], vbh[0], vbh[1]);
                mma16816(oacc[np * 2 + 1], pah[t], vbh[2], vbh[3]);
            }
        }
        __syncthreads();
    }

    float inv0 = 1.f / l0, inv1 = 1.f / l1;
    size_t row0 = (size_t)(b * SEQ + qrow0 + 16 * wid + g) * HIDDEN + hq * HD;
    size_t row1 = row0 + (size_t)8 * HIDDEN;
#pragma unroll
    for (int nd = 0; nd < 16; nd++) {
        int col = nd * 8 + 2 * tig;
        *(uint32_t*)(aoh + row0 + col) = pack_h2(
            __float2half_rn(oacc[nd][0] * inv0), __float2half_rn(oacc[nd][1] * inv0));
        *(uint32_t*)(aoh + row1 + col) = pack_h2(
            __float2half_rn(oacc[nd][2] * inv1), __float2half_rn(oacc[nd][3] * inv1));
    }
}

// ============================================================================
extern "C" void kernel_launch(void* const* d_in, const int* in_sizes, int n_in,
                              void* d_out, int out_size)
{
    const float* x  = (const float*)d_in[0];
    const float* Wq = (const float*)d_in[1];
    const float* Wk = (const float*)d_in[2];
    const float* Wv = (const float*)d_in[3];
    const float* Wo = (const float*)d_in[4];
    float* out = (float*)d_out;

    __half *xh, *wqh, *wkh, *wvh, *woh;
    __half *qh, *kh, *vh, *vth, *aoh;
    cudaGetSymbolAddress((void**)&xh,  g_xh);
    cudaGetSymbolAddress((void**)&wqh, g_wqh);
    cudaGetSymbolAddress((void**)&wkh, g_wkh);
    cudaGetSymbolAddress((void**)&wvh, g_wvh);
    cudaGetSymbolAddress((void**)&woh, g_woh);
    cudaGetSymbolAddress((void**)&qh,  g_qh);
    cudaGetSymbolAddress((void**)&kh,  g_kh);
    cudaGetSymbolAddress((void**)&vh,  g_vh);
    cudaGetSymbolAddress((void**)&vth, g_vth);
    cudaGetSymbolAddress((void**)&aoh, g_aoh);

    cudaFuncSetAttribute(qkv_hmma,   cudaFuncAttributeMaxDynamicSharedMemorySize, GEMM_SMEM);
    cudaFuncSetAttribute(gemm_wo,    cudaFuncAttributeMaxDynamicSharedMemorySize, WO_SMEM);
    cudaFuncSetAttribute(flash_hmma, cudaFuncAttributeMaxDynamicSharedMemorySize, FLASH_SMEM);

    split_all<<<(CVT_TOT + 255) / 256, 256>>>(
        (const float4*)x, (const float4*)Wq, (const float4*)Wk,
        (const float4*)Wv, (const float4*)Wo,
        (__half2*)xh, (__half2*)wqh, (__half2*)wkh, (__half2*)wvh, (__half2*)woh);

    qkv_hmma<<<dim3(6144 / BN, TOKENS / BM), 256, GEMM_SMEM>>>(
        xh, wqh, wkh, wvh, qh, kh, vh);

    transpose_v<<<dim3(SEQ / 32, KVDIM / 32, BATCH), 256>>>(vh, vth);

    flash_hmma<<<dim3(SEQ / 128, NH, BATCH), 256, FLASH_SMEM>>>(
        qh, kh, vth, aoh);

    gemm_wo<<<dim3(HIDDEN / WON, TOKENS / WOM), 256, WO_SMEM>>>(
        aoh, woh, out, HIDDEN, HIDDEN);
}